// round 1
// baseline (speedup 1.0000x reference)
#include <cuda_runtime.h>
#include <math.h>
#include <stdint.h>

// ---------------------------------------------------------------------------
// Problem: UPGAT layer.  N=100000 entities, R=500 relations, D=512, E=150000
// edges, B=4096 query triples.  All dims derived from in_sizes at launch.
// ---------------------------------------------------------------------------

#define MAX_N 100000
#define MAX_E 150000
#define MAX_R 500
#define MAX_D 512

// Scratch (device globals; allocation-free per harness rules).  ~1.13 GB bss.
__device__ float g_e0   [(size_t)MAX_N * MAX_D];  // normalized entities; reused as ent_new
__device__ float g_Cbase[(size_t)MAX_N * MAX_D];
__device__ float g_Cedge[(size_t)MAX_E * MAX_D];
__device__ float g_Anew [(size_t)MAX_N * MAX_D];
__device__ float g_Epre [(size_t)MAX_N * MAX_D];
__device__ float g_reln [(size_t)MAX_R * MAX_D];
__device__ float g_denom[MAX_N];
__device__ float g_abexp[MAX_N];
__device__ int   g_flag [MAX_N];

// ---------------------------------------------------------------------------
// Utility: zero a float buffer (float4 vectorized, grid-stride)
// ---------------------------------------------------------------------------
__global__ void zero4_kernel(float4* __restrict__ p, size_t n4) {
    size_t i = (size_t)blockIdx.x * blockDim.x + threadIdx.x;
    size_t stride = (size_t)gridDim.x * blockDim.x;
    float4 z = make_float4(0.f, 0.f, 0.f, 0.f);
    for (; i < n4; i += stride) p[i] = z;
}

// ---------------------------------------------------------------------------
// Row L2-normalize: out[r,:] = in[r,:] / max(||in[r,:]||, 1e-12).  Warp/row.
// ---------------------------------------------------------------------------
__global__ void normalize_rows(const float* __restrict__ in, float* __restrict__ out,
                               int M, int D) {
    int warp = (blockIdx.x * blockDim.x + threadIdx.x) >> 5;
    int lane = threadIdx.x & 31;
    if (warp >= M) return;
    const float4* ip = (const float4*)(in + (size_t)warp * D);
    float4* op = (float4*)(out + (size_t)warp * D);
    int nv = D >> 2;
    float s = 0.f;
    for (int i = lane; i < nv; i += 32) {
        float4 v = ip[i];
        s += v.x * v.x + v.y * v.y + v.z * v.z + v.w * v.w;
    }
    #pragma unroll
    for (int o = 16; o; o >>= 1) s += __shfl_xor_sync(0xFFFFFFFFu, s, o);
    float inv = 1.f / fmaxf(sqrtf(s), 1e-12f);
    for (int i = lane; i < nv; i += 32) {
        float4 v = ip[i];
        op[i] = make_float4(v.x * inv, v.y * inv, v.z * inv, v.w * inv);
    }
}

// ---------------------------------------------------------------------------
// Tiled SGEMM, C[M,D] = A' @ W-op.  BM=128, BN=128, BK=16, 256 thr, 8x8 tiles.
//   MODE 0 (PLAIN): A'[i,k] = A0[i,k]
//   MODE 1 (SCALE): A'[i,k] = A0[i,k] * gvec[k]
//   MODE 2 (EDGE) : A'[i,k] = A0[idx0[i],k] * A1[idx1[i],k]
//   TRANSB=true : C[i,j] = sum_k A'[i,k] * W[j,k]   (A' @ W^T)
//   TRANSB=false: C[i,j] = sum_k A'[i,k] * W[k,j]   (A' @ W)
// Requires D % 128 == 0 and D % 16 == 0.
// ---------------------------------------------------------------------------
template<int MODE, bool TRANSB>
__global__ void gemm128_kernel(const float* __restrict__ A0, const float* __restrict__ A1,
                               const int* __restrict__ idx0, const int* __restrict__ idx1,
                               const float* __restrict__ gvec,
                               const float* __restrict__ W, float* __restrict__ C,
                               int M, int D) {
    constexpr int BM = 128, BN = 128, BK = 16;
    __shared__ float As[BK][BM];
    __shared__ float Bs[BK][BN];

    int tid = threadIdx.x;                 // 256 threads
    int mb = blockIdx.x * BM;
    int nb = blockIdx.y * BN;
    int tx = tid & 15;                     // N group
    int ty = tid >> 4;                     // M group

    float acc[8][8];
    #pragma unroll
    for (int i = 0; i < 8; i++)
        #pragma unroll
        for (int j = 0; j < 8; j++) acc[i][j] = 0.f;

    for (int kb = 0; kb < D; kb += BK) {
        // ---- load A tile (constructed on the fly), transpose into As[k][m]
        #pragma unroll
        for (int i = 0; i < 2; i++) {
            int q = tid + i * 256;         // 0..511
            int row = q >> 2;              // 0..127
            int kc = (q & 3) << 2;         // 0,4,8,12
            int gr = mb + row;
            float4 v = make_float4(0.f, 0.f, 0.f, 0.f);
            if (gr < M) {
                if (MODE == 0) {
                    v = *(const float4*)(A0 + (size_t)gr * D + kb + kc);
                } else if (MODE == 1) {
                    float4 a = *(const float4*)(A0 + (size_t)gr * D + kb + kc);
                    float4 g = *(const float4*)(gvec + kb + kc);
                    v = make_float4(a.x * g.x, a.y * g.y, a.z * g.z, a.w * g.w);
                } else {
                    int r0 = idx0[gr];
                    int r1 = idx1[gr];
                    float4 a = *(const float4*)(A0 + (size_t)r0 * D + kb + kc);
                    float4 b = *(const float4*)(A1 + (size_t)r1 * D + kb + kc);
                    v = make_float4(a.x * b.x, a.y * b.y, a.z * b.z, a.w * b.w);
                }
            }
            As[kc + 0][row] = v.x;
            As[kc + 1][row] = v.y;
            As[kc + 2][row] = v.z;
            As[kc + 3][row] = v.w;
        }
        // ---- load W tile into Bs[k][n]
        if (TRANSB) {
            #pragma unroll
            for (int i = 0; i < 2; i++) {
                int q = tid + i * 256;
                int j = q >> 2;            // 0..127
                int kc = (q & 3) << 2;
                float4 v = *(const float4*)(W + (size_t)(nb + j) * D + kb + kc);
                Bs[kc + 0][j] = v.x;
                Bs[kc + 1][j] = v.y;
                Bs[kc + 2][j] = v.z;
                Bs[kc + 3][j] = v.w;
            }
        } else {
            #pragma unroll
            for (int i = 0; i < 2; i++) {
                int q = tid + i * 256;
                int kr = q >> 5;           // 0..15
                int jc = (q & 31) << 2;    // 0..124
                float4 v = *(const float4*)(W + (size_t)(kb + kr) * D + nb + jc);
                *(float4*)&Bs[kr][jc] = v;
            }
        }
        __syncthreads();

        #pragma unroll
        for (int k = 0; k < BK; k++) {
            float a[8], b[8];
            *(float4*)&a[0] = *(const float4*)&As[k][ty * 8];
            *(float4*)&a[4] = *(const float4*)&As[k][ty * 8 + 4];
            *(float4*)&b[0] = *(const float4*)&Bs[k][tx * 8];
            *(float4*)&b[4] = *(const float4*)&Bs[k][tx * 8 + 4];
            #pragma unroll
            for (int i = 0; i < 8; i++)
                #pragma unroll
                for (int j = 0; j < 8; j++)
                    acc[i][j] = fmaf(a[i], b[j], acc[i][j]);
        }
        __syncthreads();
    }

    #pragma unroll
    for (int i = 0; i < 8; i++) {
        int gr = mb + ty * 8 + i;
        if (gr < M) {
            float* cp = C + (size_t)gr * D + nb + tx * 8;
            *(float4*)(cp + 0) = make_float4(acc[i][0], acc[i][1], acc[i][2], acc[i][3]);
            *(float4*)(cp + 4) = make_float4(acc[i][4], acc[i][5], acc[i][6], acc[i][7]);
        }
    }
}

// ---------------------------------------------------------------------------
// Per-node baseline attention: abexp[n] = exp(-leaky(sum_d e0[n,d]*tanh(Cb[n,d])*Wa[d]))
// ---------------------------------------------------------------------------
__global__ void baseline_reduce(const float* __restrict__ e0, const float* __restrict__ Cb,
                                const float* __restrict__ Wa, float* __restrict__ abexp,
                                int N, int D) {
    int warp = (blockIdx.x * blockDim.x + threadIdx.x) >> 5;
    int lane = threadIdx.x & 31;
    if (warp >= N) return;
    const float4* ep = (const float4*)(e0 + (size_t)warp * D);
    const float4* cp = (const float4*)(Cb + (size_t)warp * D);
    const float4* wp = (const float4*)Wa;
    int nv = D >> 2;
    float s = 0.f;
    for (int i = lane; i < nv; i += 32) {
        float4 e = ep[i], c = cp[i], w = wp[i];
        s += e.x * tanhf(c.x) * w.x + e.y * tanhf(c.y) * w.y +
             e.z * tanhf(c.z) * w.z + e.w * tanhf(c.w) * w.w;
    }
    #pragma unroll
    for (int o = 16; o; o >>= 1) s += __shfl_xor_sync(0xFFFFFFFFu, s, o);
    if (lane == 0) {
        float l = s > 0.f ? s : 0.2f * s;   // leaky_relu(s, 0.2)
        abexp[warp] = expf(-l);
    }
}

// ---------------------------------------------------------------------------
// Per-edge attention + scatter:  warp per edge.
//   a = -leaky(sum_d e0[src,d]*tanh(Ce[e,d])*Wa[d]);  aexp = exp(a)
//   denom[src] += aexp;  flag[src] = 1;  Anew[src,:] += aexp * Ce[e,:]
// ---------------------------------------------------------------------------
__global__ void edge_scatter(const float* __restrict__ e0, const float* __restrict__ Ce,
                             const float* __restrict__ Wa, const int* __restrict__ srcs,
                             float* __restrict__ Anew, float* __restrict__ denom,
                             int* __restrict__ flag, int E, int D) {
    int warp = (blockIdx.x * blockDim.x + threadIdx.x) >> 5;
    int lane = threadIdx.x & 31;
    if (warp >= E) return;
    int src = srcs[warp];
    const float4* cp = (const float4*)(Ce + (size_t)warp * D);
    const float4* ep = (const float4*)(e0 + (size_t)src * D);
    const float4* wp = (const float4*)Wa;
    int cnt = D >> 7;   // D/128 float4's per lane (<=4 for D<=512)
    float4 cv[4];
    float s = 0.f;
    #pragma unroll
    for (int i = 0; i < 4; i++) {
        if (i >= cnt) break;
        int ii = lane + i * 32;
        float4 c = cp[ii];
        cv[i] = c;
        float4 e = ep[ii], w = wp[ii];
        s += e.x * tanhf(c.x) * w.x + e.y * tanhf(c.y) * w.y +
             e.z * tanhf(c.z) * w.z + e.w * tanhf(c.w) * w.w;
    }
    #pragma unroll
    for (int o = 16; o; o >>= 1) s += __shfl_xor_sync(0xFFFFFFFFu, s, o);
    float l = s > 0.f ? s : 0.2f * s;
    float aexp = expf(-l);
    if (lane == 0) {
        atomicAdd(&denom[src], aexp);
        flag[src] = 1;   // plain store; all writers write 1
    }
    float* ap = Anew + (size_t)src * D;
    #pragma unroll
    for (int i = 0; i < 4; i++) {
        if (i >= cnt) break;
        int d = (lane + i * 32) << 2;
        atomicAdd(ap + d + 0, aexp * cv[i].x);
        atomicAdd(ap + d + 1, aexp * cv[i].y);
        atomicAdd(ap + d + 2, aexp * cv[i].z);
        atomicAdd(ap + d + 3, aexp * cv[i].w);
    }
}

// ---------------------------------------------------------------------------
// Combine + ELU + residual + l2norm:  warp per node.
//   num = Anew[n,:] + flag*abexp[n]*Cbase[n,:];  den = denom[n] + flag*abexp[n]
//   h = elu(num / max(den != 0 ? den : EPS));  ent_new = l2norm(Epre[n,:] + h)
// ---------------------------------------------------------------------------
__global__ void combine_kernel(const float* __restrict__ Anew, const float* __restrict__ Cb,
                               const float* __restrict__ Epre, const float* __restrict__ denom,
                               const float* __restrict__ abexp, const int* __restrict__ flag,
                               float* __restrict__ entnew, int N, int D) {
    int warp = (blockIdx.x * blockDim.x + threadIdx.x) >> 5;
    int lane = threadIdx.x & 31;
    if (warp >= N) return;
    float ab = abexp[warp];
    int fl = flag[warp];
    float coef = fl ? ab : 0.f;
    float den = denom[warp] + coef;
    if (den == 0.f) den = 1e-12f;
    float invden = 1.f / den;
    const float4* anp = (const float4*)(Anew + (size_t)warp * D);
    const float4* cbp = (const float4*)(Cb + (size_t)warp * D);
    const float4* epp = (const float4*)(Epre + (size_t)warp * D);
    float4* op = (float4*)(entnew + (size_t)warp * D);
    int cnt = D >> 7;
    float4 tv[4];
    float s = 0.f;
    #pragma unroll
    for (int i = 0; i < 4; i++) {
        if (i >= cnt) break;
        int ii = lane + i * 32;
        float4 an = anp[ii], cb = cbp[ii], ep = epp[ii];
        float4 t;
        {
            float x = (an.x + coef * cb.x) * invden;
            t.x = ep.x + (x > 0.f ? x : expm1f(x));
            x = (an.y + coef * cb.y) * invden;
            t.y = ep.y + (x > 0.f ? x : expm1f(x));
            x = (an.z + coef * cb.z) * invden;
            t.z = ep.z + (x > 0.f ? x : expm1f(x));
            x = (an.w + coef * cb.w) * invden;
            t.w = ep.w + (x > 0.f ? x : expm1f(x));
        }
        tv[i] = t;
        s += t.x * t.x + t.y * t.y + t.z * t.z + t.w * t.w;
    }
    #pragma unroll
    for (int o = 16; o; o >>= 1) s += __shfl_xor_sync(0xFFFFFFFFu, s, o);
    float inv = 1.f / fmaxf(sqrtf(s), 1e-12f);
    #pragma unroll
    for (int i = 0; i < 4; i++) {
        if (i >= cnt) break;
        int ii = lane + i * 32;
        float4 t = tv[i];
        op[ii] = make_float4(t.x * inv, t.y * inv, t.z * inv, t.w * inv);
    }
}

// ---------------------------------------------------------------------------
// Final gather: out[b, 0|2, :] = ent_new[triples[b,0|2]], out[b,1,:] = rel_new[triples[b,1]]
// ---------------------------------------------------------------------------
__global__ void gather_out(const int* __restrict__ triples, const float* __restrict__ entn,
                           const float* __restrict__ reln, float4* __restrict__ out,
                           int B, int D) {
    int nv = D >> 2;
    int total = B * 3 * nv;
    int i = blockIdx.x * blockDim.x + threadIdx.x;
    int stride = gridDim.x * blockDim.x;
    for (; i < total; i += stride) {
        int d4 = i % nv;
        int bt = i / nv;
        int t = bt % 3;
        int b = bt / 3;
        int idx = triples[b * 3 + t];
        const float4* srcp = (t == 1) ? (const float4*)(reln + (size_t)idx * D)
                                      : (const float4*)(entn + (size_t)idx * D);
        out[i] = srcp[d4];
    }
}

// ---------------------------------------------------------------------------
// Launch
// ---------------------------------------------------------------------------
extern "C" void kernel_launch(void* const* d_in, const int* in_sizes, int n_in,
                              void* d_out, int out_size) {
    const int*   triples  = (const int*)d_in[0];
    const int*   nodelist = (const int*)d_in[1];
    const int*   edgelist = (const int*)d_in[2];
    const float* ent      = (const float*)d_in[3];
    const float* rel      = (const float*)d_in[4];
    const float* W1       = (const float*)d_in[5];
    const float* Wa       = (const float*)d_in[6];
    const float* g0       = (const float*)d_in[7];
    const float* WE       = (const float*)d_in[8];
    const float* WR       = (const float*)d_in[9];

    int B = in_sizes[0] / 3;
    int E = in_sizes[2];
    int D = in_sizes[6];
    int N = in_sizes[3] / D;
    int R = in_sizes[4] / D;

    float *e0, *Cbase, *Cedge, *Anew, *Epre, *reln, *denom, *abexp;
    int* flag;
    cudaGetSymbolAddress((void**)&e0,    g_e0);
    cudaGetSymbolAddress((void**)&Cbase, g_Cbase);
    cudaGetSymbolAddress((void**)&Cedge, g_Cedge);
    cudaGetSymbolAddress((void**)&Anew,  g_Anew);
    cudaGetSymbolAddress((void**)&Epre,  g_Epre);
    cudaGetSymbolAddress((void**)&reln,  g_reln);
    cudaGetSymbolAddress((void**)&denom, g_denom);
    cudaGetSymbolAddress((void**)&abexp, g_abexp);
    cudaGetSymbolAddress((void**)&flag,  g_flag);

    // zero scratch accumulators
    {
        size_t n4 = ((size_t)N * D) >> 2;
        zero4_kernel<<<2048, 256>>>((float4*)Anew, n4);
        zero4_kernel<<<64, 256>>>((float4*)denom, (size_t)N >> 2);
        zero4_kernel<<<64, 256>>>((float4*)flag, (size_t)N >> 2);
    }

    // e0 = l2norm(ent)
    normalize_rows<<<(N + 7) / 8, 256>>>(ent, e0, N, D);

    dim3 gN((N + 127) / 128, D / 128);
    dim3 gE((E + 127) / 128, D / 128);
    dim3 gR((R + 127) / 128, D / 128);

    // Cbase = (e0 * g0) @ W1^T  (per node)
    gemm128_kernel<1, true><<<gN, 256>>>(e0, nullptr, nullptr, nullptr, g0, W1, Cbase, N, D);
    // abexp[n]
    baseline_reduce<<<(N + 7) / 8, 256>>>(e0, Cbase, Wa, abexp, N, D);
    // Cedge = (e0[dst] * rel[edge]) @ W1^T  (per edge); dst = node_list[1,:]
    gemm128_kernel<2, true><<<gE, 256>>>(e0, rel, nodelist + E, edgelist, nullptr, W1, Cedge, E, D);
    // attention + scatter-add into Anew/denom; src = node_list[0,:]
    edge_scatter<<<(E + 7) / 8, 256>>>(e0, Cedge, Wa, nodelist, Anew, denom, flag, E, D);
    // Epre = e0 @ W_E
    gemm128_kernel<0, false><<<gN, 256>>>(e0, nullptr, nullptr, nullptr, nullptr, WE, Epre, N, D);
    // ent_new (reuses g_e0 storage: no later consumer reads e0)
    combine_kernel<<<(N + 7) / 8, 256>>>(Anew, Cbase, Epre, denom, abexp, flag, e0, N, D);
    // rel_new = rel @ W_R
    gemm128_kernel<0, false><<<gR, 256>>>(rel, nullptr, nullptr, nullptr, nullptr, WR, reln, R, D);
    // gather output
    int total4 = B * 3 * (D >> 2);
    gather_out<<<(total4 + 255) / 256, 256>>>(triples, e0, reln, (float4*)d_out, B, D);
}

// round 3
// speedup vs baseline: 2.0507x; 2.0507x over previous
#include <cuda_runtime.h>
#include <cuda_bf16.h>
#include <math.h>
#include <stdint.h>

// ---------------------------------------------------------------------------
// UPGAT layer.  N=100000, R=500, D=512, E=150000, B=4096.
// Big GEMMs: bf16 hi/lo split (3 passes) on mma.sync tensor cores (fp32 acc).
// (tcgen05 PTX rejected by this toolchain's compute_103 PTX target.)
// ---------------------------------------------------------------------------

#define MAX_N 100000
#define MAX_E 150000
#define MAX_R 500
#define MAX_D 512

__device__ float g_e0   [(size_t)MAX_N * MAX_D];
__device__ float g_Cbase[(size_t)MAX_N * MAX_D];
__device__ float g_Cedge[(size_t)MAX_E * MAX_D];
__device__ float g_Anew [(size_t)MAX_N * MAX_D];
__device__ float g_Epre [(size_t)MAX_N * MAX_D];
__device__ float g_reln [(size_t)MAX_R * MAX_D];
__device__ float g_denom[MAX_N];
__device__ float g_abexp[MAX_N];
__device__ int   g_flag [MAX_N];

__device__ __nv_bfloat16 g_e0h[(size_t)MAX_N * MAX_D], g_e0l[(size_t)MAX_N * MAX_D];
__device__ __nv_bfloat16 g_egh[(size_t)MAX_N * MAX_D], g_egl[(size_t)MAX_N * MAX_D];
__device__ __nv_bfloat16 g_edh[(size_t)MAX_E * MAX_D], g_edl[(size_t)MAX_E * MAX_D];
__device__ __nv_bfloat16 g_w1h[MAX_D * MAX_D], g_w1l[MAX_D * MAX_D];
__device__ __nv_bfloat16 g_weth[MAX_D * MAX_D], g_wetl[MAX_D * MAX_D];

// ---------------------------------------------------------------------------
// helpers
// ---------------------------------------------------------------------------
__device__ __forceinline__ uint32_t smem_to_u32(const void* smem_ptr) {
    uint32_t addr;
    asm("{ .reg .u64 tmp; cvta.to.shared.u64 tmp, %1; cvt.u32.u64 %0, tmp; }"
        : "=r"(addr) : "l"(smem_ptr));
    return addr;
}
__device__ __forceinline__ void ldsm4(uint32_t addr, uint32_t& r0, uint32_t& r1,
                                      uint32_t& r2, uint32_t& r3) {
    asm volatile("ldmatrix.sync.aligned.m8n8.x4.shared.b16 {%0,%1,%2,%3}, [%4];"
                 : "=r"(r0), "=r"(r1), "=r"(r2), "=r"(r3) : "r"(addr));
}
__device__ __forceinline__ void mma_bf16(float* d, const uint32_t* a, const uint32_t* b) {
    asm volatile(
        "mma.sync.aligned.m16n8k16.row.col.f32.bf16.bf16.f32 "
        "{%0,%1,%2,%3}, {%4,%5,%6,%7}, {%8,%9}, {%0,%1,%2,%3};"
        : "+f"(d[0]), "+f"(d[1]), "+f"(d[2]), "+f"(d[3])
        : "r"(a[0]), "r"(a[1]), "r"(a[2]), "r"(a[3]), "r"(b[0]), "r"(b[1]));
}
__device__ __forceinline__ uint32_t pkbf(__nv_bfloat16 a, __nv_bfloat16 b) {
    __nv_bfloat162 t = __halves2bfloat162(a, b);
    return *reinterpret_cast<uint32_t*>(&t);
}
__device__ __forceinline__ void split4(float4 v, uint2& hi, uint2& lo) {
    __nv_bfloat16 h0 = __float2bfloat16_rn(v.x);
    __nv_bfloat16 h1 = __float2bfloat16_rn(v.y);
    __nv_bfloat16 h2 = __float2bfloat16_rn(v.z);
    __nv_bfloat16 h3 = __float2bfloat16_rn(v.w);
    __nv_bfloat16 l0 = __float2bfloat16_rn(v.x - __bfloat162float(h0));
    __nv_bfloat16 l1 = __float2bfloat16_rn(v.y - __bfloat162float(h1));
    __nv_bfloat16 l2 = __float2bfloat16_rn(v.z - __bfloat162float(h2));
    __nv_bfloat16 l3 = __float2bfloat16_rn(v.w - __bfloat162float(h3));
    hi = make_uint2(pkbf(h0, h1), pkbf(h2, h3));
    lo = make_uint2(pkbf(l0, l1), pkbf(l2, l3));
}

// ---------------------------------------------------------------------------
__global__ void zero4_kernel(float4* __restrict__ p, size_t n4) {
    size_t i = (size_t)blockIdx.x * blockDim.x + threadIdx.x;
    size_t stride = (size_t)gridDim.x * blockDim.x;
    float4 z = make_float4(0.f, 0.f, 0.f, 0.f);
    for (; i < n4; i += stride) p[i] = z;
}

// ---------------------------------------------------------------------------
// e0 = l2norm(ent); emit bf16 splits of e0 and e0*g0.  Warp per row.
// ---------------------------------------------------------------------------
__global__ void normalize_split(const float* __restrict__ in, const float* __restrict__ g0,
                                float* __restrict__ e0,
                                __nv_bfloat16* __restrict__ e0h, __nv_bfloat16* __restrict__ e0l,
                                __nv_bfloat16* __restrict__ egh, __nv_bfloat16* __restrict__ egl,
                                int M, int D) {
    int warp = (blockIdx.x * blockDim.x + threadIdx.x) >> 5;
    int lane = threadIdx.x & 31;
    if (warp >= M) return;
    const float4* ip = (const float4*)(in + (size_t)warp * D);
    const float4* gp = (const float4*)g0;
    float4* op = (float4*)(e0 + (size_t)warp * D);
    int nv = D >> 2;
    float s = 0.f;
    for (int i = lane; i < nv; i += 32) {
        float4 v = ip[i];
        s += v.x * v.x + v.y * v.y + v.z * v.z + v.w * v.w;
    }
    #pragma unroll
    for (int o = 16; o; o >>= 1) s += __shfl_xor_sync(0xFFFFFFFFu, s, o);
    float inv = 1.f / fmaxf(sqrtf(s), 1e-12f);
    size_t rbase = (size_t)warp * D;
    for (int i = lane; i < nv; i += 32) {
        float4 v = ip[i];
        float4 n = make_float4(v.x * inv, v.y * inv, v.z * inv, v.w * inv);
        op[i] = n;
        uint2 hi, lo;
        split4(n, hi, lo);
        *(uint2*)(e0h + rbase + i * 4) = hi;
        *(uint2*)(e0l + rbase + i * 4) = lo;
        float4 g = gp[i];
        float4 w = make_float4(n.x * g.x, n.y * g.y, n.z * g.z, n.w * g.w);
        split4(w, hi, lo);
        *(uint2*)(egh + rbase + i * 4) = hi;
        *(uint2*)(egl + rbase + i * 4) = lo;
    }
}

// ---------------------------------------------------------------------------
// Edge operand: A[e,:] = e0[dst[e],:] * rel[edge[e],:], split to bf16.
// ---------------------------------------------------------------------------
__global__ void split_edge(const float* __restrict__ e0, const float* __restrict__ rel,
                           const int* __restrict__ dsts, const int* __restrict__ edges,
                           __nv_bfloat16* __restrict__ eh, __nv_bfloat16* __restrict__ el,
                           int E, int D) {
    int warp = (blockIdx.x * blockDim.x + threadIdx.x) >> 5;
    int lane = threadIdx.x & 31;
    if (warp >= E) return;
    int dst = dsts[warp];
    int rl = edges[warp];
    const float4* ap = (const float4*)(e0 + (size_t)dst * D);
    const float4* gp = (const float4*)(rel + (size_t)rl * D);
    size_t rbase = (size_t)warp * D;
    int nv = D >> 2;
    for (int i = lane; i < nv; i += 32) {
        float4 a = ap[i], g = gp[i];
        float4 v = make_float4(a.x * g.x, a.y * g.y, a.z * g.z, a.w * g.w);
        uint2 hi, lo;
        split4(v, hi, lo);
        *(uint2*)(eh + rbase + i * 4) = hi;
        *(uint2*)(el + rbase + i * 4) = lo;
    }
}

// ---------------------------------------------------------------------------
// Weight splits: W1 as-is ([N,K] for A@W1^T); WE transposed ([N,K]=WE[k,n]).
// ---------------------------------------------------------------------------
__global__ void split_weights(const float* __restrict__ W1, const float* __restrict__ WE,
                              __nv_bfloat16* __restrict__ w1h, __nv_bfloat16* __restrict__ w1l,
                              __nv_bfloat16* __restrict__ weth, __nv_bfloat16* __restrict__ wetl,
                              int D) {
    int i = blockIdx.x * blockDim.x + threadIdx.x;
    int tot = D * D;
    if (i >= tot) return;
    float v = W1[i];
    __nv_bfloat16 h = __float2bfloat16_rn(v);
    w1h[i] = h;
    w1l[i] = __float2bfloat16_rn(v - __bfloat162float(h));
    int k = i / D, j = i % D;
    float u = WE[i];
    h = __float2bfloat16_rn(u);
    size_t o = (size_t)j * D + k;
    weth[o] = h;
    wetl[o] = __float2bfloat16_rn(u - __bfloat162float(h));
}

// ---------------------------------------------------------------------------
// mma.sync bf16-split GEMM: C[M,D] = (Ah+Al) @ (Bh+Bl)^T,  B stored [N,K].
// CTA 128x256, BK=32, 512 threads (16 warps 4x4), warp tile 32x64.
// Smem stride 40 halves (80B): ldmatrix conflict-free (5i mod 8 covers quads).
// ---------------------------------------------------------------------------
#define MM_BM 128
#define MM_BN 256
#define MM_BK 32
#define MM_LD 40
static constexpr int MM_AH = 0;
static constexpr int MM_AL = 128 * MM_LD;                 // 5120 halves
static constexpr int MM_BH = 2 * 128 * MM_LD;             // 10240
static constexpr int MM_BL = 2 * 128 * MM_LD + 256 * MM_LD; // 20480
static constexpr int MM_STAGE_H = 30720;                  // halves per stage
static constexpr int MM_SMEM_BYTES = 2 * MM_STAGE_H * 2;  // 122880

__global__ void __launch_bounds__(512, 1)
gemm_mma_kernel(const __nv_bfloat16* __restrict__ Ah, const __nv_bfloat16* __restrict__ Al,
                const __nv_bfloat16* __restrict__ Bh, const __nv_bfloat16* __restrict__ Bl,
                float* __restrict__ C, int M, int D) {
    extern __shared__ __nv_bfloat16 sh[];
    uint32_t sbase = smem_to_u32(sh);
    int tid = threadIdx.x;
    int lane = tid & 31;
    int warp = tid >> 5;
    int mb = blockIdx.x * MM_BM;
    int nb = blockIdx.y * MM_BN;
    int wm = (warp >> 2) * 32;
    int wn = (warp & 3) * 64;

    // global staging indices
    int arow = tid >> 2;            // 0..127
    int achk = (tid & 3) * 8;       // half offset within K-chunk (16B chunks)

    float acc[2][8][4];
    #pragma unroll
    for (int i = 0; i < 2; i++)
        #pragma unroll
        for (int j = 0; j < 8; j++)
            #pragma unroll
            for (int q = 0; q < 4; q++) acc[i][j][q] = 0.f;

    uint4 rah, ral, rbh0, rbl0, rbh1, rbl1;
    const uint4 z4 = make_uint4(0, 0, 0, 0);

    auto gload = [&](int kb) {
        int gm = mb + arow;
        if (gm < M) {
            size_t ao = (size_t)gm * D + kb + achk;
            rah = *(const uint4*)(Ah + ao);
            ral = *(const uint4*)(Al + ao);
        } else { rah = z4; ral = z4; }
        size_t bo0 = (size_t)(nb + arow) * D + kb + achk;
        size_t bo1 = bo0 + (size_t)128 * D;
        rbh0 = *(const uint4*)(Bh + bo0);
        rbl0 = *(const uint4*)(Bl + bo0);
        rbh1 = *(const uint4*)(Bh + bo1);
        rbl1 = *(const uint4*)(Bl + bo1);
    };
    auto sstore = [&](int s) {
        __nv_bfloat16* st = sh + s * MM_STAGE_H;
        *(uint4*)(st + MM_AH + arow * MM_LD + achk) = rah;
        *(uint4*)(st + MM_AL + arow * MM_LD + achk) = ral;
        *(uint4*)(st + MM_BH + arow * MM_LD + achk) = rbh0;
        *(uint4*)(st + MM_BL + arow * MM_LD + achk) = rbl0;
        *(uint4*)(st + MM_BH + (arow + 128) * MM_LD + achk) = rbh1;
        *(uint4*)(st + MM_BL + (arow + 128) * MM_LD + achk) = rbl1;
    };

    gload(0);
    sstore(0);
    __syncthreads();

    const int nch = D / MM_BK;
    // per-lane ldmatrix row/col components
    int a_r = (lane & 15);
    int a_c = (lane >> 4) << 3;
    int b_r = (lane & 7) + ((lane & 16) >> 1);
    int b_c = (lane & 8);

    for (int ch = 0; ch < nch; ch++) {
        int s = ch & 1;
        if (ch + 1 < nch) gload((ch + 1) * MM_BK);
        uint32_t stb = sbase + s * (MM_STAGE_H * 2);

        #pragma unroll
        for (int s16 = 0; s16 < 2; s16++) {
            int k0 = s16 * 16;
            uint32_t a[2][4], b[8][2];
            // --- pass 0: Ahi x Bhi
            #pragma unroll
            for (int mi = 0; mi < 2; mi++) {
                uint32_t addr = stb + (MM_AH + (wm + mi * 16 + a_r) * MM_LD + k0 + a_c) * 2;
                ldsm4(addr, a[mi][0], a[mi][1], a[mi][2], a[mi][3]);
            }
            #pragma unroll
            for (int nj = 0; nj < 4; nj++) {
                uint32_t addr = stb + (MM_BH + (wn + nj * 16 + b_r) * MM_LD + k0 + b_c) * 2;
                ldsm4(addr, b[2 * nj][0], b[2 * nj][1], b[2 * nj + 1][0], b[2 * nj + 1][1]);
            }
            #pragma unroll
            for (int mi = 0; mi < 2; mi++)
                #pragma unroll
                for (int nj = 0; nj < 8; nj++) mma_bf16(acc[mi][nj], a[mi], b[nj]);
            // --- pass 1: Alo x Bhi (reuse b)
            #pragma unroll
            for (int mi = 0; mi < 2; mi++) {
                uint32_t addr = stb + (MM_AL + (wm + mi * 16 + a_r) * MM_LD + k0 + a_c) * 2;
                ldsm4(addr, a[mi][0], a[mi][1], a[mi][2], a[mi][3]);
            }
            #pragma unroll
            for (int mi = 0; mi < 2; mi++)
                #pragma unroll
                for (int nj = 0; nj < 8; nj++) mma_bf16(acc[mi][nj], a[mi], b[nj]);
            // --- pass 2: Ahi x Blo
            #pragma unroll
            for (int mi = 0; mi < 2; mi++) {
                uint32_t addr = stb + (MM_AH + (wm + mi * 16 + a_r) * MM_LD + k0 + a_c) * 2;
                ldsm4(addr, a[mi][0], a[mi][1], a[mi][2], a[mi][3]);
            }
            #pragma unroll
            for (int nj = 0; nj < 4; nj++) {
                uint32_t addr = stb + (MM_BL + (wn + nj * 16 + b_r) * MM_LD + k0 + b_c) * 2;
                ldsm4(addr, b[2 * nj][0], b[2 * nj][1], b[2 * nj + 1][0], b[2 * nj + 1][1]);
            }
            #pragma unroll
            for (int mi = 0; mi < 2; mi++)
                #pragma unroll
                for (int nj = 0; nj < 8; nj++) mma_bf16(acc[mi][nj], a[mi], b[nj]);
        }
        if (ch + 1 < nch) sstore(s ^ 1);
        __syncthreads();
    }

    // epilogue
    #pragma unroll
    for (int mi = 0; mi < 2; mi++) {
        int gm0 = mb + wm + mi * 16 + (lane >> 2);
        int gm1 = gm0 + 8;
        #pragma unroll
        for (int nj = 0; nj < 8; nj++) {
            int gn = nb + wn + nj * 8 + (lane & 3) * 2;
            if (gm0 < M)
                *(float2*)(C + (size_t)gm0 * D + gn) = make_float2(acc[mi][nj][0], acc[mi][nj][1]);
            if (gm1 < M)
                *(float2*)(C + (size_t)gm1 * D + gn) = make_float2(acc[mi][nj][2], acc[mi][nj][3]);
        }
    }
}

// ---------------------------------------------------------------------------
// fp32 tiled SGEMM (tiny rel_new GEMM, R=500)
// ---------------------------------------------------------------------------
__global__ void gemm128_plain(const float* __restrict__ A0, const float* __restrict__ W,
                              float* __restrict__ C, int M, int D) {
    constexpr int BM = 128, BN = 128, BK = 16;
    __shared__ float As[BK][BM];
    __shared__ float Bs[BK][BN];
    int tid = threadIdx.x;
    int mb = blockIdx.x * BM;
    int nb = blockIdx.y * BN;
    int tx = tid & 15, ty = tid >> 4;
    float acc[8][8];
    #pragma unroll
    for (int i = 0; i < 8; i++)
        #pragma unroll
        for (int j = 0; j < 8; j++) acc[i][j] = 0.f;
    for (int kb = 0; kb < D; kb += BK) {
        #pragma unroll
        for (int i = 0; i < 2; i++) {
            int q = tid + i * 256;
            int row = q >> 2;
            int kc = (q & 3) << 2;
            int gr = mb + row;
            float4 v = make_float4(0.f, 0.f, 0.f, 0.f);
            if (gr < M) v = *(const float4*)(A0 + (size_t)gr * D + kb + kc);
            As[kc + 0][row] = v.x; As[kc + 1][row] = v.y;
            As[kc + 2][row] = v.z; As[kc + 3][row] = v.w;
        }
        #pragma unroll
        for (int i = 0; i < 2; i++) {
            int q = tid + i * 256;
            int kr = q >> 5;
            int jc = (q & 31) << 2;
            *(float4*)&Bs[kr][jc] = *(const float4*)(W + (size_t)(kb + kr) * D + nb + jc);
        }
        __syncthreads();
        #pragma unroll
        for (int k = 0; k < BK; k++) {
            float a[8], b[8];
            *(float4*)&a[0] = *(const float4*)&As[k][ty * 8];
            *(float4*)&a[4] = *(const float4*)&As[k][ty * 8 + 4];
            *(float4*)&b[0] = *(const float4*)&Bs[k][tx * 8];
            *(float4*)&b[4] = *(const float4*)&Bs[k][tx * 8 + 4];
            #pragma unroll
            for (int i = 0; i < 8; i++)
                #pragma unroll
                for (int j = 0; j < 8; j++)
                    acc[i][j] = fmaf(a[i], b[j], acc[i][j]);
        }
        __syncthreads();
    }
    #pragma unroll
    for (int i = 0; i < 8; i++) {
        int gr = mb + ty * 8 + i;
        if (gr < M) {
            float* cp = C + (size_t)gr * D + nb + tx * 8;
            *(float4*)(cp + 0) = make_float4(acc[i][0], acc[i][1], acc[i][2], acc[i][3]);
            *(float4*)(cp + 4) = make_float4(acc[i][4], acc[i][5], acc[i][6], acc[i][7]);
        }
    }
}

// ---------------------------------------------------------------------------
// Per-node baseline attention
// ---------------------------------------------------------------------------
__global__ void baseline_reduce(const float* __restrict__ e0, const float* __restrict__ Cb,
                                const float* __restrict__ Wa, float* __restrict__ abexp,
                                int N, int D) {
    int warp = (blockIdx.x * blockDim.x + threadIdx.x) >> 5;
    int lane = threadIdx.x & 31;
    if (warp >= N) return;
    const float4* ep = (const float4*)(e0 + (size_t)warp * D);
    const float4* cp = (const float4*)(Cb + (size_t)warp * D);
    const float4* wp = (const float4*)Wa;
    int nv = D >> 2;
    float s = 0.f;
    for (int i = lane; i < nv; i += 32) {
        float4 e = ep[i], c = cp[i], w = wp[i];
        s += e.x * tanhf(c.x) * w.x + e.y * tanhf(c.y) * w.y +
             e.z * tanhf(c.z) * w.z + e.w * tanhf(c.w) * w.w;
    }
    #pragma unroll
    for (int o = 16; o; o >>= 1) s += __shfl_xor_sync(0xFFFFFFFFu, s, o);
    if (lane == 0) {
        float l = s > 0.f ? s : 0.2f * s;
        abexp[warp] = expf(-l);
    }
}

// ---------------------------------------------------------------------------
// Per-edge attention + scatter
// ---------------------------------------------------------------------------
__global__ void edge_scatter(const float* __restrict__ e0, const float* __restrict__ Ce,
                             const float* __restrict__ Wa, const int* __restrict__ srcs,
                             float* __restrict__ Anew, float* __restrict__ denom,
                             int* __restrict__ flag, int E, int D) {
    int warp = (blockIdx.x * blockDim.x + threadIdx.x) >> 5;
    int lane = threadIdx.x & 31;
    if (warp >= E) return;
    int src = srcs[warp];
    const float4* cp = (const float4*)(Ce + (size_t)warp * D);
    const float4* ep = (const float4*)(e0 + (size_t)src * D);
    const float4* wp = (const float4*)Wa;
    int cnt = D >> 7;
    float4 cv[4];
    float s = 0.f;
    #pragma unroll
    for (int i = 0; i < 4; i++) {
        if (i >= cnt) break;
        int ii = lane + i * 32;
        float4 c = cp[ii];
        cv[i] = c;
        float4 e = ep[ii], w = wp[ii];
        s += e.x * tanhf(c.x) * w.x + e.y * tanhf(c.y) * w.y +
             e.z * tanhf(c.z) * w.z + e.w * tanhf(c.w) * w.w;
    }
    #pragma unroll
    for (int o = 16; o; o >>= 1) s += __shfl_xor_sync(0xFFFFFFFFu, s, o);
    float l = s > 0.f ? s : 0.2f * s;
    float aexp = expf(-l);
    if (lane == 0) {
        atomicAdd(&denom[src], aexp);
        flag[src] = 1;
    }
    float* ap = Anew + (size_t)src * D;
    #pragma unroll
    for (int i = 0; i < 4; i++) {
        if (i >= cnt) break;
        int d = (lane + i * 32) << 2;
        atomicAdd(ap + d + 0, aexp * cv[i].x);
        atomicAdd(ap + d + 1, aexp * cv[i].y);
        atomicAdd(ap + d + 2, aexp * cv[i].z);
        atomicAdd(ap + d + 3, aexp * cv[i].w);
    }
}

// ---------------------------------------------------------------------------
// Combine + ELU + residual + l2norm
// ---------------------------------------------------------------------------
__global__ void combine_kernel(const float* __restrict__ Anew, const float* __restrict__ Cb,
                               const float* __restrict__ Epre, const float* __restrict__ denom,
                               const float* __restrict__ abexp, const int* __restrict__ flag,
                               float* __restrict__ entnew, int N, int D) {
    int warp = (blockIdx.x * blockDim.x + threadIdx.x) >> 5;
    int lane = threadIdx.x & 31;
    if (warp >= N) return;
    float ab = abexp[warp];
    int fl = flag[warp];
    float coef = fl ? ab : 0.f;
    float den = denom[warp] + coef;
    if (den == 0.f) den = 1e-12f;
    float invden = 1.f / den;
    const float4* anp = (const float4*)(Anew + (size_t)warp * D);
    const float4* cbp = (const float4*)(Cb + (size_t)warp * D);
    const float4* epp = (const float4*)(Epre + (size_t)warp * D);
    float4* op = (float4*)(entnew + (size_t)warp * D);
    int cnt = D >> 7;
    float4 tv[4];
    float s = 0.f;
    #pragma unroll
    for (int i = 0; i < 4; i++) {
        if (i >= cnt) break;
        int ii = lane + i * 32;
        float4 an = anp[ii], cb = cbp[ii], ep = epp[ii];
        float4 t;
        float x = (an.x + coef * cb.x) * invden;
        t.x = ep.x + (x > 0.f ? x : expm1f(x));
        x = (an.y + coef * cb.y) * invden;
        t.y = ep.y + (x > 0.f ? x : expm1f(x));
        x = (an.z + coef * cb.z) * invden;
        t.z = ep.z + (x > 0.f ? x : expm1f(x));
        x = (an.w + coef * cb.w) * invden;
        t.w = ep.w + (x > 0.f ? x : expm1f(x));
        tv[i] = t;
        s += t.x * t.x + t.y * t.y + t.z * t.z + t.w * t.w;
    }
    #pragma unroll
    for (int o = 16; o; o >>= 1) s += __shfl_xor_sync(0xFFFFFFFFu, s, o);
    float inv = 1.f / fmaxf(sqrtf(s), 1e-12f);
    #pragma unroll
    for (int i = 0; i < 4; i++) {
        if (i >= cnt) break;
        int ii = lane + i * 32;
        float4 t = tv[i];
        op[ii] = make_float4(t.x * inv, t.y * inv, t.z * inv, t.w * inv);
    }
}

// ---------------------------------------------------------------------------
// Final gather
// ---------------------------------------------------------------------------
__global__ void gather_out(const int* __restrict__ triples, const float* __restrict__ entn,
                           const float* __restrict__ reln, float4* __restrict__ out,
                           int B, int D) {
    int nv = D >> 2;
    int total = B * 3 * nv;
    int i = blockIdx.x * blockDim.x + threadIdx.x;
    int stride = gridDim.x * blockDim.x;
    for (; i < total; i += stride) {
        int d4 = i % nv;
        int bt = i / nv;
        int t = bt % 3;
        int b = bt / 3;
        int idx = triples[b * 3 + t];
        const float4* srcp = (t == 1) ? (const float4*)(reln + (size_t)idx * D)
                                      : (const float4*)(entn + (size_t)idx * D);
        out[i] = srcp[d4];
    }
}

// ---------------------------------------------------------------------------
// Launch
// ---------------------------------------------------------------------------
extern "C" void kernel_launch(void* const* d_in, const int* in_sizes, int n_in,
                              void* d_out, int out_size) {
    const int*   triples  = (const int*)d_in[0];
    const int*   nodelist = (const int*)d_in[1];
    const int*   edgelist = (const int*)d_in[2];
    const float* ent      = (const float*)d_in[3];
    const float* rel      = (const float*)d_in[4];
    const float* W1       = (const float*)d_in[5];
    const float* Wa       = (const float*)d_in[6];
    const float* g0       = (const float*)d_in[7];
    const float* WE       = (const float*)d_in[8];
    const float* WR       = (const float*)d_in[9];

    int B = in_sizes[0] / 3;
    int E = in_sizes[2];
    int D = in_sizes[6];
    int N = in_sizes[3] / D;
    int R = in_sizes[4] / D;

    float *e0, *Cbase, *Cedge, *Anew, *Epre, *reln, *denom, *abexp;
    int* flag;
    __nv_bfloat16 *e0h, *e0l, *egh, *egl, *edh, *edl, *w1h, *w1l, *weth, *wetl;
    cudaGetSymbolAddress((void**)&e0,    g_e0);
    cudaGetSymbolAddress((void**)&Cbase, g_Cbase);
    cudaGetSymbolAddress((void**)&Cedge, g_Cedge);
    cudaGetSymbolAddress((void**)&Anew,  g_Anew);
    cudaGetSymbolAddress((void**)&Epre,  g_Epre);
    cudaGetSymbolAddress((void**)&reln,  g_reln);
    cudaGetSymbolAddress((void**)&denom, g_denom);
    cudaGetSymbolAddress((void**)&abexp, g_abexp);
    cudaGetSymbolAddress((void**)&flag,  g_flag);
    cudaGetSymbolAddress((void**)&e0h,   g_e0h);
    cudaGetSymbolAddress((void**)&e0l,   g_e0l);
    cudaGetSymbolAddress((void**)&egh,   g_egh);
    cudaGetSymbolAddress((void**)&egl,   g_egl);
    cudaGetSymbolAddress((void**)&edh,   g_edh);
    cudaGetSymbolAddress((void**)&edl,   g_edl);
    cudaGetSymbolAddress((void**)&w1h,   g_w1h);
    cudaGetSymbolAddress((void**)&w1l,   g_w1l);
    cudaGetSymbolAddress((void**)&weth,  g_weth);
    cudaGetSymbolAddress((void**)&wetl,  g_wetl);

    cudaFuncSetAttribute(gemm_mma_kernel,
                         cudaFuncAttributeMaxDynamicSharedMemorySize, MM_SMEM_BYTES);

    // zero scratch accumulators
    {
        size_t n4 = ((size_t)N * D) >> 2;
        zero4_kernel<<<2048, 256>>>((float4*)Anew, n4);
        zero4_kernel<<<64, 256>>>((float4*)denom, (size_t)N >> 2);
        zero4_kernel<<<64, 256>>>((float4*)flag, (size_t)N >> 2);
    }

    normalize_split<<<(N + 7) / 8, 256>>>(ent, g0, e0, e0h, e0l, egh, egl, N, D);
    split_weights<<<(D * D + 255) / 256, 256>>>(W1, WE, w1h, w1l, weth, wetl, D);
    split_edge<<<(E + 7) / 8, 256>>>(e0, rel, nodelist + E, edgelist, edh, edl, E, D);

    dim3 gN((N + MM_BM - 1) / MM_BM, D / MM_BN);
    dim3 gE2((E + MM_BM - 1) / MM_BM, D / MM_BN);

    // Cbase = (e0 * g0) @ W1^T
    gemm_mma_kernel<<<gN, 512, MM_SMEM_BYTES>>>(egh, egl, w1h, w1l, Cbase, N, D);
    // Cedge = (e0[dst] * rel[edge]) @ W1^T
    gemm_mma_kernel<<<gE2, 512, MM_SMEM_BYTES>>>(edh, edl, w1h, w1l, Cedge, E, D);
    // Epre = e0 @ W_E
    gemm_mma_kernel<<<gN, 512, MM_SMEM_BYTES>>>(e0h, e0l, weth, wetl, Epre, N, D);

    baseline_reduce<<<(N + 7) / 8, 256>>>(e0, Cbase, Wa, abexp, N, D);
    edge_scatter<<<(E + 7) / 8, 256>>>(e0, Cedge, Wa, nodelist, Anew, denom, flag, E, D);
    combine_kernel<<<(N + 7) / 8, 256>>>(Anew, Cbase, Epre, denom, abexp, flag, e0, N, D);
    dim3 gR((R + 127) / 128, D / 128);
    gemm128_plain<<<gR, 256>>>(rel, WR, reln, R, D);
    int total4 = B * 3 * (D >> 2);
    gather_out<<<(total4 + 255) / 256, 256>>>(triples, e0, reln, (float4*)d_out, B, D);
}

// round 4
// speedup vs baseline: 2.2640x; 1.1040x over previous
#include <cuda_runtime.h>
#include <cuda_bf16.h>
#include <math.h>
#include <stdint.h>

// ---------------------------------------------------------------------------
// UPGAT layer.  N=100000, R=500, D=512, E=150000, B=4096.
// Big GEMMs: bf16 hi/lo split (3 passes) on mma.sync tensor cores (fp32 acc),
// cp.async 3-stage pipelined mainloop.
// ---------------------------------------------------------------------------

#define MAX_N 100000
#define MAX_E 150000
#define MAX_R 500
#define MAX_D 512

__device__ float g_e0   [(size_t)MAX_N * MAX_D];
__device__ float g_Cbase[(size_t)MAX_N * MAX_D];
__device__ float g_Cedge[(size_t)MAX_E * MAX_D];
__device__ float g_Anew [(size_t)MAX_N * MAX_D];
__device__ float g_Epre [(size_t)MAX_N * MAX_D];
__device__ float g_reln [(size_t)MAX_R * MAX_D];
__device__ float g_denom[MAX_N];
__device__ float g_abexp[MAX_N];
__device__ int   g_flag [MAX_N];

__device__ __nv_bfloat16 g_e0h[(size_t)MAX_N * MAX_D], g_e0l[(size_t)MAX_N * MAX_D];
__device__ __nv_bfloat16 g_egh[(size_t)MAX_N * MAX_D], g_egl[(size_t)MAX_N * MAX_D];
__device__ __nv_bfloat16 g_edh[(size_t)MAX_E * MAX_D], g_edl[(size_t)MAX_E * MAX_D];
__device__ __nv_bfloat16 g_w1h[MAX_D * MAX_D], g_w1l[MAX_D * MAX_D];
__device__ __nv_bfloat16 g_weth[MAX_D * MAX_D], g_wetl[MAX_D * MAX_D];

// ---------------------------------------------------------------------------
// helpers
// ---------------------------------------------------------------------------
__device__ __forceinline__ uint32_t smem_to_u32(const void* smem_ptr) {
    uint32_t addr;
    asm("{ .reg .u64 tmp; cvta.to.shared.u64 tmp, %1; cvt.u32.u64 %0, tmp; }"
        : "=r"(addr) : "l"(smem_ptr));
    return addr;
}
__device__ __forceinline__ void ldsm4(uint32_t addr, uint32_t& r0, uint32_t& r1,
                                      uint32_t& r2, uint32_t& r3) {
    asm volatile("ldmatrix.sync.aligned.m8n8.x4.shared.b16 {%0,%1,%2,%3}, [%4];"
                 : "=r"(r0), "=r"(r1), "=r"(r2), "=r"(r3) : "r"(addr));
}
__device__ __forceinline__ void mma_bf16(float* d, const uint32_t* a, const uint32_t* b) {
    asm volatile(
        "mma.sync.aligned.m16n8k16.row.col.f32.bf16.bf16.f32 "
        "{%0,%1,%2,%3}, {%4,%5,%6,%7}, {%8,%9}, {%0,%1,%2,%3};"
        : "+f"(d[0]), "+f"(d[1]), "+f"(d[2]), "+f"(d[3])
        : "r"(a[0]), "r"(a[1]), "r"(a[2]), "r"(a[3]), "r"(b[0]), "r"(b[1]));
}
__device__ __forceinline__ void cp16(uint32_t dst, const void* src, bool pred) {
    int sz = pred ? 16 : 0;
    asm volatile("cp.async.cg.shared.global [%0], [%1], 16, %2;"
                 :: "r"(dst), "l"(src), "r"(sz) : "memory");
}
__device__ __forceinline__ uint32_t pkbf(__nv_bfloat16 a, __nv_bfloat16 b) {
    __nv_bfloat162 t = __halves2bfloat162(a, b);
    return *reinterpret_cast<uint32_t*>(&t);
}
__device__ __forceinline__ void split4(float4 v, uint2& hi, uint2& lo) {
    __nv_bfloat16 h0 = __float2bfloat16_rn(v.x);
    __nv_bfloat16 h1 = __float2bfloat16_rn(v.y);
    __nv_bfloat16 h2 = __float2bfloat16_rn(v.z);
    __nv_bfloat16 h3 = __float2bfloat16_rn(v.w);
    __nv_bfloat16 l0 = __float2bfloat16_rn(v.x - __bfloat162float(h0));
    __nv_bfloat16 l1 = __float2bfloat16_rn(v.y - __bfloat162float(h1));
    __nv_bfloat16 l2 = __float2bfloat16_rn(v.z - __bfloat162float(h2));
    __nv_bfloat16 l3 = __float2bfloat16_rn(v.w - __bfloat162float(h3));
    hi = make_uint2(pkbf(h0, h1), pkbf(h2, h3));
    lo = make_uint2(pkbf(l0, l1), pkbf(l2, l3));
}

// ---------------------------------------------------------------------------
__global__ void zero4_kernel(float4* __restrict__ p, size_t n4) {
    size_t i = (size_t)blockIdx.x * blockDim.x + threadIdx.x;
    size_t stride = (size_t)gridDim.x * blockDim.x;
    float4 z = make_float4(0.f, 0.f, 0.f, 0.f);
    for (; i < n4; i += stride) p[i] = z;
}

// ---------------------------------------------------------------------------
// e0 = l2norm(ent); emit bf16 splits of e0 and e0*g0.  Warp per row.
// ---------------------------------------------------------------------------
__global__ void normalize_split(const float* __restrict__ in, const float* __restrict__ g0,
                                float* __restrict__ e0,
                                __nv_bfloat16* __restrict__ e0h, __nv_bfloat16* __restrict__ e0l,
                                __nv_bfloat16* __restrict__ egh, __nv_bfloat16* __restrict__ egl,
                                int M, int D) {
    int warp = (blockIdx.x * blockDim.x + threadIdx.x) >> 5;
    int lane = threadIdx.x & 31;
    if (warp >= M) return;
    const float4* ip = (const float4*)(in + (size_t)warp * D);
    const float4* gp = (const float4*)g0;
    float4* op = (float4*)(e0 + (size_t)warp * D);
    int nv = D >> 2;
    float s = 0.f;
    for (int i = lane; i < nv; i += 32) {
        float4 v = ip[i];
        s += v.x * v.x + v.y * v.y + v.z * v.z + v.w * v.w;
    }
    #pragma unroll
    for (int o = 16; o; o >>= 1) s += __shfl_xor_sync(0xFFFFFFFFu, s, o);
    float inv = 1.f / fmaxf(sqrtf(s), 1e-12f);
    size_t rbase = (size_t)warp * D;
    for (int i = lane; i < nv; i += 32) {
        float4 v = ip[i];
        float4 n = make_float4(v.x * inv, v.y * inv, v.z * inv, v.w * inv);
        op[i] = n;
        uint2 hi, lo;
        split4(n, hi, lo);
        *(uint2*)(e0h + rbase + i * 4) = hi;
        *(uint2*)(e0l + rbase + i * 4) = lo;
        float4 g = gp[i];
        float4 w = make_float4(n.x * g.x, n.y * g.y, n.z * g.z, n.w * g.w);
        split4(w, hi, lo);
        *(uint2*)(egh + rbase + i * 4) = hi;
        *(uint2*)(egl + rbase + i * 4) = lo;
    }
}

// ---------------------------------------------------------------------------
// Edge operand: A[e,:] = e0[dst[e],:] * rel[edge[e],:], split to bf16.
// ---------------------------------------------------------------------------
__global__ void split_edge(const float* __restrict__ e0, const float* __restrict__ rel,
                           const int* __restrict__ dsts, const int* __restrict__ edges,
                           __nv_bfloat16* __restrict__ eh, __nv_bfloat16* __restrict__ el,
                           int E, int D) {
    int warp = (blockIdx.x * blockDim.x + threadIdx.x) >> 5;
    int lane = threadIdx.x & 31;
    if (warp >= E) return;
    int dst = dsts[warp];
    int rl = edges[warp];
    const float4* ap = (const float4*)(e0 + (size_t)dst * D);
    const float4* gp = (const float4*)(rel + (size_t)rl * D);
    size_t rbase = (size_t)warp * D;
    int nv = D >> 2;
    for (int i = lane; i < nv; i += 32) {
        float4 a = ap[i], g = gp[i];
        float4 v = make_float4(a.x * g.x, a.y * g.y, a.z * g.z, a.w * g.w);
        uint2 hi, lo;
        split4(v, hi, lo);
        *(uint2*)(eh + rbase + i * 4) = hi;
        *(uint2*)(el + rbase + i * 4) = lo;
    }
}

// ---------------------------------------------------------------------------
// Weight splits: W1 as-is ([N,K] for A@W1^T); WE transposed ([N,K]=WE[k,n]).
// ---------------------------------------------------------------------------
__global__ void split_weights(const float* __restrict__ W1, const float* __restrict__ WE,
                              __nv_bfloat16* __restrict__ w1h, __nv_bfloat16* __restrict__ w1l,
                              __nv_bfloat16* __restrict__ weth, __nv_bfloat16* __restrict__ wetl,
                              int D) {
    int i = blockIdx.x * blockDim.x + threadIdx.x;
    int tot = D * D;
    if (i >= tot) return;
    float v = W1[i];
    __nv_bfloat16 h = __float2bfloat16_rn(v);
    w1h[i] = h;
    w1l[i] = __float2bfloat16_rn(v - __bfloat162float(h));
    int k = i / D, j = i % D;
    float u = WE[i];
    h = __float2bfloat16_rn(u);
    size_t o = (size_t)j * D + k;
    weth[o] = h;
    wetl[o] = __float2bfloat16_rn(u - __bfloat162float(h));
}

// ---------------------------------------------------------------------------
// mma.sync bf16-split GEMM: C[M,D] = (Ah+Al) @ (Bh+Bl)^T,  B stored [N,K].
// CTA 128x256, BK=32, 512 threads (16 warps 4x4), warp tile 32x64.
// cp.async 3-stage pipeline; 12 ldsm4 per k16 with fragment register reuse.
// ---------------------------------------------------------------------------
#define MM_BM 128
#define MM_BN 256
#define MM_BK 32
#define MM_LD 40
static constexpr int MM_AH = 0;
static constexpr int MM_AL = 128 * MM_LD;                   // 5120 halves
static constexpr int MM_BH = 2 * 128 * MM_LD;               // 10240
static constexpr int MM_BL = 2 * 128 * MM_LD + 256 * MM_LD; // 20480
static constexpr int MM_STAGE_H = 30720;                    // halves per stage
static constexpr int MM_STAGE_BYTES = MM_STAGE_H * 2;       // 61440
static constexpr int MM_SMEM_BYTES = 3 * MM_STAGE_BYTES;    // 184320

__global__ void __launch_bounds__(512, 1)
gemm_mma_kernel(const __nv_bfloat16* __restrict__ Ah, const __nv_bfloat16* __restrict__ Al,
                const __nv_bfloat16* __restrict__ Bh, const __nv_bfloat16* __restrict__ Bl,
                float* __restrict__ C, int M, int D) {
    extern __shared__ __nv_bfloat16 sh[];
    uint32_t sbase = smem_to_u32(sh);
    int tid = threadIdx.x;
    int lane = tid & 31;
    int warp = tid >> 5;
    int mb = blockIdx.x * MM_BM;
    int nb = blockIdx.y * MM_BN;
    int wm = (warp >> 2) * 32;
    int wn = (warp & 3) * 64;
    const int nch = D / MM_BK;   // 16

    float acc[2][8][4];
    #pragma unroll
    for (int i = 0; i < 2; i++)
        #pragma unroll
        for (int j = 0; j < 8; j++)
            #pragma unroll
            for (int q = 0; q < 4; q++) acc[i][j][q] = 0.f;

    // cp.async staging: A row per 4 threads; B two batches of 512.
    int arow = tid >> 2;
    int achk = (tid & 3) * 8;
    int gma = mb + arow;
    bool apred = gma < M;
    size_t abase = (size_t)(apred ? gma : 0) * D + achk;

    auto stage_load = [&](int ch) {
        if (ch < nch) {
            int kb = ch * MM_BK;
            uint32_t st = sbase + (ch % 3) * MM_STAGE_BYTES;
            cp16(st + (MM_AH + arow * MM_LD + achk) * 2, Ah + abase + kb, apred);
            cp16(st + (MM_AL + arow * MM_LD + achk) * 2, Al + abase + kb, apred);
            #pragma unroll
            for (int i = 0; i < 2; i++) {
                int idx = tid + i * 512;
                int row = idx >> 2;
                int chk = (idx & 3) * 8;
                size_t go = (size_t)(nb + row) * D + kb + chk;
                cp16(st + (MM_BH + row * MM_LD + chk) * 2, Bh + go, true);
                cp16(st + (MM_BL + row * MM_LD + chk) * 2, Bl + go, true);
            }
        }
        asm volatile("cp.async.commit_group;" ::: "memory");
    };

    stage_load(0);
    stage_load(1);

    // per-lane ldmatrix row/col components
    int a_r = (lane & 15);
    int a_c = (lane >> 4) << 3;
    int b_r = (lane & 7) + ((lane & 16) >> 1);
    int b_c = (lane & 8);

    for (int ch = 0; ch < nch; ch++) {
        asm volatile("cp.async.wait_group 1;" ::: "memory");
        __syncthreads();
        stage_load(ch + 2);

        uint32_t stb = sbase + (ch % 3) * MM_STAGE_BYTES;
        #pragma unroll
        for (int s16 = 0; s16 < 2; s16++) {
            int k0 = s16 * 16;
            uint32_t ah[2][4], al[2][4], bh[8][2], bl[8][2];
            #pragma unroll
            for (int mi = 0; mi < 2; mi++) {
                uint32_t addr = stb + (MM_AH + (wm + mi * 16 + a_r) * MM_LD + k0 + a_c) * 2;
                ldsm4(addr, ah[mi][0], ah[mi][1], ah[mi][2], ah[mi][3]);
            }
            #pragma unroll
            for (int nj = 0; nj < 4; nj++) {
                uint32_t addr = stb + (MM_BH + (wn + nj * 16 + b_r) * MM_LD + k0 + b_c) * 2;
                ldsm4(addr, bh[2 * nj][0], bh[2 * nj][1], bh[2 * nj + 1][0], bh[2 * nj + 1][1]);
            }
            #pragma unroll
            for (int mi = 0; mi < 2; mi++)
                #pragma unroll
                for (int nj = 0; nj < 8; nj++) mma_bf16(acc[mi][nj], ah[mi], bh[nj]);
            #pragma unroll
            for (int mi = 0; mi < 2; mi++) {
                uint32_t addr = stb + (MM_AL + (wm + mi * 16 + a_r) * MM_LD + k0 + a_c) * 2;
                ldsm4(addr, al[mi][0], al[mi][1], al[mi][2], al[mi][3]);
            }
            #pragma unroll
            for (int mi = 0; mi < 2; mi++)
                #pragma unroll
                for (int nj = 0; nj < 8; nj++) mma_bf16(acc[mi][nj], al[mi], bh[nj]);
            #pragma unroll
            for (int nj = 0; nj < 4; nj++) {
                uint32_t addr = stb + (MM_BL + (wn + nj * 16 + b_r) * MM_LD + k0 + b_c) * 2;
                ldsm4(addr, bl[2 * nj][0], bl[2 * nj][1], bl[2 * nj + 1][0], bl[2 * nj + 1][1]);
            }
            #pragma unroll
            for (int mi = 0; mi < 2; mi++)
                #pragma unroll
                for (int nj = 0; nj < 8; nj++) mma_bf16(acc[mi][nj], ah[mi], bl[nj]);
        }
        __syncthreads();
    }

    // epilogue
    #pragma unroll
    for (int mi = 0; mi < 2; mi++) {
        int gm0 = mb + wm + mi * 16 + (lane >> 2);
        int gm1 = gm0 + 8;
        #pragma unroll
        for (int nj = 0; nj < 8; nj++) {
            int gn = nb + wn + nj * 8 + (lane & 3) * 2;
            if (gm0 < M)
                *(float2*)(C + (size_t)gm0 * D + gn) = make_float2(acc[mi][nj][0], acc[mi][nj][1]);
            if (gm1 < M)
                *(float2*)(C + (size_t)gm1 * D + gn) = make_float2(acc[mi][nj][2], acc[mi][nj][3]);
        }
    }
}

// ---------------------------------------------------------------------------
// fp32 tiled SGEMM (tiny rel_new GEMM, R=500)
// ---------------------------------------------------------------------------
__global__ void gemm128_plain(const float* __restrict__ A0, const float* __restrict__ W,
                              float* __restrict__ C, int M, int D) {
    constexpr int BM = 128, BN = 128, BK = 16;
    __shared__ float As[BK][BM];
    __shared__ float Bs[BK][BN];
    int tid = threadIdx.x;
    int mb = blockIdx.x * BM;
    int nb = blockIdx.y * BN;
    int tx = tid & 15, ty = tid >> 4;
    float acc[8][8];
    #pragma unroll
    for (int i = 0; i < 8; i++)
        #pragma unroll
        for (int j = 0; j < 8; j++) acc[i][j] = 0.f;
    for (int kb = 0; kb < D; kb += BK) {
        #pragma unroll
        for (int i = 0; i < 2; i++) {
            int q = tid + i * 256;
            int row = q >> 2;
            int kc = (q & 3) << 2;
            int gr = mb + row;
            float4 v = make_float4(0.f, 0.f, 0.f, 0.f);
            if (gr < M) v = *(const float4*)(A0 + (size_t)gr * D + kb + kc);
            As[kc + 0][row] = v.x; As[kc + 1][row] = v.y;
            As[kc + 2][row] = v.z; As[kc + 3][row] = v.w;
        }
        #pragma unroll
        for (int i = 0; i < 2; i++) {
            int q = tid + i * 256;
            int kr = q >> 5;
            int jc = (q & 31) << 2;
            *(float4*)&Bs[kr][jc] = *(const float4*)(W + (size_t)(kb + kr) * D + nb + jc);
        }
        __syncthreads();
        #pragma unroll
        for (int k = 0; k < BK; k++) {
            float a[8], b[8];
            *(float4*)&a[0] = *(const float4*)&As[k][ty * 8];
            *(float4*)&a[4] = *(const float4*)&As[k][ty * 8 + 4];
            *(float4*)&b[0] = *(const float4*)&Bs[k][tx * 8];
            *(float4*)&b[4] = *(const float4*)&Bs[k][tx * 8 + 4];
            #pragma unroll
            for (int i = 0; i < 8; i++)
                #pragma unroll
                for (int j = 0; j < 8; j++)
                    acc[i][j] = fmaf(a[i], b[j], acc[i][j]);
        }
        __syncthreads();
    }
    #pragma unroll
    for (int i = 0; i < 8; i++) {
        int gr = mb + ty * 8 + i;
        if (gr < M) {
            float* cp = C + (size_t)gr * D + nb + tx * 8;
            *(float4*)(cp + 0) = make_float4(acc[i][0], acc[i][1], acc[i][2], acc[i][3]);
            *(float4*)(cp + 4) = make_float4(acc[i][4], acc[i][5], acc[i][6], acc[i][7]);
        }
    }
}

// ---------------------------------------------------------------------------
// Per-node baseline attention
// ---------------------------------------------------------------------------
__global__ void baseline_reduce(const float* __restrict__ e0, const float* __restrict__ Cb,
                                const float* __restrict__ Wa, float* __restrict__ abexp,
                                int N, int D) {
    int warp = (blockIdx.x * blockDim.x + threadIdx.x) >> 5;
    int lane = threadIdx.x & 31;
    if (warp >= N) return;
    const float4* ep = (const float4*)(e0 + (size_t)warp * D);
    const float4* cp = (const float4*)(Cb + (size_t)warp * D);
    const float4* wp = (const float4*)Wa;
    int nv = D >> 2;
    float s = 0.f;
    for (int i = lane; i < nv; i += 32) {
        float4 e = ep[i], c = cp[i], w = wp[i];
        s += e.x * tanhf(c.x) * w.x + e.y * tanhf(c.y) * w.y +
             e.z * tanhf(c.z) * w.z + e.w * tanhf(c.w) * w.w;
    }
    #pragma unroll
    for (int o = 16; o; o >>= 1) s += __shfl_xor_sync(0xFFFFFFFFu, s, o);
    if (lane == 0) {
        float l = s > 0.f ? s : 0.2f * s;
        abexp[warp] = expf(-l);
    }
}

// ---------------------------------------------------------------------------
// Per-edge attention + scatter
// ---------------------------------------------------------------------------
__global__ void edge_scatter(const float* __restrict__ e0, const float* __restrict__ Ce,
                             const float* __restrict__ Wa, const int* __restrict__ srcs,
                             float* __restrict__ Anew, float* __restrict__ denom,
                             int* __restrict__ flag, int E, int D) {
    int warp = (blockIdx.x * blockDim.x + threadIdx.x) >> 5;
    int lane = threadIdx.x & 31;
    if (warp >= E) return;
    int src = srcs[warp];
    const float4* cp = (const float4*)(Ce + (size_t)warp * D);
    const float4* ep = (const float4*)(e0 + (size_t)src * D);
    const float4* wp = (const float4*)Wa;
    int cnt = D >> 7;
    float4 cv[4];
    float s = 0.f;
    #pragma unroll
    for (int i = 0; i < 4; i++) {
        if (i >= cnt) break;
        int ii = lane + i * 32;
        float4 c = cp[ii];
        cv[i] = c;
        float4 e = ep[ii], w = wp[ii];
        s += e.x * tanhf(c.x) * w.x + e.y * tanhf(c.y) * w.y +
             e.z * tanhf(c.z) * w.z + e.w * tanhf(c.w) * w.w;
    }
    #pragma unroll
    for (int o = 16; o; o >>= 1) s += __shfl_xor_sync(0xFFFFFFFFu, s, o);
    float l = s > 0.f ? s : 0.2f * s;
    float aexp = expf(-l);
    if (lane == 0) {
        atomicAdd(&denom[src], aexp);
        flag[src] = 1;
    }
    float* ap = Anew + (size_t)src * D;
    #pragma unroll
    for (int i = 0; i < 4; i++) {
        if (i >= cnt) break;
        int d = (lane + i * 32) << 2;
        atomicAdd(ap + d + 0, aexp * cv[i].x);
        atomicAdd(ap + d + 1, aexp * cv[i].y);
        atomicAdd(ap + d + 2, aexp * cv[i].z);
        atomicAdd(ap + d + 3, aexp * cv[i].w);
    }
}

// ---------------------------------------------------------------------------
// Combine + ELU + residual + l2norm
// ---------------------------------------------------------------------------
__global__ void combine_kernel(const float* __restrict__ Anew, const float* __restrict__ Cb,
                               const float* __restrict__ Epre, const float* __restrict__ denom,
                               const float* __restrict__ abexp, const int* __restrict__ flag,
                               float* __restrict__ entnew, int N, int D) {
    int warp = (blockIdx.x * blockDim.x + threadIdx.x) >> 5;
    int lane = threadIdx.x & 31;
    if (warp >= N) return;
    float ab = abexp[warp];
    int fl = flag[warp];
    float coef = fl ? ab : 0.f;
    float den = denom[warp] + coef;
    if (den == 0.f) den = 1e-12f;
    float invden = 1.f / den;
    const float4* anp = (const float4*)(Anew + (size_t)warp * D);
    const float4* cbp = (const float4*)(Cb + (size_t)warp * D);
    const float4* epp = (const float4*)(Epre + (size_t)warp * D);
    float4* op = (float4*)(entnew + (size_t)warp * D);
    int cnt = D >> 7;
    float4 tv[4];
    float s = 0.f;
    #pragma unroll
    for (int i = 0; i < 4; i++) {
        if (i >= cnt) break;
        int ii = lane + i * 32;
        float4 an = anp[ii], cb = cbp[ii], ep = epp[ii];
        float4 t;
        float x = (an.x + coef * cb.x) * invden;
        t.x = ep.x + (x > 0.f ? x : expm1f(x));
        x = (an.y + coef * cb.y) * invden;
        t.y = ep.y + (x > 0.f ? x : expm1f(x));
        x = (an.z + coef * cb.z) * invden;
        t.z = ep.z + (x > 0.f ? x : expm1f(x));
        x = (an.w + coef * cb.w) * invden;
        t.w = ep.w + (x > 0.f ? x : expm1f(x));
        tv[i] = t;
        s += t.x * t.x + t.y * t.y + t.z * t.z + t.w * t.w;
    }
    #pragma unroll
    for (int o = 16; o; o >>= 1) s += __shfl_xor_sync(0xFFFFFFFFu, s, o);
    float inv = 1.f / fmaxf(sqrtf(s), 1e-12f);
    #pragma unroll
    for (int i = 0; i < 4; i++) {
        if (i >= cnt) break;
        int ii = lane + i * 32;
        float4 t = tv[i];
        op[ii] = make_float4(t.x * inv, t.y * inv, t.z * inv, t.w * inv);
    }
}

// ---------------------------------------------------------------------------
// Final gather
// ---------------------------------------------------------------------------
__global__ void gather_out(const int* __restrict__ triples, const float* __restrict__ entn,
                           const float* __restrict__ reln, float4* __restrict__ out,
                           int B, int D) {
    int nv = D >> 2;
    int total = B * 3 * nv;
    int i = blockIdx.x * blockDim.x + threadIdx.x;
    int stride = gridDim.x * blockDim.x;
    for (; i < total; i += stride) {
        int d4 = i % nv;
        int bt = i / nv;
        int t = bt % 3;
        int b = bt / 3;
        int idx = triples[b * 3 + t];
        const float4* srcp = (t == 1) ? (const float4*)(reln + (size_t)idx * D)
                                      : (const float4*)(entn + (size_t)idx * D);
        out[i] = srcp[d4];
    }
}

// ---------------------------------------------------------------------------
// Launch
// ---------------------------------------------------------------------------
extern "C" void kernel_launch(void* const* d_in, const int* in_sizes, int n_in,
                              void* d_out, int out_size) {
    const int*   triples  = (const int*)d_in[0];
    const int*   nodelist = (const int*)d_in[1];
    const int*   edgelist = (const int*)d_in[2];
    const float* ent      = (const float*)d_in[3];
    const float* rel      = (const float*)d_in[4];
    const float* W1       = (const float*)d_in[5];
    const float* Wa       = (const float*)d_in[6];
    const float* g0       = (const float*)d_in[7];
    const float* WE       = (const float*)d_in[8];
    const float* WR       = (const float*)d_in[9];

    int B = in_sizes[0] / 3;
    int E = in_sizes[2];
    int D = in_sizes[6];
    int N = in_sizes[3] / D;
    int R = in_sizes[4] / D;

    float *e0, *Cbase, *Cedge, *Anew, *Epre, *reln, *denom, *abexp;
    int* flag;
    __nv_bfloat16 *e0h, *e0l, *egh, *egl, *edh, *edl, *w1h, *w1l, *weth, *wetl;
    cudaGetSymbolAddress((void**)&e0,    g_e0);
    cudaGetSymbolAddress((void**)&Cbase, g_Cbase);
    cudaGetSymbolAddress((void**)&Cedge, g_Cedge);
    cudaGetSymbolAddress((void**)&Anew,  g_Anew);
    cudaGetSymbolAddress((void**)&Epre,  g_Epre);
    cudaGetSymbolAddress((void**)&reln,  g_reln);
    cudaGetSymbolAddress((void**)&denom, g_denom);
    cudaGetSymbolAddress((void**)&abexp, g_abexp);
    cudaGetSymbolAddress((void**)&flag,  g_flag);
    cudaGetSymbolAddress((void**)&e0h,   g_e0h);
    cudaGetSymbolAddress((void**)&e0l,   g_e0l);
    cudaGetSymbolAddress((void**)&egh,   g_egh);
    cudaGetSymbolAddress((void**)&egl,   g_egl);
    cudaGetSymbolAddress((void**)&edh,   g_edh);
    cudaGetSymbolAddress((void**)&edl,   g_edl);
    cudaGetSymbolAddress((void**)&w1h,   g_w1h);
    cudaGetSymbolAddress((void**)&w1l,   g_w1l);
    cudaGetSymbolAddress((void**)&weth,  g_weth);
    cudaGetSymbolAddress((void**)&wetl,  g_wetl);

    cudaFuncSetAttribute(gemm_mma_kernel,
                         cudaFuncAttributeMaxDynamicSharedMemorySize, MM_SMEM_BYTES);

    // zero scratch accumulators
    {
        size_t n4 = ((size_t)N * D) >> 2;
        zero4_kernel<<<2048, 256>>>((float4*)Anew, n4);
        zero4_kernel<<<64, 256>>>((float4*)denom, (size_t)N >> 2);
        zero4_kernel<<<64, 256>>>((float4*)flag, (size_t)N >> 2);
    }

    normalize_split<<<(N + 7) / 8, 256>>>(ent, g0, e0, e0h, e0l, egh, egl, N, D);
    split_weights<<<(D * D + 255) / 256, 256>>>(W1, WE, w1h, w1l, weth, wetl, D);
    split_edge<<<(E + 7) / 8, 256>>>(e0, rel, nodelist + E, edgelist, edh, edl, E, D);

    dim3 gN((N + MM_BM - 1) / MM_BM, D / MM_BN);
    dim3 gE2((E + MM_BM - 1) / MM_BM, D / MM_BN);

    // Cbase = (e0 * g0) @ W1^T
    gemm_mma_kernel<<<gN, 512, MM_SMEM_BYTES>>>(egh, egl, w1h, w1l, Cbase, N, D);
    // Cedge = (e0[dst] * rel[edge]) @ W1^T
    gemm_mma_kernel<<<gE2, 512, MM_SMEM_BYTES>>>(edh, edl, w1h, w1l, Cedge, E, D);
    // Epre = e0 @ W_E
    gemm_mma_kernel<<<gN, 512, MM_SMEM_BYTES>>>(e0h, e0l, weth, wetl, Epre, N, D);

    baseline_reduce<<<(N + 7) / 8, 256>>>(e0, Cbase, Wa, abexp, N, D);
    edge_scatter<<<(E + 7) / 8, 256>>>(e0, Cedge, Wa, nodelist, Anew, denom, flag, E, D);
    combine_kernel<<<(N + 7) / 8, 256>>>(Anew, Cbase, Epre, denom, abexp, flag, e0, N, D);
    dim3 gR((R + 127) / 128, D / 128);
    gemm128_plain<<<gR, 256>>>(rel, WR, reln, R, D);
    int total4 = B * 3 * (D >> 2);
    gather_out<<<(total4 + 255) / 256, 256>>>(triples, e0, reln, (float4*)d_out, B, D);
}

// round 5
// speedup vs baseline: 2.7483x; 1.2139x over previous
#include <cuda_runtime.h>
#include <cuda_fp16.h>
#include <math.h>
#include <stdint.h>

// ---------------------------------------------------------------------------
// UPGAT layer.  N=100000, R=500, D=512, E=150000, B=4096.
// Big GEMMs: fp16 A (1 term) x fp16 hi/lo weights (2 passes) on mma.sync,
// fp32 accumulate.  cp.async 3-stage pipelined mainloop.
// ---------------------------------------------------------------------------

#define MAX_N 100000
#define MAX_E 150000
#define MAX_R 500
#define MAX_D 512

__device__ float g_e0   [(size_t)MAX_N * MAX_D];
__device__ float g_Cbase[(size_t)MAX_N * MAX_D];
__device__ float g_Cedge[(size_t)MAX_E * MAX_D];
__device__ float g_Anew [(size_t)MAX_N * MAX_D];
__device__ float g_Epre [(size_t)MAX_N * MAX_D];
__device__ float g_reln [(size_t)MAX_R * MAX_D];
__device__ float g_denom[MAX_N];
__device__ float g_abexp[MAX_N];
__device__ int   g_flag [MAX_N];

// fp16 operands (A single-precision-term; weights hi/lo)
__device__ __half g_e0h[(size_t)MAX_N * MAX_D];
__device__ __half g_egh[(size_t)MAX_N * MAX_D];
__device__ __half g_edh[(size_t)MAX_E * MAX_D];
__device__ __half g_w1h[MAX_D * MAX_D], g_w1l[MAX_D * MAX_D];
__device__ __half g_weth[MAX_D * MAX_D], g_wetl[MAX_D * MAX_D];

// ---------------------------------------------------------------------------
// helpers
// ---------------------------------------------------------------------------
__device__ __forceinline__ uint32_t smem_to_u32(const void* smem_ptr) {
    uint32_t addr;
    asm("{ .reg .u64 tmp; cvta.to.shared.u64 tmp, %1; cvt.u32.u64 %0, tmp; }"
        : "=r"(addr) : "l"(smem_ptr));
    return addr;
}
__device__ __forceinline__ void ldsm4(uint32_t addr, uint32_t& r0, uint32_t& r1,
                                      uint32_t& r2, uint32_t& r3) {
    asm volatile("ldmatrix.sync.aligned.m8n8.x4.shared.b16 {%0,%1,%2,%3}, [%4];"
                 : "=r"(r0), "=r"(r1), "=r"(r2), "=r"(r3) : "r"(addr));
}
__device__ __forceinline__ void mma_fp16(float* d, const uint32_t* a, const uint32_t* b) {
    asm volatile(
        "mma.sync.aligned.m16n8k16.row.col.f32.f16.f16.f32 "
        "{%0,%1,%2,%3}, {%4,%5,%6,%7}, {%8,%9}, {%0,%1,%2,%3};"
        : "+f"(d[0]), "+f"(d[1]), "+f"(d[2]), "+f"(d[3])
        : "r"(a[0]), "r"(a[1]), "r"(a[2]), "r"(a[3]), "r"(b[0]), "r"(b[1]));
}
__device__ __forceinline__ void cp16(uint32_t dst, const void* src, bool pred) {
    int sz = pred ? 16 : 0;
    asm volatile("cp.async.cg.shared.global [%0], [%1], 16, %2;"
                 :: "r"(dst), "l"(src), "r"(sz) : "memory");
}
__device__ __forceinline__ uint32_t pkh(__half a, __half b) {
    __half2 t = __halves2half2(a, b);
    return *reinterpret_cast<uint32_t*>(&t);
}
// round float4 -> 4 fp16 packed in uint2
__device__ __forceinline__ uint2 h4(float4 v) {
    return make_uint2(pkh(__float2half_rn(v.x), __float2half_rn(v.y)),
                      pkh(__float2half_rn(v.z), __float2half_rn(v.w)));
}

// ---------------------------------------------------------------------------
__global__ void zero4_kernel(float4* __restrict__ p, size_t n4) {
    size_t i = (size_t)blockIdx.x * blockDim.x + threadIdx.x;
    size_t stride = (size_t)gridDim.x * blockDim.x;
    float4 z = make_float4(0.f, 0.f, 0.f, 0.f);
    for (; i < n4; i += stride) p[i] = z;
}

// ---------------------------------------------------------------------------
// e0 = l2norm(ent); emit fp16 of e0 and e0*g0.  Warp per row.
// ---------------------------------------------------------------------------
__global__ void normalize_split(const float* __restrict__ in, const float* __restrict__ g0,
                                float* __restrict__ e0,
                                __half* __restrict__ e0h, __half* __restrict__ egh,
                                int M, int D) {
    int warp = (blockIdx.x * blockDim.x + threadIdx.x) >> 5;
    int lane = threadIdx.x & 31;
    if (warp >= M) return;
    const float4* ip = (const float4*)(in + (size_t)warp * D);
    const float4* gp = (const float4*)g0;
    float4* op = (float4*)(e0 + (size_t)warp * D);
    int nv = D >> 2;
    float s = 0.f;
    for (int i = lane; i < nv; i += 32) {
        float4 v = ip[i];
        s += v.x * v.x + v.y * v.y + v.z * v.z + v.w * v.w;
    }
    #pragma unroll
    for (int o = 16; o; o >>= 1) s += __shfl_xor_sync(0xFFFFFFFFu, s, o);
    float inv = 1.f / fmaxf(sqrtf(s), 1e-12f);
    size_t rbase = (size_t)warp * D;
    for (int i = lane; i < nv; i += 32) {
        float4 v = ip[i];
        float4 n = make_float4(v.x * inv, v.y * inv, v.z * inv, v.w * inv);
        op[i] = n;
        *(uint2*)(e0h + rbase + i * 4) = h4(n);
        float4 g = gp[i];
        *(uint2*)(egh + rbase + i * 4) =
            h4(make_float4(n.x * g.x, n.y * g.y, n.z * g.z, n.w * g.w));
    }
}

// ---------------------------------------------------------------------------
// Edge operand: A[e,:] = fp16(e0[dst[e],:] * rel[edge[e],:]).  Warp per edge.
// ---------------------------------------------------------------------------
__global__ void split_edge(const float* __restrict__ e0, const float* __restrict__ rel,
                           const int* __restrict__ dsts, const int* __restrict__ edges,
                           __half* __restrict__ eh, int E, int D) {
    int warp = (blockIdx.x * blockDim.x + threadIdx.x) >> 5;
    int lane = threadIdx.x & 31;
    if (warp >= E) return;
    int dst = dsts[warp];
    int rl = edges[warp];
    const float4* ap = (const float4*)(e0 + (size_t)dst * D);
    const float4* gp = (const float4*)(rel + (size_t)rl * D);
    size_t rbase = (size_t)warp * D;
    int nv = D >> 2;
    for (int i = lane; i < nv; i += 32) {
        float4 a = ap[i], g = gp[i];
        *(uint2*)(eh + rbase + i * 4) =
            h4(make_float4(a.x * g.x, a.y * g.y, a.z * g.z, a.w * g.w));
    }
}

// ---------------------------------------------------------------------------
// Weight splits (fp16 hi/lo): W1 as-is ([N,K]); WE transposed ([N,K]=WE[k,n]).
// ---------------------------------------------------------------------------
__global__ void split_weights(const float* __restrict__ W1, const float* __restrict__ WE,
                              __half* __restrict__ w1h, __half* __restrict__ w1l,
                              __half* __restrict__ weth, __half* __restrict__ wetl,
                              int D) {
    int i = blockIdx.x * blockDim.x + threadIdx.x;
    int tot = D * D;
    if (i >= tot) return;
    float v = W1[i];
    __half h = __float2half_rn(v);
    w1h[i] = h;
    w1l[i] = __float2half_rn(v - __half2float(h));
    int k = i / D, j = i % D;
    float u = WE[i];
    h = __float2half_rn(u);
    size_t o = (size_t)j * D + k;
    weth[o] = h;
    wetl[o] = __float2half_rn(u - __half2float(h));
}

// ---------------------------------------------------------------------------
// mma.sync fp16 GEMM: C[M,D] = A @ (Wh+Wl)^T,  W stored [N,K].
// CTA 128x256, BK=32, 512 threads (16 warps 4x4), warp tile 32x64.
// cp.async 3-stage pipeline; 10 ldsm4 per k16; 2 MMA passes.
// ---------------------------------------------------------------------------
#define MM_BM 128
#define MM_BN 256
#define MM_BK 32
#define MM_LD 40
static constexpr int MM_AH = 0;
static constexpr int MM_BH = 128 * MM_LD;                 // 5120 halves
static constexpr int MM_BL = 128 * MM_LD + 256 * MM_LD;   // 15360
static constexpr int MM_STAGE_H = 25600;                  // halves per stage
static constexpr int MM_STAGE_BYTES = MM_STAGE_H * 2;     // 51200
static constexpr int MM_SMEM_BYTES = 3 * MM_STAGE_BYTES;  // 153600

__global__ void __launch_bounds__(512, 1)
gemm_mma_kernel(const __half* __restrict__ A,
                const __half* __restrict__ Bh, const __half* __restrict__ Bl,
                float* __restrict__ C, int M, int D) {
    extern __shared__ __half sh[];
    uint32_t sbase = smem_to_u32(sh);
    int tid = threadIdx.x;
    int lane = tid & 31;
    int warp = tid >> 5;
    int mb = blockIdx.x * MM_BM;
    int nb = blockIdx.y * MM_BN;
    int wm = (warp >> 2) * 32;
    int wn = (warp & 3) * 64;
    const int nch = D / MM_BK;   // 16

    float acc[2][8][4];
    #pragma unroll
    for (int i = 0; i < 2; i++)
        #pragma unroll
        for (int j = 0; j < 8; j++)
            #pragma unroll
            for (int q = 0; q < 4; q++) acc[i][j][q] = 0.f;

    int arow = tid >> 2;
    int achk = (tid & 3) * 8;
    int gma = mb + arow;
    bool apred = gma < M;
    size_t abase = (size_t)(apred ? gma : 0) * D + achk;

    auto stage_load = [&](int ch) {
        if (ch < nch) {
            int kb = ch * MM_BK;
            uint32_t st = sbase + (ch % 3) * MM_STAGE_BYTES;
            cp16(st + (MM_AH + arow * MM_LD + achk) * 2, A + abase + kb, apred);
            #pragma unroll
            for (int i = 0; i < 2; i++) {
                int idx = tid + i * 512;
                int row = idx >> 2;
                int chk = (idx & 3) * 8;
                size_t go = (size_t)(nb + row) * D + kb + chk;
                cp16(st + (MM_BH + row * MM_LD + chk) * 2, Bh + go, true);
                cp16(st + (MM_BL + row * MM_LD + chk) * 2, Bl + go, true);
            }
        }
        asm volatile("cp.async.commit_group;" ::: "memory");
    };

    stage_load(0);
    stage_load(1);

    int a_r = (lane & 15);
    int a_c = (lane >> 4) << 3;
    int b_r = (lane & 7) + ((lane & 16) >> 1);
    int b_c = (lane & 8);

    for (int ch = 0; ch < nch; ch++) {
        asm volatile("cp.async.wait_group 1;" ::: "memory");
        __syncthreads();
        stage_load(ch + 2);

        uint32_t stb = sbase + (ch % 3) * MM_STAGE_BYTES;
        #pragma unroll
        for (int s16 = 0; s16 < 2; s16++) {
            int k0 = s16 * 16;
            uint32_t ah[2][4], bh[8][2], bl[8][2];
            #pragma unroll
            for (int mi = 0; mi < 2; mi++) {
                uint32_t addr = stb + (MM_AH + (wm + mi * 16 + a_r) * MM_LD + k0 + a_c) * 2;
                ldsm4(addr, ah[mi][0], ah[mi][1], ah[mi][2], ah[mi][3]);
            }
            #pragma unroll
            for (int nj = 0; nj < 4; nj++) {
                uint32_t addr = stb + (MM_BH + (wn + nj * 16 + b_r) * MM_LD + k0 + b_c) * 2;
                ldsm4(addr, bh[2 * nj][0], bh[2 * nj][1], bh[2 * nj + 1][0], bh[2 * nj + 1][1]);
            }
            #pragma unroll
            for (int mi = 0; mi < 2; mi++)
                #pragma unroll
                for (int nj = 0; nj < 8; nj++) mma_fp16(acc[mi][nj], ah[mi], bh[nj]);
            #pragma unroll
            for (int nj = 0; nj < 4; nj++) {
                uint32_t addr = stb + (MM_BL + (wn + nj * 16 + b_r) * MM_LD + k0 + b_c) * 2;
                ldsm4(addr, bl[2 * nj][0], bl[2 * nj][1], bl[2 * nj + 1][0], bl[2 * nj + 1][1]);
            }
            #pragma unroll
            for (int mi = 0; mi < 2; mi++)
                #pragma unroll
                for (int nj = 0; nj < 8; nj++) mma_fp16(acc[mi][nj], ah[mi], bl[nj]);
        }
        __syncthreads();
    }

    // epilogue
    #pragma unroll
    for (int mi = 0; mi < 2; mi++) {
        int gm0 = mb + wm + mi * 16 + (lane >> 2);
        int gm1 = gm0 + 8;
        #pragma unroll
        for (int nj = 0; nj < 8; nj++) {
            int gn = nb + wn + nj * 8 + (lane & 3) * 2;
            if (gm0 < M)
                *(float2*)(C + (size_t)gm0 * D + gn) = make_float2(acc[mi][nj][0], acc[mi][nj][1]);
            if (gm1 < M)
                *(float2*)(C + (size_t)gm1 * D + gn) = make_float2(acc[mi][nj][2], acc[mi][nj][3]);
        }
    }
}

// ---------------------------------------------------------------------------
// fp32 tiled SGEMM (tiny rel_new GEMM, R=500)
// ---------------------------------------------------------------------------
__global__ void gemm128_plain(const float* __restrict__ A0, const float* __restrict__ W,
                              float* __restrict__ C, int M, int D) {
    constexpr int BM = 128, BN = 128, BK = 16;
    __shared__ float As[BK][BM];
    __shared__ float Bs[BK][BN];
    int tid = threadIdx.x;
    int mb = blockIdx.x * BM;
    int nb = blockIdx.y * BN;
    int tx = tid & 15, ty = tid >> 4;
    float acc[8][8];
    #pragma unroll
    for (int i = 0; i < 8; i++)
        #pragma unroll
        for (int j = 0; j < 8; j++) acc[i][j] = 0.f;
    for (int kb = 0; kb < D; kb += BK) {
        #pragma unroll
        for (int i = 0; i < 2; i++) {
            int q = tid + i * 256;
            int row = q >> 2;
            int kc = (q & 3) << 2;
            int gr = mb + row;
            float4 v = make_float4(0.f, 0.f, 0.f, 0.f);
            if (gr < M) v = *(const float4*)(A0 + (size_t)gr * D + kb + kc);
            As[kc + 0][row] = v.x; As[kc + 1][row] = v.y;
            As[kc + 2][row] = v.z; As[kc + 3][row] = v.w;
        }
        #pragma unroll
        for (int i = 0; i < 2; i++) {
            int q = tid + i * 256;
            int kr = q >> 5;
            int jc = (q & 31) << 2;
            *(float4*)&Bs[kr][jc] = *(const float4*)(W + (size_t)(kb + kr) * D + nb + jc);
        }
        __syncthreads();
        #pragma unroll
        for (int k = 0; k < BK; k++) {
            float a[8], b[8];
            *(float4*)&a[0] = *(const float4*)&As[k][ty * 8];
            *(float4*)&a[4] = *(const float4*)&As[k][ty * 8 + 4];
            *(float4*)&b[0] = *(const float4*)&Bs[k][tx * 8];
            *(float4*)&b[4] = *(const float4*)&Bs[k][tx * 8 + 4];
            #pragma unroll
            for (int i = 0; i < 8; i++)
                #pragma unroll
                for (int j = 0; j < 8; j++)
                    acc[i][j] = fmaf(a[i], b[j], acc[i][j]);
        }
        __syncthreads();
    }
    #pragma unroll
    for (int i = 0; i < 8; i++) {
        int gr = mb + ty * 8 + i;
        if (gr < M) {
            float* cp = C + (size_t)gr * D + nb + tx * 8;
            *(float4*)(cp + 0) = make_float4(acc[i][0], acc[i][1], acc[i][2], acc[i][3]);
            *(float4*)(cp + 4) = make_float4(acc[i][4], acc[i][5], acc[i][6], acc[i][7]);
        }
    }
}

// ---------------------------------------------------------------------------
// Per-node baseline attention
// ---------------------------------------------------------------------------
__global__ void baseline_reduce(const float* __restrict__ e0, const float* __restrict__ Cb,
                                const float* __restrict__ Wa, float* __restrict__ abexp,
                                int N, int D) {
    int warp = (blockIdx.x * blockDim.x + threadIdx.x) >> 5;
    int lane = threadIdx.x & 31;
    if (warp >= N) return;
    const float4* ep = (const float4*)(e0 + (size_t)warp * D);
    const float4* cp = (const float4*)(Cb + (size_t)warp * D);
    const float4* wp = (const float4*)Wa;
    int nv = D >> 2;
    float s = 0.f;
    for (int i = lane; i < nv; i += 32) {
        float4 e = ep[i], c = cp[i], w = wp[i];
        s += e.x * tanhf(c.x) * w.x + e.y * tanhf(c.y) * w.y +
             e.z * tanhf(c.z) * w.z + e.w * tanhf(c.w) * w.w;
    }
    #pragma unroll
    for (int o = 16; o; o >>= 1) s += __shfl_xor_sync(0xFFFFFFFFu, s, o);
    if (lane == 0) {
        float l = s > 0.f ? s : 0.2f * s;
        abexp[warp] = expf(-l);
    }
}

// ---------------------------------------------------------------------------
// Per-edge attention + scatter
// ---------------------------------------------------------------------------
__global__ void edge_scatter(const float* __restrict__ e0, const float* __restrict__ Ce,
                             const float* __restrict__ Wa, const int* __restrict__ srcs,
                             float* __restrict__ Anew, float* __restrict__ denom,
                             int* __restrict__ flag, int E, int D) {
    int warp = (blockIdx.x * blockDim.x + threadIdx.x) >> 5;
    int lane = threadIdx.x & 31;
    if (warp >= E) return;
    int src = srcs[warp];
    const float4* cp = (const float4*)(Ce + (size_t)warp * D);
    const float4* ep = (const float4*)(e0 + (size_t)src * D);
    const float4* wp = (const float4*)Wa;
    int cnt = D >> 7;
    float4 cv[4];
    float s = 0.f;
    #pragma unroll
    for (int i = 0; i < 4; i++) {
        if (i >= cnt) break;
        int ii = lane + i * 32;
        float4 c = cp[ii];
        cv[i] = c;
        float4 e = ep[ii], w = wp[ii];
        s += e.x * tanhf(c.x) * w.x + e.y * tanhf(c.y) * w.y +
             e.z * tanhf(c.z) * w.z + e.w * tanhf(c.w) * w.w;
    }
    #pragma unroll
    for (int o = 16; o; o >>= 1) s += __shfl_xor_sync(0xFFFFFFFFu, s, o);
    float l = s > 0.f ? s : 0.2f * s;
    float aexp = expf(-l);
    if (lane == 0) {
        atomicAdd(&denom[src], aexp);
        flag[src] = 1;
    }
    float* ap = Anew + (size_t)src * D;
    #pragma unroll
    for (int i = 0; i < 4; i++) {
        if (i >= cnt) break;
        int d = (lane + i * 32) << 2;
        atomicAdd(ap + d + 0, aexp * cv[i].x);
        atomicAdd(ap + d + 1, aexp * cv[i].y);
        atomicAdd(ap + d + 2, aexp * cv[i].z);
        atomicAdd(ap + d + 3, aexp * cv[i].w);
    }
}

// ---------------------------------------------------------------------------
// Combine + ELU + residual + l2norm
// ---------------------------------------------------------------------------
__global__ void combine_kernel(const float* __restrict__ Anew, const float* __restrict__ Cb,
                               const float* __restrict__ Epre, const float* __restrict__ denom,
                               const float* __restrict__ abexp, const int* __restrict__ flag,
                               float* __restrict__ entnew, int N, int D) {
    int warp = (blockIdx.x * blockDim.x + threadIdx.x) >> 5;
    int lane = threadIdx.x & 31;
    if (warp >= N) return;
    float ab = abexp[warp];
    int fl = flag[warp];
    float coef = fl ? ab : 0.f;
    float den = denom[warp] + coef;
    if (den == 0.f) den = 1e-12f;
    float invden = 1.f / den;
    const float4* anp = (const float4*)(Anew + (size_t)warp * D);
    const float4* cbp = (const float4*)(Cb + (size_t)warp * D);
    const float4* epp = (const float4*)(Epre + (size_t)warp * D);
    float4* op = (float4*)(entnew + (size_t)warp * D);
    int cnt = D >> 7;
    float4 tv[4];
    float s = 0.f;
    #pragma unroll
    for (int i = 0; i < 4; i++) {
        if (i >= cnt) break;
        int ii = lane + i * 32;
        float4 an = anp[ii], cb = cbp[ii], ep = epp[ii];
        float4 t;
        float x = (an.x + coef * cb.x) * invden;
        t.x = ep.x + (x > 0.f ? x : expm1f(x));
        x = (an.y + coef * cb.y) * invden;
        t.y = ep.y + (x > 0.f ? x : expm1f(x));
        x = (an.z + coef * cb.z) * invden;
        t.z = ep.z + (x > 0.f ? x : expm1f(x));
        x = (an.w + coef * cb.w) * invden;
        t.w = ep.w + (x > 0.f ? x : expm1f(x));
        tv[i] = t;
        s += t.x * t.x + t.y * t.y + t.z * t.z + t.w * t.w;
    }
    #pragma unroll
    for (int o = 16; o; o >>= 1) s += __shfl_xor_sync(0xFFFFFFFFu, s, o);
    float inv = 1.f / fmaxf(sqrtf(s), 1e-12f);
    #pragma unroll
    for (int i = 0; i < 4; i++) {
        if (i >= cnt) break;
        int ii = lane + i * 32;
        float4 t = tv[i];
        op[ii] = make_float4(t.x * inv, t.y * inv, t.z * inv, t.w * inv);
    }
}

// ---------------------------------------------------------------------------
// Final gather
// ---------------------------------------------------------------------------
__global__ void gather_out(const int* __restrict__ triples, const float* __restrict__ entn,
                           const float* __restrict__ reln, float4* __restrict__ out,
                           int B, int D) {
    int nv = D >> 2;
    int total = B * 3 * nv;
    int i = blockIdx.x * blockDim.x + threadIdx.x;
    int stride = gridDim.x * blockDim.x;
    for (; i < total; i += stride) {
        int d4 = i % nv;
        int bt = i / nv;
        int t = bt % 3;
        int b = bt / 3;
        int idx = triples[b * 3 + t];
        const float4* srcp = (t == 1) ? (const float4*)(reln + (size_t)idx * D)
                                      : (const float4*)(entn + (size_t)idx * D);
        out[i] = srcp[d4];
    }
}

// ---------------------------------------------------------------------------
// Launch
// ---------------------------------------------------------------------------
extern "C" void kernel_launch(void* const* d_in, const int* in_sizes, int n_in,
                              void* d_out, int out_size) {
    const int*   triples  = (const int*)d_in[0];
    const int*   nodelist = (const int*)d_in[1];
    const int*   edgelist = (const int*)d_in[2];
    const float* ent      = (const float*)d_in[3];
    const float* rel      = (const float*)d_in[4];
    const float* W1       = (const float*)d_in[5];
    const float* Wa       = (const float*)d_in[6];
    const float* g0       = (const float*)d_in[7];
    const float* WE       = (const float*)d_in[8];
    const float* WR       = (const float*)d_in[9];

    int B = in_sizes[0] / 3;
    int E = in_sizes[2];
    int D = in_sizes[6];
    int N = in_sizes[3] / D;
    int R = in_sizes[4] / D;

    float *e0, *Cbase, *Cedge, *Anew, *Epre, *reln, *denom, *abexp;
    int* flag;
    __half *e0h, *egh, *edh, *w1h, *w1l, *weth, *wetl;
    cudaGetSymbolAddress((void**)&e0,    g_e0);
    cudaGetSymbolAddress((void**)&Cbase, g_Cbase);
    cudaGetSymbolAddress((void**)&Cedge, g_Cedge);
    cudaGetSymbolAddress((void**)&Anew,  g_Anew);
    cudaGetSymbolAddress((void**)&Epre,  g_Epre);
    cudaGetSymbolAddress((void**)&reln,  g_reln);
    cudaGetSymbolAddress((void**)&denom, g_denom);
    cudaGetSymbolAddress((void**)&abexp, g_abexp);
    cudaGetSymbolAddress((void**)&flag,  g_flag);
    cudaGetSymbolAddress((void**)&e0h,   g_e0h);
    cudaGetSymbolAddress((void**)&egh,   g_egh);
    cudaGetSymbolAddress((void**)&edh,   g_edh);
    cudaGetSymbolAddress((void**)&w1h,   g_w1h);
    cudaGetSymbolAddress((void**)&w1l,   g_w1l);
    cudaGetSymbolAddress((void**)&weth,  g_weth);
    cudaGetSymbolAddress((void**)&wetl,  g_wetl);

    cudaFuncSetAttribute(gemm_mma_kernel,
                         cudaFuncAttributeMaxDynamicSharedMemorySize, MM_SMEM_BYTES);

    // zero scratch accumulators
    {
        size_t n4 = ((size_t)N * D) >> 2;
        zero4_kernel<<<2048, 256>>>((float4*)Anew, n4);
        zero4_kernel<<<64, 256>>>((float4*)denom, (size_t)N >> 2);
        zero4_kernel<<<64, 256>>>((float4*)flag, (size_t)N >> 2);
    }

    normalize_split<<<(N + 7) / 8, 256>>>(ent, g0, e0, e0h, egh, N, D);
    split_weights<<<(D * D + 255) / 256, 256>>>(W1, WE, w1h, w1l, weth, wetl, D);
    split_edge<<<(E + 7) / 8, 256>>>(e0, rel, nodelist + E, edgelist, edh, E, D);

    dim3 gN((N + MM_BM - 1) / MM_BM, D / MM_BN);
    dim3 gE2((E + MM_BM - 1) / MM_BM, D / MM_BN);

    // Cbase = (e0 * g0) @ W1^T
    gemm_mma_kernel<<<gN, 512, MM_SMEM_BYTES>>>(egh, w1h, w1l, Cbase, N, D);
    // Cedge = (e0[dst] * rel[edge]) @ W1^T
    gemm_mma_kernel<<<gE2, 512, MM_SMEM_BYTES>>>(edh, w1h, w1l, Cedge, E, D);
    // Epre = e0 @ W_E
    gemm_mma_kernel<<<gN, 512, MM_SMEM_BYTES>>>(e0h, weth, wetl, Epre, N, D);

    baseline_reduce<<<(N + 7) / 8, 256>>>(e0, Cbase, Wa, abexp, N, D);
    edge_scatter<<<(E + 7) / 8, 256>>>(e0, Cedge, Wa, nodelist, Anew, denom, flag, E, D);
    combine_kernel<<<(N + 7) / 8, 256>>>(Anew, Cbase, Epre, denom, abexp, flag, e0, N, D);
    dim3 gR((R + 127) / 128, D / 128);
    gemm128_plain<<<gR, 256>>>(rel, WR, reln, R, D);
    int total4 = B * 3 * (D >> 2);
    gather_out<<<(total4 + 255) / 256, 256>>>(triples, e0, reln, (float4*)d_out, B, D);
}

// round 6
// speedup vs baseline: 3.0066x; 1.0940x over previous
#include <cuda_runtime.h>
#include <cuda_fp16.h>
#include <math.h>
#include <stdint.h>

// ---------------------------------------------------------------------------
// UPGAT layer.  N=100000, R=500, D=512, E=150000, B=4096.
// GEMMs: fp16 A x fp16 hi/lo weights (2 passes) on mma.sync, fp32 accumulate.
// Aggregation: pull-style CSR (no big atomics), fully fused epilogue.
// ---------------------------------------------------------------------------

#define MAX_N 100000
#define MAX_E 150000
#define MAX_R 500
#define MAX_D 512

__device__ float g_e0   [(size_t)MAX_N * MAX_D];
__device__ float g_Cbase[(size_t)MAX_N * MAX_D];
__device__ float g_Cedge[(size_t)MAX_E * MAX_D];
__device__ float g_Epre [(size_t)MAX_N * MAX_D];
__device__ float g_reln [(size_t)MAX_R * MAX_D];

// CSR scratch
__device__ int g_cnt [MAX_N];
__device__ int g_off [MAX_N + 1];
__device__ int g_cur [MAX_N];
__device__ int g_eidx[MAX_E];
__device__ int g_bsum[128];

// fp16 operands
__device__ __half g_e0h[(size_t)MAX_N * MAX_D];
__device__ __half g_egh[(size_t)MAX_N * MAX_D];
__device__ __half g_edh[(size_t)MAX_E * MAX_D];
__device__ __half g_w1h[MAX_D * MAX_D], g_w1l[MAX_D * MAX_D];
__device__ __half g_weth[MAX_D * MAX_D], g_wetl[MAX_D * MAX_D];

// ---------------------------------------------------------------------------
// helpers
// ---------------------------------------------------------------------------
__device__ __forceinline__ uint32_t smem_to_u32(const void* smem_ptr) {
    uint32_t addr;
    asm("{ .reg .u64 tmp; cvta.to.shared.u64 tmp, %1; cvt.u32.u64 %0, tmp; }"
        : "=r"(addr) : "l"(smem_ptr));
    return addr;
}
__device__ __forceinline__ void ldsm4(uint32_t addr, uint32_t& r0, uint32_t& r1,
                                      uint32_t& r2, uint32_t& r3) {
    asm volatile("ldmatrix.sync.aligned.m8n8.x4.shared.b16 {%0,%1,%2,%3}, [%4];"
                 : "=r"(r0), "=r"(r1), "=r"(r2), "=r"(r3) : "r"(addr));
}
__device__ __forceinline__ void mma_fp16(float* d, const uint32_t* a, const uint32_t* b) {
    asm volatile(
        "mma.sync.aligned.m16n8k16.row.col.f32.f16.f16.f32 "
        "{%0,%1,%2,%3}, {%4,%5,%6,%7}, {%8,%9}, {%0,%1,%2,%3};"
        : "+f"(d[0]), "+f"(d[1]), "+f"(d[2]), "+f"(d[3])
        : "r"(a[0]), "r"(a[1]), "r"(a[2]), "r"(a[3]), "r"(b[0]), "r"(b[1]));
}
__device__ __forceinline__ void cp16(uint32_t dst, const void* src, bool pred) {
    int sz = pred ? 16 : 0;
    asm volatile("cp.async.cg.shared.global [%0], [%1], 16, %2;"
                 :: "r"(dst), "l"(src), "r"(sz) : "memory");
}
__device__ __forceinline__ uint32_t pkh(__half a, __half b) {
    __half2 t = __halves2half2(a, b);
    return *reinterpret_cast<uint32_t*>(&t);
}
__device__ __forceinline__ uint2 h4(float4 v) {
    return make_uint2(pkh(__float2half_rn(v.x), __float2half_rn(v.y)),
                      pkh(__float2half_rn(v.z), __float2half_rn(v.w)));
}

// ---------------------------------------------------------------------------
__global__ void zero_int(int* __restrict__ p, int n) {
    int i = blockIdx.x * blockDim.x + threadIdx.x;
    if (i < n) p[i] = 0;
}

// ---------------------------------------------------------------------------
// e0 = l2norm(ent); emit fp16 of e0 and e0*g0.  Warp per row.
// ---------------------------------------------------------------------------
__global__ void normalize_split(const float* __restrict__ in, const float* __restrict__ g0,
                                float* __restrict__ e0,
                                __half* __restrict__ e0h, __half* __restrict__ egh,
                                int M, int D) {
    int warp = (blockIdx.x * blockDim.x + threadIdx.x) >> 5;
    int lane = threadIdx.x & 31;
    if (warp >= M) return;
    const float4* ip = (const float4*)(in + (size_t)warp * D);
    const float4* gp = (const float4*)g0;
    float4* op = (float4*)(e0 + (size_t)warp * D);
    int nv = D >> 2;
    float s = 0.f;
    for (int i = lane; i < nv; i += 32) {
        float4 v = ip[i];
        s += v.x * v.x + v.y * v.y + v.z * v.z + v.w * v.w;
    }
    #pragma unroll
    for (int o = 16; o; o >>= 1) s += __shfl_xor_sync(0xFFFFFFFFu, s, o);
    float inv = 1.f / fmaxf(sqrtf(s), 1e-12f);
    size_t rbase = (size_t)warp * D;
    for (int i = lane; i < nv; i += 32) {
        float4 v = ip[i];
        float4 n = make_float4(v.x * inv, v.y * inv, v.z * inv, v.w * inv);
        op[i] = n;
        *(uint2*)(e0h + rbase + i * 4) = h4(n);
        float4 g = gp[i];
        *(uint2*)(egh + rbase + i * 4) =
            h4(make_float4(n.x * g.x, n.y * g.y, n.z * g.z, n.w * g.w));
    }
}

// ---------------------------------------------------------------------------
// Edge operand: A[e,:] = fp16(e0[dst[e],:] * rel[edge[e],:]).  Warp per edge.
// ---------------------------------------------------------------------------
__global__ void split_edge(const float* __restrict__ e0, const float* __restrict__ rel,
                           const int* __restrict__ dsts, const int* __restrict__ edges,
                           __half* __restrict__ eh, int E, int D) {
    int warp = (blockIdx.x * blockDim.x + threadIdx.x) >> 5;
    int lane = threadIdx.x & 31;
    if (warp >= E) return;
    int dst = dsts[warp];
    int rl = edges[warp];
    const float4* ap = (const float4*)(e0 + (size_t)dst * D);
    const float4* gp = (const float4*)(rel + (size_t)rl * D);
    size_t rbase = (size_t)warp * D;
    int nv = D >> 2;
    for (int i = lane; i < nv; i += 32) {
        float4 a = ap[i], g = gp[i];
        *(uint2*)(eh + rbase + i * 4) =
            h4(make_float4(a.x * g.x, a.y * g.y, a.z * g.z, a.w * g.w));
    }
}

// ---------------------------------------------------------------------------
// Weight splits (fp16 hi/lo): W1 as-is ([N,K]); WE transposed.
// ---------------------------------------------------------------------------
__global__ void split_weights(const float* __restrict__ W1, const float* __restrict__ WE,
                              __half* __restrict__ w1h, __half* __restrict__ w1l,
                              __half* __restrict__ weth, __half* __restrict__ wetl,
                              int D) {
    int i = blockIdx.x * blockDim.x + threadIdx.x;
    int tot = D * D;
    if (i >= tot) return;
    float v = W1[i];
    __half h = __float2half_rn(v);
    w1h[i] = h;
    w1l[i] = __float2half_rn(v - __half2float(h));
    int k = i / D, j = i % D;
    float u = WE[i];
    h = __float2half_rn(u);
    size_t o = (size_t)j * D + k;
    weth[o] = h;
    wetl[o] = __float2half_rn(u - __half2float(h));
}

// ---------------------------------------------------------------------------
// CSR build
// ---------------------------------------------------------------------------
__global__ void count_deg(const int* __restrict__ srcs, int* __restrict__ cnt, int E) {
    int e = blockIdx.x * blockDim.x + threadIdx.x;
    if (e < E) atomicAdd(&cnt[srcs[e]], 1);
}
// block-wise exclusive scan (1024/block)
__global__ void scan1(const int* __restrict__ cnt, int* __restrict__ off,
                      int* __restrict__ bsum, int N) {
    __shared__ int sm[1024];
    int tid = threadIdx.x;
    int i = blockIdx.x * 1024 + tid;
    int v = (i < N) ? cnt[i] : 0;
    sm[tid] = v;
    __syncthreads();
    #pragma unroll
    for (int d = 1; d < 1024; d <<= 1) {
        int t = (tid >= d) ? sm[tid - d] : 0;
        __syncthreads();
        sm[tid] += t;
        __syncthreads();
    }
    if (i < N) off[i] = sm[tid] - v;
    if (tid == 1023) bsum[blockIdx.x] = sm[1023];
}
// scan of block sums (single block, up to 1024 blocks)
__global__ void scan2(int* __restrict__ bsum, int nb) {
    __shared__ int sm[1024];
    int tid = threadIdx.x;
    int v = (tid < nb) ? bsum[tid] : 0;
    sm[tid] = v;
    __syncthreads();
    #pragma unroll
    for (int d = 1; d < 1024; d <<= 1) {
        int t = (tid >= d) ? sm[tid - d] : 0;
        __syncthreads();
        sm[tid] += t;
        __syncthreads();
    }
    if (tid < nb) bsum[tid] = sm[tid] - v;   // exclusive
}
__global__ void scan3(int* __restrict__ off, int* __restrict__ cur,
                      const int* __restrict__ bsum, int N, int E) {
    int i = blockIdx.x * blockDim.x + threadIdx.x;
    if (i < N) {
        int o = off[i] + bsum[i >> 10];
        off[i] = o;
        cur[i] = o;
    }
    if (i == 0) off[N] = E;
}
__global__ void fill_eidx(const int* __restrict__ srcs, int* __restrict__ cur,
                          int* __restrict__ eidx, int E) {
    int e = blockIdx.x * blockDim.x + threadIdx.x;
    if (e < E) {
        int pos = atomicAdd(&cur[srcs[e]], 1);
        eidx[pos] = e;
    }
}

// ---------------------------------------------------------------------------
// Fused node aggregation: warp per node.
//   e0r = e0[n]; cb = Cbase[n]; sb = sum(e0r*tanh(cb)*Wa); ab = exp(-leaky(sb))
//   acc = (deg>0 ? ab : 0)*cb; den = same
//   for each edge e of n: c = Cedge[e]; s = sum(e0r*tanh(c)*Wa);
//        aexp = exp(-leaky(s)); acc += aexp*c; den += aexp
//   x = acc / (den==0 ? eps : den); out = l2norm(Epre[n] + elu(x))
// ---------------------------------------------------------------------------
__global__ void node_aggregate(const float* __restrict__ e0, const float* __restrict__ Cb,
                               const float* __restrict__ Ce, const float* __restrict__ Epre,
                               const float* __restrict__ Wa,
                               const int* __restrict__ off, const int* __restrict__ eidx,
                               float* __restrict__ entnew, int N, int D) {
    __shared__ float waS[512];
    for (int i = threadIdx.x; i < D; i += blockDim.x) waS[i] = Wa[i];
    __syncthreads();

    int warp = (blockIdx.x * blockDim.x + threadIdx.x) >> 5;
    int lane = threadIdx.x & 31;
    if (warp >= N) return;
    int o0 = off[warp], o1 = off[warp + 1];
    int deg = o1 - o0;

    const float4* ep = (const float4*)(e0 + (size_t)warp * D);
    const float4* cbp = (const float4*)(Cb + (size_t)warp * D);
    const float4* wp = (const float4*)waS;

    // registers: 4 float4 per lane covers D=512 (lane + i*32)
    float4 er[4], wr[4], acc[4];
    float sb = 0.f;
    #pragma unroll
    for (int i = 0; i < 4; i++) {
        int ii = lane + i * 32;
        er[i] = ep[ii];
        wr[i] = wp[ii];
        float4 c = cbp[ii];
        acc[i] = c;   // stash cb in acc temporarily (will scale by coef)
        sb += er[i].x * tanhf(c.x) * wr[i].x + er[i].y * tanhf(c.y) * wr[i].y +
              er[i].z * tanhf(c.z) * wr[i].z + er[i].w * tanhf(c.w) * wr[i].w;
    }
    #pragma unroll
    for (int o = 16; o; o >>= 1) sb += __shfl_xor_sync(0xFFFFFFFFu, sb, o);
    float lb = sb > 0.f ? sb : 0.2f * sb;
    float ab = expf(-lb);
    float coef = (deg > 0) ? ab : 0.f;
    float den = coef;
    #pragma unroll
    for (int i = 0; i < 4; i++) {
        acc[i].x *= coef; acc[i].y *= coef; acc[i].z *= coef; acc[i].w *= coef;
    }

    for (int j = o0; j < o1; j++) {
        int e = eidx[j];
        const float4* cp = (const float4*)(Ce + (size_t)e * D);
        float4 cv[4];
        float s = 0.f;
        #pragma unroll
        for (int i = 0; i < 4; i++) {
            int ii = lane + i * 32;
            float4 c = cp[ii];
            cv[i] = c;
            s += er[i].x * tanhf(c.x) * wr[i].x + er[i].y * tanhf(c.y) * wr[i].y +
                 er[i].z * tanhf(c.z) * wr[i].z + er[i].w * tanhf(c.w) * wr[i].w;
        }
        #pragma unroll
        for (int o = 16; o; o >>= 1) s += __shfl_xor_sync(0xFFFFFFFFu, s, o);
        float l = s > 0.f ? s : 0.2f * s;
        float aexp = expf(-l);
        den += aexp;
        #pragma unroll
        for (int i = 0; i < 4; i++) {
            acc[i].x = fmaf(aexp, cv[i].x, acc[i].x);
            acc[i].y = fmaf(aexp, cv[i].y, acc[i].y);
            acc[i].z = fmaf(aexp, cv[i].z, acc[i].z);
            acc[i].w = fmaf(aexp, cv[i].w, acc[i].w);
        }
    }

    if (den == 0.f) den = 1e-12f;
    float invden = 1.f / den;
    const float4* epp = (const float4*)(Epre + (size_t)warp * D);
    float4* op = (float4*)(entnew + (size_t)warp * D);
    float nrm = 0.f;
    float4 tv[4];
    #pragma unroll
    for (int i = 0; i < 4; i++) {
        int ii = lane + i * 32;
        float4 ep4 = epp[ii];
        float4 t;
        float x = acc[i].x * invden; t.x = ep4.x + (x > 0.f ? x : expm1f(x));
        x = acc[i].y * invden;       t.y = ep4.y + (x > 0.f ? x : expm1f(x));
        x = acc[i].z * invden;       t.z = ep4.z + (x > 0.f ? x : expm1f(x));
        x = acc[i].w * invden;       t.w = ep4.w + (x > 0.f ? x : expm1f(x));
        tv[i] = t;
        nrm += t.x * t.x + t.y * t.y + t.z * t.z + t.w * t.w;
    }
    #pragma unroll
    for (int o = 16; o; o >>= 1) nrm += __shfl_xor_sync(0xFFFFFFFFu, nrm, o);
    float inv = 1.f / fmaxf(sqrtf(nrm), 1e-12f);
    #pragma unroll
    for (int i = 0; i < 4; i++) {
        int ii = lane + i * 32;
        float4 t = tv[i];
        op[ii] = make_float4(t.x * inv, t.y * inv, t.z * inv, t.w * inv);
    }
}

// ---------------------------------------------------------------------------
// mma.sync fp16 GEMM: C[M,D] = A @ (Wh+Wl)^T,  W stored [N,K].
// ---------------------------------------------------------------------------
#define MM_BM 128
#define MM_BN 256
#define MM_BK 32
#define MM_LD 40
static constexpr int MM_AH = 0;
static constexpr int MM_BH = 128 * MM_LD;
static constexpr int MM_BL = 128 * MM_LD + 256 * MM_LD;
static constexpr int MM_STAGE_H = 25600;
static constexpr int MM_STAGE_BYTES = MM_STAGE_H * 2;
static constexpr int MM_SMEM_BYTES = 3 * MM_STAGE_BYTES;

__global__ void __launch_bounds__(512, 1)
gemm_mma_kernel(const __half* __restrict__ A,
                const __half* __restrict__ Bh, const __half* __restrict__ Bl,
                float* __restrict__ C, int M, int D) {
    extern __shared__ __half sh[];
    uint32_t sbase = smem_to_u32(sh);
    int tid = threadIdx.x;
    int lane = tid & 31;
    int warp = tid >> 5;
    int mb = blockIdx.x * MM_BM;
    int nb = blockIdx.y * MM_BN;
    int wm = (warp >> 2) * 32;
    int wn = (warp & 3) * 64;
    const int nch = D / MM_BK;

    float acc[2][8][4];
    #pragma unroll
    for (int i = 0; i < 2; i++)
        #pragma unroll
        for (int j = 0; j < 8; j++)
            #pragma unroll
            for (int q = 0; q < 4; q++) acc[i][j][q] = 0.f;

    int arow = tid >> 2;
    int achk = (tid & 3) * 8;
    int gma = mb + arow;
    bool apred = gma < M;
    size_t abase = (size_t)(apred ? gma : 0) * D + achk;

    auto stage_load = [&](int ch) {
        if (ch < nch) {
            int kb = ch * MM_BK;
            uint32_t st = sbase + (ch % 3) * MM_STAGE_BYTES;
            cp16(st + (MM_AH + arow * MM_LD + achk) * 2, A + abase + kb, apred);
            #pragma unroll
            for (int i = 0; i < 2; i++) {
                int idx = tid + i * 512;
                int row = idx >> 2;
                int chk = (idx & 3) * 8;
                size_t go = (size_t)(nb + row) * D + kb + chk;
                cp16(st + (MM_BH + row * MM_LD + chk) * 2, Bh + go, true);
                cp16(st + (MM_BL + row * MM_LD + chk) * 2, Bl + go, true);
            }
        }
        asm volatile("cp.async.commit_group;" ::: "memory");
    };

    stage_load(0);
    stage_load(1);

    int a_r = (lane & 15);
    int a_c = (lane >> 4) << 3;
    int b_r = (lane & 7) + ((lane & 16) >> 1);
    int b_c = (lane & 8);

    for (int ch = 0; ch < nch; ch++) {
        asm volatile("cp.async.wait_group 1;" ::: "memory");
        __syncthreads();
        stage_load(ch + 2);

        uint32_t stb = sbase + (ch % 3) * MM_STAGE_BYTES;
        #pragma unroll
        for (int s16 = 0; s16 < 2; s16++) {
            int k0 = s16 * 16;
            uint32_t ah[2][4], bh[8][2], bl[8][2];
            #pragma unroll
            for (int mi = 0; mi < 2; mi++) {
                uint32_t addr = stb + (MM_AH + (wm + mi * 16 + a_r) * MM_LD + k0 + a_c) * 2;
                ldsm4(addr, ah[mi][0], ah[mi][1], ah[mi][2], ah[mi][3]);
            }
            #pragma unroll
            for (int nj = 0; nj < 4; nj++) {
                uint32_t addr = stb + (MM_BH + (wn + nj * 16 + b_r) * MM_LD + k0 + b_c) * 2;
                ldsm4(addr, bh[2 * nj][0], bh[2 * nj][1], bh[2 * nj + 1][0], bh[2 * nj + 1][1]);
            }
            #pragma unroll
            for (int mi = 0; mi < 2; mi++)
                #pragma unroll
                for (int nj = 0; nj < 8; nj++) mma_fp16(acc[mi][nj], ah[mi], bh[nj]);
            #pragma unroll
            for (int nj = 0; nj < 4; nj++) {
                uint32_t addr = stb + (MM_BL + (wn + nj * 16 + b_r) * MM_LD + k0 + b_c) * 2;
                ldsm4(addr, bl[2 * nj][0], bl[2 * nj][1], bl[2 * nj + 1][0], bl[2 * nj + 1][1]);
            }
            #pragma unroll
            for (int mi = 0; mi < 2; mi++)
                #pragma unroll
                for (int nj = 0; nj < 8; nj++) mma_fp16(acc[mi][nj], ah[mi], bl[nj]);
        }
        __syncthreads();
    }

    #pragma unroll
    for (int mi = 0; mi < 2; mi++) {
        int gm0 = mb + wm + mi * 16 + (lane >> 2);
        int gm1 = gm0 + 8;
        #pragma unroll
        for (int nj = 0; nj < 8; nj++) {
            int gn = nb + wn + nj * 8 + (lane & 3) * 2;
            if (gm0 < M)
                *(float2*)(C + (size_t)gm0 * D + gn) = make_float2(acc[mi][nj][0], acc[mi][nj][1]);
            if (gm1 < M)
                *(float2*)(C + (size_t)gm1 * D + gn) = make_float2(acc[mi][nj][2], acc[mi][nj][3]);
        }
    }
}

// ---------------------------------------------------------------------------
// fp32 tiled SGEMM (tiny rel_new GEMM, R=500)
// ---------------------------------------------------------------------------
__global__ void gemm128_plain(const float* __restrict__ A0, const float* __restrict__ W,
                              float* __restrict__ C, int M, int D) {
    constexpr int BM = 128, BN = 128, BK = 16;
    __shared__ float As[BK][BM];
    __shared__ float Bs[BK][BN];
    int tid = threadIdx.x;
    int mb = blockIdx.x * BM;
    int nb = blockIdx.y * BN;
    int tx = tid & 15, ty = tid >> 4;
    float acc[8][8];
    #pragma unroll
    for (int i = 0; i < 8; i++)
        #pragma unroll
        for (int j = 0; j < 8; j++) acc[i][j] = 0.f;
    for (int kb = 0; kb < D; kb += BK) {
        #pragma unroll
        for (int i = 0; i < 2; i++) {
            int q = tid + i * 256;
            int row = q >> 2;
            int kc = (q & 3) << 2;
            int gr = mb + row;
            float4 v = make_float4(0.f, 0.f, 0.f, 0.f);
            if (gr < M) v = *(const float4*)(A0 + (size_t)gr * D + kb + kc);
            As[kc + 0][row] = v.x; As[kc + 1][row] = v.y;
            As[kc + 2][row] = v.z; As[kc + 3][row] = v.w;
        }
        #pragma unroll
        for (int i = 0; i < 2; i++) {
            int q = tid + i * 256;
            int kr = q >> 5;
            int jc = (q & 31) << 2;
            *(float4*)&Bs[kr][jc] = *(const float4*)(W + (size_t)(kb + kr) * D + nb + jc);
        }
        __syncthreads();
        #pragma unroll
        for (int k = 0; k < BK; k++) {
            float a[8], b[8];
            *(float4*)&a[0] = *(const float4*)&As[k][ty * 8];
            *(float4*)&a[4] = *(const float4*)&As[k][ty * 8 + 4];
            *(float4*)&b[0] = *(const float4*)&Bs[k][tx * 8];
            *(float4*)&b[4] = *(const float4*)&Bs[k][tx * 8 + 4];
            #pragma unroll
            for (int i = 0; i < 8; i++)
                #pragma unroll
                for (int j = 0; j < 8; j++)
                    acc[i][j] = fmaf(a[i], b[j], acc[i][j]);
        }
        __syncthreads();
    }
    #pragma unroll
    for (int i = 0; i < 8; i++) {
        int gr = mb + ty * 8 + i;
        if (gr < M) {
            float* cp = C + (size_t)gr * D + nb + tx * 8;
            *(float4*)(cp + 0) = make_float4(acc[i][0], acc[i][1], acc[i][2], acc[i][3]);
            *(float4*)(cp + 4) = make_float4(acc[i][4], acc[i][5], acc[i][6], acc[i][7]);
        }
    }
}

// ---------------------------------------------------------------------------
// Final gather
// ---------------------------------------------------------------------------
__global__ void gather_out(const int* __restrict__ triples, const float* __restrict__ entn,
                           const float* __restrict__ reln, float4* __restrict__ out,
                           int B, int D) {
    int nv = D >> 2;
    int total = B * 3 * nv;
    int i = blockIdx.x * blockDim.x + threadIdx.x;
    int stride = gridDim.x * blockDim.x;
    for (; i < total; i += stride) {
        int d4 = i % nv;
        int bt = i / nv;
        int t = bt % 3;
        int b = bt / 3;
        int idx = triples[b * 3 + t];
        const float4* srcp = (t == 1) ? (const float4*)(reln + (size_t)idx * D)
                                      : (const float4*)(entn + (size_t)idx * D);
        out[i] = srcp[d4];
    }
}

// ---------------------------------------------------------------------------
// Launch
// ---------------------------------------------------------------------------
extern "C" void kernel_launch(void* const* d_in, const int* in_sizes, int n_in,
                              void* d_out, int out_size) {
    const int*   triples  = (const int*)d_in[0];
    const int*   nodelist = (const int*)d_in[1];
    const int*   edgelist = (const int*)d_in[2];
    const float* ent      = (const float*)d_in[3];
    const float* rel      = (const float*)d_in[4];
    const float* W1       = (const float*)d_in[5];
    const float* Wa       = (const float*)d_in[6];
    const float* g0       = (const float*)d_in[7];
    const float* WE       = (const float*)d_in[8];
    const float* WR       = (const float*)d_in[9];

    int B = in_sizes[0] / 3;
    int E = in_sizes[2];
    int D = in_sizes[6];
    int N = in_sizes[3] / D;
    int R = in_sizes[4] / D;

    float *e0, *Cbase, *Cedge, *Epre, *reln;
    int *cnt, *off, *cur, *eidx, *bsum;
    __half *e0h, *egh, *edh, *w1h, *w1l, *weth, *wetl;
    cudaGetSymbolAddress((void**)&e0,    g_e0);
    cudaGetSymbolAddress((void**)&Cbase, g_Cbase);
    cudaGetSymbolAddress((void**)&Cedge, g_Cedge);
    cudaGetSymbolAddress((void**)&Epre,  g_Epre);
    cudaGetSymbolAddress((void**)&reln,  g_reln);
    cudaGetSymbolAddress((void**)&cnt,   g_cnt);
    cudaGetSymbolAddress((void**)&off,   g_off);
    cudaGetSymbolAddress((void**)&cur,   g_cur);
    cudaGetSymbolAddress((void**)&eidx,  g_eidx);
    cudaGetSymbolAddress((void**)&bsum,  g_bsum);
    cudaGetSymbolAddress((void**)&e0h,   g_e0h);
    cudaGetSymbolAddress((void**)&egh,   g_egh);
    cudaGetSymbolAddress((void**)&edh,   g_edh);
    cudaGetSymbolAddress((void**)&w1h,   g_w1h);
    cudaGetSymbolAddress((void**)&w1l,   g_w1l);
    cudaGetSymbolAddress((void**)&weth,  g_weth);
    cudaGetSymbolAddress((void**)&wetl,  g_wetl);

    cudaFuncSetAttribute(gemm_mma_kernel,
                         cudaFuncAttributeMaxDynamicSharedMemorySize, MM_SMEM_BYTES);

    // ---- CSR build (src = node_list[0,:])
    zero_int<<<(N + 255) / 256, 256>>>(cnt, N);
    count_deg<<<(E + 255) / 256, 256>>>(nodelist, cnt, E);
    int nblk = (N + 1023) / 1024;
    scan1<<<nblk, 1024>>>(cnt, off, bsum, N);
    scan2<<<1, 1024>>>(bsum, nblk);
    scan3<<<(N + 255) / 256, 256>>>(off, cur, bsum, N, E);
    fill_eidx<<<(E + 255) / 256, 256>>>(nodelist, cur, eidx, E);

    // ---- operand prep
    normalize_split<<<(N + 7) / 8, 256>>>(ent, g0, e0, e0h, egh, N, D);
    split_weights<<<(D * D + 255) / 256, 256>>>(W1, WE, w1h, w1l, weth, wetl, D);
    split_edge<<<(E + 7) / 8, 256>>>(e0, rel, nodelist + E, edgelist, edh, E, D);

    // ---- GEMMs
    dim3 gN((N + MM_BM - 1) / MM_BM, D / MM_BN);
    dim3 gE2((E + MM_BM - 1) / MM_BM, D / MM_BN);
    gemm_mma_kernel<<<gN, 512, MM_SMEM_BYTES>>>(egh, w1h, w1l, Cbase, N, D);
    gemm_mma_kernel<<<gE2, 512, MM_SMEM_BYTES>>>(edh, w1h, w1l, Cedge, E, D);
    gemm_mma_kernel<<<gN, 512, MM_SMEM_BYTES>>>(e0h, weth, wetl, Epre, N, D);

    // ---- fused aggregation + epilogue (writes ent_new into e0 buffer)
    node_aggregate<<<(N + 7) / 8, 256>>>(e0, Cbase, Cedge, Epre, Wa, off, eidx, e0, N, D);

    // ---- rel_new + output gather
    dim3 gR((R + 127) / 128, D / 128);
    gemm128_plain<<<gR, 256>>>(rel, WR, reln, R, D);
    int total4 = B * 3 * (D >> 2);
    gather_out<<<(total4 + 255) / 256, 256>>>(triples, e0, reln, (float4*)d_out, B, D);
}

// round 7
// speedup vs baseline: 4.1161x; 1.3690x over previous
#include <cuda_runtime.h>
#include <cuda_fp16.h>
#include <math.h>
#include <stdint.h>

// ---------------------------------------------------------------------------
// UPGAT layer.  N=100000, R=500, D=512, E=150000, B=4096.
// GEMMs: pure fp16 single-pass on mma.sync (fp32 acc), 4-stage cp.async.
// Aggregation: pull-style CSR, fully fused epilogue.
// ---------------------------------------------------------------------------

#define MAX_N 100000
#define MAX_E 150000
#define MAX_R 500
#define MAX_D 512

__device__ float g_e0   [(size_t)MAX_N * MAX_D];
__device__ float g_Cbase[(size_t)MAX_N * MAX_D];
__device__ float g_Cedge[(size_t)MAX_E * MAX_D];
__device__ float g_Epre [(size_t)MAX_N * MAX_D];
__device__ float g_reln [(size_t)MAX_R * MAX_D];

// CSR scratch
__device__ int g_cnt [MAX_N];
__device__ int g_off [MAX_N + 1];
__device__ int g_cur [MAX_N];
__device__ int g_eidx[MAX_E];
__device__ int g_bsum[128];

// fp16 operands
__device__ __half g_e0h[(size_t)MAX_N * MAX_D];
__device__ __half g_egh[(size_t)MAX_N * MAX_D];
__device__ __half g_edh[(size_t)MAX_E * MAX_D];
__device__ __half g_w1h[MAX_D * MAX_D];
__device__ __half g_weth[MAX_D * MAX_D];

// ---------------------------------------------------------------------------
// helpers
// ---------------------------------------------------------------------------
__device__ __forceinline__ uint32_t smem_to_u32(const void* smem_ptr) {
    uint32_t addr;
    asm("{ .reg .u64 tmp; cvta.to.shared.u64 tmp, %1; cvt.u32.u64 %0, tmp; }"
        : "=r"(addr) : "l"(smem_ptr));
    return addr;
}
__device__ __forceinline__ void ldsm4(uint32_t addr, uint32_t& r0, uint32_t& r1,
                                      uint32_t& r2, uint32_t& r3) {
    asm volatile("ldmatrix.sync.aligned.m8n8.x4.shared.b16 {%0,%1,%2,%3}, [%4];"
                 : "=r"(r0), "=r"(r1), "=r"(r2), "=r"(r3) : "r"(addr));
}
__device__ __forceinline__ void mma_fp16(float* d, const uint32_t* a, const uint32_t* b) {
    asm volatile(
        "mma.sync.aligned.m16n8k16.row.col.f32.f16.f16.f32 "
        "{%0,%1,%2,%3}, {%4,%5,%6,%7}, {%8,%9}, {%0,%1,%2,%3};"
        : "+f"(d[0]), "+f"(d[1]), "+f"(d[2]), "+f"(d[3])
        : "r"(a[0]), "r"(a[1]), "r"(a[2]), "r"(a[3]), "r"(b[0]), "r"(b[1]));
}
__device__ __forceinline__ void cp16(uint32_t dst, const void* src, bool pred) {
    int sz = pred ? 16 : 0;
    asm volatile("cp.async.cg.shared.global [%0], [%1], 16, %2;"
                 :: "r"(dst), "l"(src), "r"(sz) : "memory");
}
__device__ __forceinline__ uint32_t pkh(__half a, __half b) {
    __half2 t = __halves2half2(a, b);
    return *reinterpret_cast<uint32_t*>(&t);
}
__device__ __forceinline__ uint2 h4(float4 v) {
    return make_uint2(pkh(__float2half_rn(v.x), __float2half_rn(v.y)),
                      pkh(__float2half_rn(v.z), __float2half_rn(v.w)));
}

// ---------------------------------------------------------------------------
__global__ void zero_int(int* __restrict__ p, int n) {
    int i = blockIdx.x * blockDim.x + threadIdx.x;
    if (i < n) p[i] = 0;
}

// ---------------------------------------------------------------------------
// e0 = l2norm(ent); emit fp16 of e0 and e0*g0.  Warp per row.
// ---------------------------------------------------------------------------
__global__ void normalize_split(const float* __restrict__ in, const float* __restrict__ g0,
                                float* __restrict__ e0,
                                __half* __restrict__ e0h, __half* __restrict__ egh,
                                int M, int D) {
    int warp = (blockIdx.x * blockDim.x + threadIdx.x) >> 5;
    int lane = threadIdx.x & 31;
    if (warp >= M) return;
    const float4* ip = (const float4*)(in + (size_t)warp * D);
    const float4* gp = (const float4*)g0;
    float4* op = (float4*)(e0 + (size_t)warp * D);
    int nv = D >> 2;
    float s = 0.f;
    for (int i = lane; i < nv; i += 32) {
        float4 v = ip[i];
        s += v.x * v.x + v.y * v.y + v.z * v.z + v.w * v.w;
    }
    #pragma unroll
    for (int o = 16; o; o >>= 1) s += __shfl_xor_sync(0xFFFFFFFFu, s, o);
    float inv = 1.f / fmaxf(sqrtf(s), 1e-12f);
    size_t rbase = (size_t)warp * D;
    for (int i = lane; i < nv; i += 32) {
        float4 v = ip[i];
        float4 n = make_float4(v.x * inv, v.y * inv, v.z * inv, v.w * inv);
        op[i] = n;
        *(uint2*)(e0h + rbase + i * 4) = h4(n);
        float4 g = gp[i];
        *(uint2*)(egh + rbase + i * 4) =
            h4(make_float4(n.x * g.x, n.y * g.y, n.z * g.z, n.w * g.w));
    }
}

// ---------------------------------------------------------------------------
// Edge operand: A[e,:] = fp16(e0[dst[e],:] * rel[edge[e],:]).  Warp per edge.
// ---------------------------------------------------------------------------
__global__ void split_edge(const float* __restrict__ e0, const float* __restrict__ rel,
                           const int* __restrict__ dsts, const int* __restrict__ edges,
                           __half* __restrict__ eh, int E, int D) {
    int warp = (blockIdx.x * blockDim.x + threadIdx.x) >> 5;
    int lane = threadIdx.x & 31;
    if (warp >= E) return;
    int dst = dsts[warp];
    int rl = edges[warp];
    const float4* ap = (const float4*)(e0 + (size_t)dst * D);
    const float4* gp = (const float4*)(rel + (size_t)rl * D);
    size_t rbase = (size_t)warp * D;
    int nv = D >> 2;
    for (int i = lane; i < nv; i += 32) {
        float4 a = ap[i], g = gp[i];
        *(uint2*)(eh + rbase + i * 4) =
            h4(make_float4(a.x * g.x, a.y * g.y, a.z * g.z, a.w * g.w));
    }
}

// ---------------------------------------------------------------------------
// Weight conversion (single fp16): W1 as-is ([N,K]); WE transposed.
// ---------------------------------------------------------------------------
__global__ void split_weights(const float* __restrict__ W1, const float* __restrict__ WE,
                              __half* __restrict__ w1h, __half* __restrict__ weth,
                              int D) {
    int i = blockIdx.x * blockDim.x + threadIdx.x;
    int tot = D * D;
    if (i >= tot) return;
    w1h[i] = __float2half_rn(W1[i]);
    int k = i / D, j = i % D;
    weth[(size_t)j * D + k] = __float2half_rn(WE[i]);
}

// ---------------------------------------------------------------------------
// CSR build
// ---------------------------------------------------------------------------
__global__ void count_deg(const int* __restrict__ srcs, int* __restrict__ cnt, int E) {
    int e = blockIdx.x * blockDim.x + threadIdx.x;
    if (e < E) atomicAdd(&cnt[srcs[e]], 1);
}
__global__ void scan1(const int* __restrict__ cnt, int* __restrict__ off,
                      int* __restrict__ bsum, int N) {
    __shared__ int sm[1024];
    int tid = threadIdx.x;
    int i = blockIdx.x * 1024 + tid;
    int v = (i < N) ? cnt[i] : 0;
    sm[tid] = v;
    __syncthreads();
    #pragma unroll
    for (int d = 1; d < 1024; d <<= 1) {
        int t = (tid >= d) ? sm[tid - d] : 0;
        __syncthreads();
        sm[tid] += t;
        __syncthreads();
    }
    if (i < N) off[i] = sm[tid] - v;
    if (tid == 1023) bsum[blockIdx.x] = sm[1023];
}
__global__ void scan2(int* __restrict__ bsum, int nb) {
    __shared__ int sm[1024];
    int tid = threadIdx.x;
    int v = (tid < nb) ? bsum[tid] : 0;
    sm[tid] = v;
    __syncthreads();
    #pragma unroll
    for (int d = 1; d < 1024; d <<= 1) {
        int t = (tid >= d) ? sm[tid - d] : 0;
        __syncthreads();
        sm[tid] += t;
        __syncthreads();
    }
    if (tid < nb) bsum[tid] = sm[tid] - v;
}
__global__ void scan3(int* __restrict__ off, int* __restrict__ cur,
                      const int* __restrict__ bsum, int N, int E) {
    int i = blockIdx.x * blockDim.x + threadIdx.x;
    if (i < N) {
        int o = off[i] + bsum[i >> 10];
        off[i] = o;
        cur[i] = o;
    }
    if (i == 0) off[N] = E;
}
__global__ void fill_eidx(const int* __restrict__ srcs, int* __restrict__ cur,
                          int* __restrict__ eidx, int E) {
    int e = blockIdx.x * blockDim.x + threadIdx.x;
    if (e < E) {
        int pos = atomicAdd(&cur[srcs[e]], 1);
        eidx[pos] = e;
    }
}

// ---------------------------------------------------------------------------
// Fused node aggregation (warp per node): attention + softmax-agg + ELU +
// residual + l2norm.  See R6 notes.
// ---------------------------------------------------------------------------
__global__ void node_aggregate(const float* __restrict__ e0, const float* __restrict__ Cb,
                               const float* __restrict__ Ce, const float* __restrict__ Epre,
                               const float* __restrict__ Wa,
                               const int* __restrict__ off, const int* __restrict__ eidx,
                               float* __restrict__ entnew, int N, int D) {
    __shared__ float waS[512];
    for (int i = threadIdx.x; i < D; i += blockDim.x) waS[i] = Wa[i];
    __syncthreads();

    int warp = (blockIdx.x * blockDim.x + threadIdx.x) >> 5;
    int lane = threadIdx.x & 31;
    if (warp >= N) return;
    int o0 = off[warp], o1 = off[warp + 1];
    int deg = o1 - o0;

    const float4* ep = (const float4*)(e0 + (size_t)warp * D);
    const float4* cbp = (const float4*)(Cb + (size_t)warp * D);
    const float4* wp = (const float4*)waS;

    float4 er[4], wr[4], acc[4];
    float sb = 0.f;
    #pragma unroll
    for (int i = 0; i < 4; i++) {
        int ii = lane + i * 32;
        er[i] = ep[ii];
        wr[i] = wp[ii];
        float4 c = cbp[ii];
        acc[i] = c;
        sb += er[i].x * tanhf(c.x) * wr[i].x + er[i].y * tanhf(c.y) * wr[i].y +
              er[i].z * tanhf(c.z) * wr[i].z + er[i].w * tanhf(c.w) * wr[i].w;
    }
    #pragma unroll
    for (int o = 16; o; o >>= 1) sb += __shfl_xor_sync(0xFFFFFFFFu, sb, o);
    float lb = sb > 0.f ? sb : 0.2f * sb;
    float ab = expf(-lb);
    float coef = (deg > 0) ? ab : 0.f;
    float den = coef;
    #pragma unroll
    for (int i = 0; i < 4; i++) {
        acc[i].x *= coef; acc[i].y *= coef; acc[i].z *= coef; acc[i].w *= coef;
    }

    for (int j = o0; j < o1; j++) {
        int e = eidx[j];
        const float4* cp = (const float4*)(Ce + (size_t)e * D);
        float4 cv[4];
        float s = 0.f;
        #pragma unroll
        for (int i = 0; i < 4; i++) {
            int ii = lane + i * 32;
            float4 c = cp[ii];
            cv[i] = c;
            s += er[i].x * tanhf(c.x) * wr[i].x + er[i].y * tanhf(c.y) * wr[i].y +
                 er[i].z * tanhf(c.z) * wr[i].z + er[i].w * tanhf(c.w) * wr[i].w;
        }
        #pragma unroll
        for (int o = 16; o; o >>= 1) s += __shfl_xor_sync(0xFFFFFFFFu, s, o);
        float l = s > 0.f ? s : 0.2f * s;
        float aexp = expf(-l);
        den += aexp;
        #pragma unroll
        for (int i = 0; i < 4; i++) {
            acc[i].x = fmaf(aexp, cv[i].x, acc[i].x);
            acc[i].y = fmaf(aexp, cv[i].y, acc[i].y);
            acc[i].z = fmaf(aexp, cv[i].z, acc[i].z);
            acc[i].w = fmaf(aexp, cv[i].w, acc[i].w);
        }
    }

    if (den == 0.f) den = 1e-12f;
    float invden = 1.f / den;
    const float4* epp = (const float4*)(Epre + (size_t)warp * D);
    float4* op = (float4*)(entnew + (size_t)warp * D);
    float nrm = 0.f;
    float4 tv[4];
    #pragma unroll
    for (int i = 0; i < 4; i++) {
        int ii = lane + i * 32;
        float4 ep4 = epp[ii];
        float4 t;
        float x = acc[i].x * invden; t.x = ep4.x + (x > 0.f ? x : expm1f(x));
        x = acc[i].y * invden;       t.y = ep4.y + (x > 0.f ? x : expm1f(x));
        x = acc[i].z * invden;       t.z = ep4.z + (x > 0.f ? x : expm1f(x));
        x = acc[i].w * invden;       t.w = ep4.w + (x > 0.f ? x : expm1f(x));
        tv[i] = t;
        nrm += t.x * t.x + t.y * t.y + t.z * t.z + t.w * t.w;
    }
    #pragma unroll
    for (int o = 16; o; o >>= 1) nrm += __shfl_xor_sync(0xFFFFFFFFu, nrm, o);
    float inv = 1.f / fmaxf(sqrtf(nrm), 1e-12f);
    #pragma unroll
    for (int i = 0; i < 4; i++) {
        int ii = lane + i * 32;
        float4 t = tv[i];
        op[ii] = make_float4(t.x * inv, t.y * inv, t.z * inv, t.w * inv);
    }
}

// ---------------------------------------------------------------------------
// mma.sync fp16 GEMM (single pass): C[M,D] = A @ W^T,  W stored [N,K].
// CTA 128x256, BK=32, 512 threads, warp tile 32x64, 4-stage cp.async.
// ---------------------------------------------------------------------------
#define MM_BM 128
#define MM_BN 256
#define MM_BK 32
#define MM_LD 40
#define MM_STAGES 4
static constexpr int MM_AH = 0;
static constexpr int MM_BH = 128 * MM_LD;                 // 5120 halves
static constexpr int MM_STAGE_H = 15360;                  // halves per stage
static constexpr int MM_STAGE_BYTES = MM_STAGE_H * 2;     // 30720
static constexpr int MM_SMEM_BYTES = MM_STAGES * MM_STAGE_BYTES; // 122880

__global__ void __launch_bounds__(512, 1)
gemm_mma_kernel(const __half* __restrict__ A, const __half* __restrict__ Bh,
                float* __restrict__ C, int M, int D) {
    extern __shared__ __half sh[];
    uint32_t sbase = smem_to_u32(sh);
    int tid = threadIdx.x;
    int lane = tid & 31;
    int warp = tid >> 5;
    int mb = blockIdx.x * MM_BM;
    int nb = blockIdx.y * MM_BN;
    int wm = (warp >> 2) * 32;
    int wn = (warp & 3) * 64;
    const int nch = D / MM_BK;   // 16

    float acc[2][8][4];
    #pragma unroll
    for (int i = 0; i < 2; i++)
        #pragma unroll
        for (int j = 0; j < 8; j++)
            #pragma unroll
            for (int q = 0; q < 4; q++) acc[i][j][q] = 0.f;

    int arow = tid >> 2;
    int achk = (tid & 3) * 8;
    int gma = mb + arow;
    bool apred = gma < M;
    size_t abase = (size_t)(apred ? gma : 0) * D + achk;

    auto stage_load = [&](int ch) {
        if (ch < nch) {
            int kb = ch * MM_BK;
            uint32_t st = sbase + (ch % MM_STAGES) * MM_STAGE_BYTES;
            cp16(st + (MM_AH + arow * MM_LD + achk) * 2, A + abase + kb, apred);
            #pragma unroll
            for (int i = 0; i < 2; i++) {
                int idx = tid + i * 512;
                int row = idx >> 2;
                int chk = (idx & 3) * 8;
                size_t go = (size_t)(nb + row) * D + kb + chk;
                cp16(st + (MM_BH + row * MM_LD + chk) * 2, Bh + go, true);
            }
        }
        asm volatile("cp.async.commit_group;" ::: "memory");
    };

    stage_load(0);
    stage_load(1);
    stage_load(2);

    int a_r = (lane & 15);
    int a_c = (lane >> 4) << 3;
    int b_r = (lane & 7) + ((lane & 16) >> 1);
    int b_c = (lane & 8);

    for (int ch = 0; ch < nch; ch++) {
        asm volatile("cp.async.wait_group 2;" ::: "memory");
        __syncthreads();
        stage_load(ch + 3);

        uint32_t stb = sbase + (ch % MM_STAGES) * MM_STAGE_BYTES;
        #pragma unroll
        for (int s16 = 0; s16 < 2; s16++) {
            int k0 = s16 * 16;
            uint32_t ah[2][4], bh[8][2];
            #pragma unroll
            for (int mi = 0; mi < 2; mi++) {
                uint32_t addr = stb + (MM_AH + (wm + mi * 16 + a_r) * MM_LD + k0 + a_c) * 2;
                ldsm4(addr, ah[mi][0], ah[mi][1], ah[mi][2], ah[mi][3]);
            }
            #pragma unroll
            for (int nj = 0; nj < 4; nj++) {
                uint32_t addr = stb + (MM_BH + (wn + nj * 16 + b_r) * MM_LD + k0 + b_c) * 2;
                ldsm4(addr, bh[2 * nj][0], bh[2 * nj][1], bh[2 * nj + 1][0], bh[2 * nj + 1][1]);
            }
            #pragma unroll
            for (int mi = 0; mi < 2; mi++)
                #pragma unroll
                for (int nj = 0; nj < 8; nj++) mma_fp16(acc[mi][nj], ah[mi], bh[nj]);
        }
        __syncthreads();
    }

    #pragma unroll
    for (int mi = 0; mi < 2; mi++) {
        int gm0 = mb + wm + mi * 16 + (lane >> 2);
        int gm1 = gm0 + 8;
        #pragma unroll
        for (int nj = 0; nj < 8; nj++) {
            int gn = nb + wn + nj * 8 + (lane & 3) * 2;
            if (gm0 < M)
                *(float2*)(C + (size_t)gm0 * D + gn) = make_float2(acc[mi][nj][0], acc[mi][nj][1]);
            if (gm1 < M)
                *(float2*)(C + (size_t)gm1 * D + gn) = make_float2(acc[mi][nj][2], acc[mi][nj][3]);
        }
    }
}

// ---------------------------------------------------------------------------
// fp32 tiled SGEMM (tiny rel_new GEMM, R=500)
// ---------------------------------------------------------------------------
__global__ void gemm128_plain(const float* __restrict__ A0, const float* __restrict__ W,
                              float* __restrict__ C, int M, int D) {
    constexpr int BM = 128, BN = 128, BK = 16;
    __shared__ float As[BK][BM];
    __shared__ float Bs[BK][BN];
    int tid = threadIdx.x;
    int mb = blockIdx.x * BM;
    int nb = blockIdx.y * BN;
    int tx = tid & 15, ty = tid >> 4;
    float acc[8][8];
    #pragma unroll
    for (int i = 0; i < 8; i++)
        #pragma unroll
        for (int j = 0; j < 8; j++) acc[i][j] = 0.f;
    for (int kb = 0; kb < D; kb += BK) {
        #pragma unroll
        for (int i = 0; i < 2; i++) {
            int q = tid + i * 256;
            int row = q >> 2;
            int kc = (q & 3) << 2;
            int gr = mb + row;
            float4 v = make_float4(0.f, 0.f, 0.f, 0.f);
            if (gr < M) v = *(const float4*)(A0 + (size_t)gr * D + kb + kc);
            As[kc + 0][row] = v.x; As[kc + 1][row] = v.y;
            As[kc + 2][row] = v.z; As[kc + 3][row] = v.w;
        }
        #pragma unroll
        for (int i = 0; i < 2; i++) {
            int q = tid + i * 256;
            int kr = q >> 5;
            int jc = (q & 31) << 2;
            *(float4*)&Bs[kr][jc] = *(const float4*)(W + (size_t)(kb + kr) * D + nb + jc);
        }
        __syncthreads();
        #pragma unroll
        for (int k = 0; k < BK; k++) {
            float a[8], b[8];
            *(float4*)&a[0] = *(const float4*)&As[k][ty * 8];
            *(float4*)&a[4] = *(const float4*)&As[k][ty * 8 + 4];
            *(float4*)&b[0] = *(const float4*)&Bs[k][tx * 8];
            *(float4*)&b[4] = *(const float4*)&Bs[k][tx * 8 + 4];
            #pragma unroll
            for (int i = 0; i < 8; i++)
                #pragma unroll
                for (int j = 0; j < 8; j++)
                    acc[i][j] = fmaf(a[i], b[j], acc[i][j]);
        }
        __syncthreads();
    }
    #pragma unroll
    for (int i = 0; i < 8; i++) {
        int gr = mb + ty * 8 + i;
        if (gr < M) {
            float* cp = C + (size_t)gr * D + nb + tx * 8;
            *(float4*)(cp + 0) = make_float4(acc[i][0], acc[i][1], acc[i][2], acc[i][3]);
            *(float4*)(cp + 4) = make_float4(acc[i][4], acc[i][5], acc[i][6], acc[i][7]);
        }
    }
}

// ---------------------------------------------------------------------------
// Final gather
// ---------------------------------------------------------------------------
__global__ void gather_out(const int* __restrict__ triples, const float* __restrict__ entn,
                           const float* __restrict__ reln, float4* __restrict__ out,
                           int B, int D) {
    int nv = D >> 2;
    int total = B * 3 * nv;
    int i = blockIdx.x * blockDim.x + threadIdx.x;
    int stride = gridDim.x * blockDim.x;
    for (; i < total; i += stride) {
        int d4 = i % nv;
        int bt = i / nv;
        int t = bt % 3;
        int b = bt / 3;
        int idx = triples[b * 3 + t];
        const float4* srcp = (t == 1) ? (const float4*)(reln + (size_t)idx * D)
                                      : (const float4*)(entn + (size_t)idx * D);
        out[i] = srcp[d4];
    }
}

// ---------------------------------------------------------------------------
// Launch
// ---------------------------------------------------------------------------
extern "C" void kernel_launch(void* const* d_in, const int* in_sizes, int n_in,
                              void* d_out, int out_size) {
    const int*   triples  = (const int*)d_in[0];
    const int*   nodelist = (const int*)d_in[1];
    const int*   edgelist = (const int*)d_in[2];
    const float* ent      = (const float*)d_in[3];
    const float* rel      = (const float*)d_in[4];
    const float* W1       = (const float*)d_in[5];
    const float* Wa       = (const float*)d_in[6];
    const float* g0       = (const float*)d_in[7];
    const float* WE       = (const float*)d_in[8];
    const float* WR       = (const float*)d_in[9];

    int B = in_sizes[0] / 3;
    int E = in_sizes[2];
    int D = in_sizes[6];
    int N = in_sizes[3] / D;
    int R = in_sizes[4] / D;

    float *e0, *Cbase, *Cedge, *Epre, *reln;
    int *cnt, *off, *cur, *eidx, *bsum;
    __half *e0h, *egh, *edh, *w1h, *weth;
    cudaGetSymbolAddress((void**)&e0,    g_e0);
    cudaGetSymbolAddress((void**)&Cbase, g_Cbase);
    cudaGetSymbolAddress((void**)&Cedge, g_Cedge);
    cudaGetSymbolAddress((void**)&Epre,  g_Epre);
    cudaGetSymbolAddress((void**)&reln,  g_reln);
    cudaGetSymbolAddress((void**)&cnt,   g_cnt);
    cudaGetSymbolAddress((void**)&off,   g_off);
    cudaGetSymbolAddress((void**)&cur,   g_cur);
    cudaGetSymbolAddress((void**)&eidx,  g_eidx);
    cudaGetSymbolAddress((void**)&bsum,  g_bsum);
    cudaGetSymbolAddress((void**)&e0h,   g_e0h);
    cudaGetSymbolAddress((void**)&egh,   g_egh);
    cudaGetSymbolAddress((void**)&edh,   g_edh);
    cudaGetSymbolAddress((void**)&w1h,   g_w1h);
    cudaGetSymbolAddress((void**)&weth,  g_weth);

    cudaFuncSetAttribute(gemm_mma_kernel,
                         cudaFuncAttributeMaxDynamicSharedMemorySize, MM_SMEM_BYTES);

    // ---- CSR build (src = node_list[0,:])
    zero_int<<<(N + 255) / 256, 256>>>(cnt, N);
    count_deg<<<(E + 255) / 256, 256>>>(nodelist, cnt, E);
    int nblk = (N + 1023) / 1024;
    scan1<<<nblk, 1024>>>(cnt, off, bsum, N);
    scan2<<<1, 1024>>>(bsum, nblk);
    scan3<<<(N + 255) / 256, 256>>>(off, cur, bsum, N, E);
    fill_eidx<<<(E + 255) / 256, 256>>>(nodelist, cur, eidx, E);

    // ---- operand prep
    normalize_split<<<(N + 7) / 8, 256>>>(ent, g0, e0, e0h, egh, N, D);
    split_weights<<<(D * D + 255) / 256, 256>>>(W1, WE, w1h, weth, D);
    split_edge<<<(E + 7) / 8, 256>>>(e0, rel, nodelist + E, edgelist, edh, E, D);

    // ---- GEMMs (single-pass fp16)
    dim3 gN((N + MM_BM - 1) / MM_BM, D / MM_BN);
    dim3 gE2((E + MM_BM - 1) / MM_BM, D / MM_BN);
    gemm_mma_kernel<<<gN, 512, MM_SMEM_BYTES>>>(egh, w1h, Cbase, N, D);
    gemm_mma_kernel<<<gE2, 512, MM_SMEM_BYTES>>>(edh, w1h, Cedge, E, D);
    gemm_mma_kernel<<<gN, 512, MM_SMEM_BYTES>>>(e0h, weth, Epre, N, D);

    // ---- fused aggregation + epilogue (writes ent_new into e0 buffer)
    node_aggregate<<<(N + 7) / 8, 256>>>(e0, Cbase, Cedge, Epre, Wa, off, eidx, e0, N, D);

    // ---- rel_new + output gather
    dim3 gR((R + 127) / 128, D / 128);
    gemm128_plain<<<gR, 256>>>(rel, WR, reln, R, D);
    int total4 = B * 3 * (D >> 2);
    gather_out<<<(total4 + 255) / 256, 256>>>(triples, e0, reln, (float4*)d_out, B, D);
}

// round 8
// speedup vs baseline: 4.6495x; 1.1296x over previous
#include <cuda_runtime.h>
#include <cuda_fp16.h>
#include <math.h>
#include <stdint.h>

// ---------------------------------------------------------------------------
// UPGAT layer.  N=100000, R=500, D=512, E=150000, B=4096.
// GEMMs: pure fp16 single-pass on mma.sync (fp32 acc), 4-stage cp.async.
// Aggregation: pull-style CSR, fused epilogue, tanh.approx, fp16 attention reads.
// ---------------------------------------------------------------------------

#define MAX_N 100000
#define MAX_E 150000
#define MAX_R 500
#define MAX_D 512

__device__ float g_entn [(size_t)MAX_N * MAX_D];   // ent_new output
__device__ float g_Cbase[(size_t)MAX_N * MAX_D];
__device__ float g_Cedge[(size_t)MAX_E * MAX_D];
__device__ float g_Epre [(size_t)MAX_N * MAX_D];
__device__ float g_reln [(size_t)MAX_R * MAX_D];

// CSR scratch
__device__ int g_cnt [MAX_N];
__device__ int g_off [MAX_N + 1];
__device__ int g_cur [MAX_N];
__device__ int g_eidx[MAX_E];
__device__ int g_bsum[128];

// fp16 operands
__device__ __half g_e0h[(size_t)MAX_N * MAX_D];
__device__ __half g_egh[(size_t)MAX_N * MAX_D];
__device__ __half g_edh[(size_t)MAX_E * MAX_D];
__device__ __half g_relh[(size_t)MAX_R * MAX_D];
__device__ __half g_w1h[MAX_D * MAX_D];
__device__ __half g_weth[MAX_D * MAX_D];

// ---------------------------------------------------------------------------
// helpers
// ---------------------------------------------------------------------------
__device__ __forceinline__ uint32_t smem_to_u32(const void* smem_ptr) {
    uint32_t addr;
    asm("{ .reg .u64 tmp; cvta.to.shared.u64 tmp, %1; cvt.u32.u64 %0, tmp; }"
        : "=r"(addr) : "l"(smem_ptr));
    return addr;
}
__device__ __forceinline__ void ldsm4(uint32_t addr, uint32_t& r0, uint32_t& r1,
                                      uint32_t& r2, uint32_t& r3) {
    asm volatile("ldmatrix.sync.aligned.m8n8.x4.shared.b16 {%0,%1,%2,%3}, [%4];"
                 : "=r"(r0), "=r"(r1), "=r"(r2), "=r"(r3) : "r"(addr));
}
__device__ __forceinline__ void mma_fp16(float* d, const uint32_t* a, const uint32_t* b) {
    asm volatile(
        "mma.sync.aligned.m16n8k16.row.col.f32.f16.f16.f32 "
        "{%0,%1,%2,%3}, {%4,%5,%6,%7}, {%8,%9}, {%0,%1,%2,%3};"
        : "+f"(d[0]), "+f"(d[1]), "+f"(d[2]), "+f"(d[3])
        : "r"(a[0]), "r"(a[1]), "r"(a[2]), "r"(a[3]), "r"(b[0]), "r"(b[1]));
}
__device__ __forceinline__ void cp16(uint32_t dst, const void* src, bool pred) {
    int sz = pred ? 16 : 0;
    asm volatile("cp.async.cg.shared.global [%0], [%1], 16, %2;"
                 :: "r"(dst), "l"(src), "r"(sz) : "memory");
}
__device__ __forceinline__ uint32_t pkh(__half a, __half b) {
    __half2 t = __halves2half2(a, b);
    return *reinterpret_cast<uint32_t*>(&t);
}
__device__ __forceinline__ uint2 h4(float4 v) {
    return make_uint2(pkh(__float2half_rn(v.x), __float2half_rn(v.y)),
                      pkh(__float2half_rn(v.z), __float2half_rn(v.w)));
}
__device__ __forceinline__ float4 f4ofh(uint2 u) {
    __half2* h2 = (__half2*)&u;
    float2 a = __half22float2(h2[0]);
    float2 b = __half22float2(h2[1]);
    return make_float4(a.x, a.y, b.x, b.y);
}
__device__ __forceinline__ float tanha(float x) {
    float y;
    asm("tanh.approx.f32 %0, %1;" : "=f"(y) : "f"(x));
    return y;
}

// ---------------------------------------------------------------------------
__global__ void zero_int(int* __restrict__ p, int n) {
    int i = blockIdx.x * blockDim.x + threadIdx.x;
    if (i < n) p[i] = 0;
}

// ---------------------------------------------------------------------------
// e0h = fp16(l2norm(ent)); egh = fp16(l2norm(ent)*g0).  Warp per row.
// (fp32 e0 is never materialized — all consumers use e0h.)
// ---------------------------------------------------------------------------
__global__ void normalize_split(const float* __restrict__ in, const float* __restrict__ g0,
                                __half* __restrict__ e0h, __half* __restrict__ egh,
                                int M, int D) {
    int warp = (blockIdx.x * blockDim.x + threadIdx.x) >> 5;
    int lane = threadIdx.x & 31;
    if (warp >= M) return;
    const float4* ip = (const float4*)(in + (size_t)warp * D);
    const float4* gp = (const float4*)g0;
    int nv = D >> 2;
    float s = 0.f;
    for (int i = lane; i < nv; i += 32) {
        float4 v = ip[i];
        s += v.x * v.x + v.y * v.y + v.z * v.z + v.w * v.w;
    }
    #pragma unroll
    for (int o = 16; o; o >>= 1) s += __shfl_xor_sync(0xFFFFFFFFu, s, o);
    float inv = 1.f / fmaxf(sqrtf(s), 1e-12f);
    size_t rbase = (size_t)warp * D;
    for (int i = lane; i < nv; i += 32) {
        float4 v = ip[i];
        float4 n = make_float4(v.x * inv, v.y * inv, v.z * inv, v.w * inv);
        *(uint2*)(e0h + rbase + i * 4) = h4(n);
        float4 g = gp[i];
        *(uint2*)(egh + rbase + i * 4) =
            h4(make_float4(n.x * g.x, n.y * g.y, n.z * g.z, n.w * g.w));
    }
}

// ---------------------------------------------------------------------------
// Edge operand (all fp16): A[e,:] = e0h[dst[e],:] * relh[edge[e],:].
// ---------------------------------------------------------------------------
__global__ void split_edge(const __half* __restrict__ e0h, const __half* __restrict__ relh,
                           const int* __restrict__ dsts, const int* __restrict__ edges,
                           __half* __restrict__ eh, int E, int D) {
    int warp = (blockIdx.x * blockDim.x + threadIdx.x) >> 5;
    int lane = threadIdx.x & 31;
    if (warp >= E) return;
    int dst = dsts[warp];
    int rl = edges[warp];
    const uint2* ap = (const uint2*)(e0h + (size_t)dst * D);
    const uint2* gp = (const uint2*)(relh + (size_t)rl * D);
    uint2* op = (uint2*)(eh + (size_t)warp * D);
    int nv = D >> 2;
    for (int i = lane; i < nv; i += 32) {
        uint2 a = ap[i], g = gp[i];
        __half2* ah = (__half2*)&a;
        __half2* gh = (__half2*)&g;
        uint2 r;
        __half2* rh = (__half2*)&r;
        rh[0] = __hmul2(ah[0], gh[0]);
        rh[1] = __hmul2(ah[1], gh[1]);
        op[i] = r;
    }
}

// ---------------------------------------------------------------------------
// Weight + relation fp16 conversion: W1 as-is ([N,K]); WE transposed; rel.
// ---------------------------------------------------------------------------
__global__ void split_weights(const float* __restrict__ W1, const float* __restrict__ WE,
                              const float* __restrict__ rel,
                              __half* __restrict__ w1h, __half* __restrict__ weth,
                              __half* __restrict__ relh, int D, int RD) {
    int i = blockIdx.x * blockDim.x + threadIdx.x;
    int tot = D * D;
    if (i < tot) {
        w1h[i] = __float2half_rn(W1[i]);
        int k = i / D, j = i % D;
        weth[(size_t)j * D + k] = __float2half_rn(WE[i]);
    }
    if (i < RD) relh[i] = __float2half_rn(rel[i]);
}

// ---------------------------------------------------------------------------
// CSR build
// ---------------------------------------------------------------------------
__global__ void count_deg(const int* __restrict__ srcs, int* __restrict__ cnt, int E) {
    int e = blockIdx.x * blockDim.x + threadIdx.x;
    if (e < E) atomicAdd(&cnt[srcs[e]], 1);
}
__global__ void scan1(const int* __restrict__ cnt, int* __restrict__ off,
                      int* __restrict__ bsum, int N) {
    __shared__ int sm[1024];
    int tid = threadIdx.x;
    int i = blockIdx.x * 1024 + tid;
    int v = (i < N) ? cnt[i] : 0;
    sm[tid] = v;
    __syncthreads();
    #pragma unroll
    for (int d = 1; d < 1024; d <<= 1) {
        int t = (tid >= d) ? sm[tid - d] : 0;
        __syncthreads();
        sm[tid] += t;
        __syncthreads();
    }
    if (i < N) off[i] = sm[tid] - v;
    if (tid == 1023) bsum[blockIdx.x] = sm[1023];
}
__global__ void scan2(int* __restrict__ bsum, int nb) {
    __shared__ int sm[1024];
    int tid = threadIdx.x;
    int v = (tid < nb) ? bsum[tid] : 0;
    sm[tid] = v;
    __syncthreads();
    #pragma unroll
    for (int d = 1; d < 1024; d <<= 1) {
        int t = (tid >= d) ? sm[tid - d] : 0;
        __syncthreads();
        sm[tid] += t;
        __syncthreads();
    }
    if (tid < nb) bsum[tid] = sm[tid] - v;
}
__global__ void scan3(int* __restrict__ off, int* __restrict__ cur,
                      const int* __restrict__ bsum, int N, int E) {
    int i = blockIdx.x * blockDim.x + threadIdx.x;
    if (i < N) {
        int o = off[i] + bsum[i >> 10];
        off[i] = o;
        cur[i] = o;
    }
    if (i == 0) off[N] = E;
}
__global__ void fill_eidx(const int* __restrict__ srcs, int* __restrict__ cur,
                          int* __restrict__ eidx, int E) {
    int e = blockIdx.x * blockDim.x + threadIdx.x;
    if (e < E) {
        int pos = atomicAdd(&cur[srcs[e]], 1);
        eidx[pos] = e;
    }
}

// ---------------------------------------------------------------------------
// Fused node aggregation (warp per node).  er from fp16 e0h; tanh.approx.
// ---------------------------------------------------------------------------
__global__ void node_aggregate(const __half* __restrict__ e0h, const float* __restrict__ Cb,
                               const float* __restrict__ Ce, const float* __restrict__ Epre,
                               const float* __restrict__ Wa,
                               const int* __restrict__ off, const int* __restrict__ eidx,
                               float* __restrict__ entnew, int N, int D) {
    __shared__ float waS[512];
    for (int i = threadIdx.x; i < D; i += blockDim.x) waS[i] = Wa[i];
    __syncthreads();

    int warp = (blockIdx.x * blockDim.x + threadIdx.x) >> 5;
    int lane = threadIdx.x & 31;
    if (warp >= N) return;
    int o0 = off[warp], o1 = off[warp + 1];
    int deg = o1 - o0;

    const uint2* ep = (const uint2*)(e0h + (size_t)warp * D);
    const float4* cbp = (const float4*)(Cb + (size_t)warp * D);
    const float4* wp = (const float4*)waS;

    // ew[i] = e0 * Wa fused coefficient (attention dot becomes sum ew*tanh(c))
    float4 ew[4], acc[4];
    float sb = 0.f;
    #pragma unroll
    for (int i = 0; i < 4; i++) {
        int ii = lane + i * 32;
        float4 e = f4ofh(ep[ii]);
        float4 w = wp[ii];
        ew[i] = make_float4(e.x * w.x, e.y * w.y, e.z * w.z, e.w * w.w);
        float4 c = cbp[ii];
        acc[i] = c;
        sb += ew[i].x * tanha(c.x) + ew[i].y * tanha(c.y) +
              ew[i].z * tanha(c.z) + ew[i].w * tanha(c.w);
    }
    #pragma unroll
    for (int o = 16; o; o >>= 1) sb += __shfl_xor_sync(0xFFFFFFFFu, sb, o);
    float lb = sb > 0.f ? sb : 0.2f * sb;
    float ab = expf(-lb);
    float coef = (deg > 0) ? ab : 0.f;
    float den = coef;
    #pragma unroll
    for (int i = 0; i < 4; i++) {
        acc[i].x *= coef; acc[i].y *= coef; acc[i].z *= coef; acc[i].w *= coef;
    }

    for (int j = o0; j < o1; j++) {
        int e = eidx[j];
        const float4* cp = (const float4*)(Ce + (size_t)e * D);
        float4 cv[4];
        float s = 0.f;
        #pragma unroll
        for (int i = 0; i < 4; i++) {
            int ii = lane + i * 32;
            float4 c = cp[ii];
            cv[i] = c;
            s += ew[i].x * tanha(c.x) + ew[i].y * tanha(c.y) +
                 ew[i].z * tanha(c.z) + ew[i].w * tanha(c.w);
        }
        #pragma unroll
        for (int o = 16; o; o >>= 1) s += __shfl_xor_sync(0xFFFFFFFFu, s, o);
        float l = s > 0.f ? s : 0.2f * s;
        float aexp = expf(-l);
        den += aexp;
        #pragma unroll
        for (int i = 0; i < 4; i++) {
            acc[i].x = fmaf(aexp, cv[i].x, acc[i].x);
            acc[i].y = fmaf(aexp, cv[i].y, acc[i].y);
            acc[i].z = fmaf(aexp, cv[i].z, acc[i].z);
            acc[i].w = fmaf(aexp, cv[i].w, acc[i].w);
        }
    }

    if (den == 0.f) den = 1e-12f;
    float invden = 1.f / den;
    const float4* epp = (const float4*)(Epre + (size_t)warp * D);
    float4* op = (float4*)(entnew + (size_t)warp * D);
    float nrm = 0.f;
    float4 tv[4];
    #pragma unroll
    for (int i = 0; i < 4; i++) {
        int ii = lane + i * 32;
        float4 ep4 = epp[ii];
        float4 t;
        float x = acc[i].x * invden; t.x = ep4.x + (x > 0.f ? x : expm1f(x));
        x = acc[i].y * invden;       t.y = ep4.y + (x > 0.f ? x : expm1f(x));
        x = acc[i].z * invden;       t.z = ep4.z + (x > 0.f ? x : expm1f(x));
        x = acc[i].w * invden;       t.w = ep4.w + (x > 0.f ? x : expm1f(x));
        tv[i] = t;
        nrm += t.x * t.x + t.y * t.y + t.z * t.z + t.w * t.w;
    }
    #pragma unroll
    for (int o = 16; o; o >>= 1) nrm += __shfl_xor_sync(0xFFFFFFFFu, nrm, o);
    float inv = 1.f / fmaxf(sqrtf(nrm), 1e-12f);
    #pragma unroll
    for (int i = 0; i < 4; i++) {
        int ii = lane + i * 32;
        float4 t = tv[i];
        op[ii] = make_float4(t.x * inv, t.y * inv, t.z * inv, t.w * inv);
    }
}

// ---------------------------------------------------------------------------
// mma.sync fp16 GEMM (single pass): C[M,D] = A @ W^T,  W stored [N,K].
// CTA 128x256, BK=32, 512 threads, warp tile 32x64, 4-stage cp.async.
// ---------------------------------------------------------------------------
#define MM_BM 128
#define MM_BN 256
#define MM_BK 32
#define MM_LD 40
#define MM_STAGES 4
static constexpr int MM_AH = 0;
static constexpr int MM_BH = 128 * MM_LD;
static constexpr int MM_STAGE_H = 15360;
static constexpr int MM_STAGE_BYTES = MM_STAGE_H * 2;
static constexpr int MM_SMEM_BYTES = MM_STAGES * MM_STAGE_BYTES;

__global__ void __launch_bounds__(512, 1)
gemm_mma_kernel(const __half* __restrict__ A, const __half* __restrict__ Bh,
                float* __restrict__ C, int M, int D) {
    extern __shared__ __half sh[];
    uint32_t sbase = smem_to_u32(sh);
    int tid = threadIdx.x;
    int lane = tid & 31;
    int warp = tid >> 5;
    int mb = blockIdx.x * MM_BM;
    int nb = blockIdx.y * MM_BN;
    int wm = (warp >> 2) * 32;
    int wn = (warp & 3) * 64;
    const int nch = D / MM_BK;

    float acc[2][8][4];
    #pragma unroll
    for (int i = 0; i < 2; i++)
        #pragma unroll
        for (int j = 0; j < 8; j++)
            #pragma unroll
            for (int q = 0; q < 4; q++) acc[i][j][q] = 0.f;

    int arow = tid >> 2;
    int achk = (tid & 3) * 8;
    int gma = mb + arow;
    bool apred = gma < M;
    size_t abase = (size_t)(apred ? gma : 0) * D + achk;

    auto stage_load = [&](int ch) {
        if (ch < nch) {
            int kb = ch * MM_BK;
            uint32_t st = sbase + (ch % MM_STAGES) * MM_STAGE_BYTES;
            cp16(st + (MM_AH + arow * MM_LD + achk) * 2, A + abase + kb, apred);
            #pragma unroll
            for (int i = 0; i < 2; i++) {
                int idx = tid + i * 512;
                int row = idx >> 2;
                int chk = (idx & 3) * 8;
                size_t go = (size_t)(nb + row) * D + kb + chk;
                cp16(st + (MM_BH + row * MM_LD + chk) * 2, Bh + go, true);
            }
        }
        asm volatile("cp.async.commit_group;" ::: "memory");
    };

    stage_load(0);
    stage_load(1);
    stage_load(2);

    int a_r = (lane & 15);
    int a_c = (lane >> 4) << 3;
    int b_r = (lane & 7) + ((lane & 16) >> 1);
    int b_c = (lane & 8);

    for (int ch = 0; ch < nch; ch++) {
        asm volatile("cp.async.wait_group 2;" ::: "memory");
        __syncthreads();
        stage_load(ch + 3);

        uint32_t stb = sbase + (ch % MM_STAGES) * MM_STAGE_BYTES;
        #pragma unroll
        for (int s16 = 0; s16 < 2; s16++) {
            int k0 = s16 * 16;
            uint32_t ah[2][4], bh[8][2];
            #pragma unroll
            for (int mi = 0; mi < 2; mi++) {
                uint32_t addr = stb + (MM_AH + (wm + mi * 16 + a_r) * MM_LD + k0 + a_c) * 2;
                ldsm4(addr, ah[mi][0], ah[mi][1], ah[mi][2], ah[mi][3]);
            }
            #pragma unroll
            for (int nj = 0; nj < 4; nj++) {
                uint32_t addr = stb + (MM_BH + (wn + nj * 16 + b_r) * MM_LD + k0 + b_c) * 2;
                ldsm4(addr, bh[2 * nj][0], bh[2 * nj][1], bh[2 * nj + 1][0], bh[2 * nj + 1][1]);
            }
            #pragma unroll
            for (int mi = 0; mi < 2; mi++)
                #pragma unroll
                for (int nj = 0; nj < 8; nj++) mma_fp16(acc[mi][nj], ah[mi], bh[nj]);
        }
        __syncthreads();
    }

    #pragma unroll
    for (int mi = 0; mi < 2; mi++) {
        int gm0 = mb + wm + mi * 16 + (lane >> 2);
        int gm1 = gm0 + 8;
        #pragma unroll
        for (int nj = 0; nj < 8; nj++) {
            int gn = nb + wn + nj * 8 + (lane & 3) * 2;
            if (gm0 < M)
                *(float2*)(C + (size_t)gm0 * D + gn) = make_float2(acc[mi][nj][0], acc[mi][nj][1]);
            if (gm1 < M)
                *(float2*)(C + (size_t)gm1 * D + gn) = make_float2(acc[mi][nj][2], acc[mi][nj][3]);
        }
    }
}

// ---------------------------------------------------------------------------
// fp32 tiled SGEMM (tiny rel_new GEMM, R=500)
// ---------------------------------------------------------------------------
__global__ void gemm128_plain(const float* __restrict__ A0, const float* __restrict__ W,
                              float* __restrict__ C, int M, int D) {
    constexpr int BM = 128, BN = 128, BK = 16;
    __shared__ float As[BK][BM];
    __shared__ float Bs[BK][BN];
    int tid = threadIdx.x;
    int mb = blockIdx.x * BM;
    int nb = blockIdx.y * BN;
    int tx = tid & 15, ty = tid >> 4;
    float acc[8][8];
    #pragma unroll
    for (int i = 0; i < 8; i++)
        #pragma unroll
        for (int j = 0; j < 8; j++) acc[i][j] = 0.f;
    for (int kb = 0; kb < D; kb += BK) {
        #pragma unroll
        for (int i = 0; i < 2; i++) {
            int q = tid + i * 256;
            int row = q >> 2;
            int kc = (q & 3) << 2;
            int gr = mb + row;
            float4 v = make_float4(0.f, 0.f, 0.f, 0.f);
            if (gr < M) v = *(const float4*)(A0 + (size_t)gr * D + kb + kc);
            As[kc + 0][row] = v.x; As[kc + 1][row] = v.y;
            As[kc + 2][row] = v.z; As[kc + 3][row] = v.w;
        }
        #pragma unroll
        for (int i = 0; i < 2; i++) {
            int q = tid + i * 256;
            int kr = q >> 5;
            int jc = (q & 31) << 2;
            *(float4*)&Bs[kr][jc] = *(const float4*)(W + (size_t)(kb + kr) * D + nb + jc);
        }
        __syncthreads();
        #pragma unroll
        for (int k = 0; k < BK; k++) {
            float a[8], b[8];
            *(float4*)&a[0] = *(const float4*)&As[k][ty * 8];
            *(float4*)&a[4] = *(const float4*)&As[k][ty * 8 + 4];
            *(float4*)&b[0] = *(const float4*)&Bs[k][tx * 8];
            *(float4*)&b[4] = *(const float4*)&Bs[k][tx * 8 + 4];
            #pragma unroll
            for (int i = 0; i < 8; i++)
                #pragma unroll
                for (int j = 0; j < 8; j++)
                    acc[i][j] = fmaf(a[i], b[j], acc[i][j]);
        }
        __syncthreads();
    }
    #pragma unroll
    for (int i = 0; i < 8; i++) {
        int gr = mb + ty * 8 + i;
        if (gr < M) {
            float* cp = C + (size_t)gr * D + nb + tx * 8;
            *(float4*)(cp + 0) = make_float4(acc[i][0], acc[i][1], acc[i][2], acc[i][3]);
            *(float4*)(cp + 4) = make_float4(acc[i][4], acc[i][5], acc[i][6], acc[i][7]);
        }
    }
}

// ---------------------------------------------------------------------------
// Final gather
// ---------------------------------------------------------------------------
__global__ void gather_out(const int* __restrict__ triples, const float* __restrict__ entn,
                           const float* __restrict__ reln, float4* __restrict__ out,
                           int B, int D) {
    int nv = D >> 2;
    int total = B * 3 * nv;
    int i = blockIdx.x * blockDim.x + threadIdx.x;
    int stride = gridDim.x * blockDim.x;
    for (; i < total; i += stride) {
        int d4 = i % nv;
        int bt = i / nv;
        int t = bt % 3;
        int b = bt / 3;
        int idx = triples[b * 3 + t];
        const float4* srcp = (t == 1) ? (const float4*)(reln + (size_t)idx * D)
                                      : (const float4*)(entn + (size_t)idx * D);
        out[i] = srcp[d4];
    }
}

// ---------------------------------------------------------------------------
// Launch
// ---------------------------------------------------------------------------
extern "C" void kernel_launch(void* const* d_in, const int* in_sizes, int n_in,
                              void* d_out, int out_size) {
    const int*   triples  = (const int*)d_in[0];
    const int*   nodelist = (const int*)d_in[1];
    const int*   edgelist = (const int*)d_in[2];
    const float* ent      = (const float*)d_in[3];
    const float* rel      = (const float*)d_in[4];
    const float* W1       = (const float*)d_in[5];
    const float* Wa       = (const float*)d_in[6];
    const float* g0       = (const float*)d_in[7];
    const float* WE       = (const float*)d_in[8];
    const float* WR       = (const float*)d_in[9];

    int B = in_sizes[0] / 3;
    int E = in_sizes[2];
    int D = in_sizes[6];
    int N = in_sizes[3] / D;
    int R = in_sizes[4] / D;

    float *entn, *Cbase, *Cedge, *Epre, *reln;
    int *cnt, *off, *cur, *eidx, *bsum;
    __half *e0h, *egh, *edh, *relh, *w1h, *weth;
    cudaGetSymbolAddress((void**)&entn,  g_entn);
    cudaGetSymbolAddress((void**)&Cbase, g_Cbase);
    cudaGetSymbolAddress((void**)&Cedge, g_Cedge);
    cudaGetSymbolAddress((void**)&Epre,  g_Epre);
    cudaGetSymbolAddress((void**)&reln,  g_reln);
    cudaGetSymbolAddress((void**)&cnt,   g_cnt);
    cudaGetSymbolAddress((void**)&off,   g_off);
    cudaGetSymbolAddress((void**)&cur,   g_cur);
    cudaGetSymbolAddress((void**)&eidx,  g_eidx);
    cudaGetSymbolAddress((void**)&bsum,  g_bsum);
    cudaGetSymbolAddress((void**)&e0h,   g_e0h);
    cudaGetSymbolAddress((void**)&egh,   g_egh);
    cudaGetSymbolAddress((void**)&edh,   g_edh);
    cudaGetSymbolAddress((void**)&relh,  g_relh);
    cudaGetSymbolAddress((void**)&w1h,   g_w1h);
    cudaGetSymbolAddress((void**)&weth,  g_weth);

    cudaFuncSetAttribute(gemm_mma_kernel,
                         cudaFuncAttributeMaxDynamicSharedMemorySize, MM_SMEM_BYTES);

    // ---- CSR build (src = node_list[0,:])
    zero_int<<<(N + 255) / 256, 256>>>(cnt, N);
    count_deg<<<(E + 255) / 256, 256>>>(nodelist, cnt, E);
    int nblk = (N + 1023) / 1024;
    scan1<<<nblk, 1024>>>(cnt, off, bsum, N);
    scan2<<<1, 1024>>>(bsum, nblk);
    scan3<<<(N + 255) / 256, 256>>>(off, cur, bsum, N, E);
    fill_eidx<<<(E + 255) / 256, 256>>>(nodelist, cur, eidx, E);

    // ---- operand prep
    normalize_split<<<(N + 7) / 8, 256>>>(ent, g0, e0h, egh, N, D);
    split_weights<<<(D * D + 255) / 256, 256>>>(W1, WE, rel, w1h, weth, relh, D, R * D);
    split_edge<<<(E + 7) / 8, 256>>>(e0h, relh, nodelist + E, edgelist, edh, E, D);

    // ---- GEMMs (single-pass fp16)
    dim3 gN((N + MM_BM - 1) / MM_BM, D / MM_BN);
    dim3 gE2((E + MM_BM - 1) / MM_BM, D / MM_BN);
    gemm_mma_kernel<<<gN, 512, MM_SMEM_BYTES>>>(egh, w1h, Cbase, N, D);
    gemm_mma_kernel<<<gE2, 512, MM_SMEM_BYTES>>>(edh, w1h, Cedge, E, D);
    gemm_mma_kernel<<<gN, 512, MM_SMEM_BYTES>>>(e0h, weth, Epre, N, D);

    // ---- fused aggregation + epilogue
    node_aggregate<<<(N + 7) / 8, 256>>>(e0h, Cbase, Cedge, Epre, Wa, off, eidx, entn, N, D);

    // ---- rel_new + output gather
    dim3 gR((R + 127) / 128, D / 128);
    gemm128_plain<<<gR, 256>>>(rel, WR, reln, R, D);
    int total4 = B * 3 * (D >> 2);
    gather_out<<<(total4 + 255) / 256, 256>>>(triples, entn, reln, (float4*)d_out, B, D);
}

// round 9
// speedup vs baseline: 4.6645x; 1.0032x over previous
#include <cuda_runtime.h>
#include <cuda_fp16.h>
#include <math.h>
#include <stdint.h>

// ---------------------------------------------------------------------------
// UPGAT layer.  N=100000, R=500, D=512, E=150000, B=4096.
// GEMMs: fp16 single-pass mma.sync (fp32 acc); Cbase/Cedge stored fp16.
// Aggregation: pull-style CSR, fused epilogue, tanh.approx.
// ---------------------------------------------------------------------------

#define MAX_N 100000
#define MAX_E 150000
#define MAX_R 500
#define MAX_D 512

__device__ float g_entn [(size_t)MAX_N * MAX_D];   // ent_new output
__device__ float g_Epre [(size_t)MAX_N * MAX_D];
__device__ float g_reln [(size_t)MAX_R * MAX_D];

// fp16 message matrices
__device__ __half g_Cbaseh[(size_t)MAX_N * MAX_D];
__device__ __half g_Cedgeh[(size_t)MAX_E * MAX_D];

// CSR scratch
__device__ int g_cnt [MAX_N];
__device__ int g_off [MAX_N + 1];
__device__ int g_cur [MAX_N];
__device__ int g_eidx[MAX_E];
__device__ int g_bsum[128];

// fp16 operands
__device__ __half g_e0h[(size_t)MAX_N * MAX_D];
__device__ __half g_egh[(size_t)MAX_N * MAX_D];
__device__ __half g_edh[(size_t)MAX_E * MAX_D];
__device__ __half g_relh[(size_t)MAX_R * MAX_D];
__device__ __half g_w1h[MAX_D * MAX_D];
__device__ __half g_weth[MAX_D * MAX_D];

// ---------------------------------------------------------------------------
// helpers
// ---------------------------------------------------------------------------
__device__ __forceinline__ uint32_t smem_to_u32(const void* smem_ptr) {
    uint32_t addr;
    asm("{ .reg .u64 tmp; cvta.to.shared.u64 tmp, %1; cvt.u32.u64 %0, tmp; }"
        : "=r"(addr) : "l"(smem_ptr));
    return addr;
}
__device__ __forceinline__ void ldsm4(uint32_t addr, uint32_t& r0, uint32_t& r1,
                                      uint32_t& r2, uint32_t& r3) {
    asm volatile("ldmatrix.sync.aligned.m8n8.x4.shared.b16 {%0,%1,%2,%3}, [%4];"
                 : "=r"(r0), "=r"(r1), "=r"(r2), "=r"(r3) : "r"(addr));
}
__device__ __forceinline__ void mma_fp16(float* d, const uint32_t* a, const uint32_t* b) {
    asm volatile(
        "mma.sync.aligned.m16n8k16.row.col.f32.f16.f16.f32 "
        "{%0,%1,%2,%3}, {%4,%5,%6,%7}, {%8,%9}, {%0,%1,%2,%3};"
        : "+f"(d[0]), "+f"(d[1]), "+f"(d[2]), "+f"(d[3])
        : "r"(a[0]), "r"(a[1]), "r"(a[2]), "r"(a[3]), "r"(b[0]), "r"(b[1]));
}
__device__ __forceinline__ void cp16(uint32_t dst, const void* src, bool pred) {
    int sz = pred ? 16 : 0;
    asm volatile("cp.async.cg.shared.global [%0], [%1], 16, %2;"
                 :: "r"(dst), "l"(src), "r"(sz) : "memory");
}
__device__ __forceinline__ uint32_t pkh(__half a, __half b) {
    __half2 t = __halves2half2(a, b);
    return *reinterpret_cast<uint32_t*>(&t);
}
__device__ __forceinline__ uint2 h4(float4 v) {
    return make_uint2(pkh(__float2half_rn(v.x), __float2half_rn(v.y)),
                      pkh(__float2half_rn(v.z), __float2half_rn(v.w)));
}
__device__ __forceinline__ float4 f4ofh(uint2 u) {
    __half2* h2 = (__half2*)&u;
    float2 a = __half22float2(h2[0]);
    float2 b = __half22float2(h2[1]);
    return make_float4(a.x, a.y, b.x, b.y);
}
__device__ __forceinline__ float tanha(float x) {
    float y;
    asm("tanh.approx.f32 %0, %1;" : "=f"(y) : "f"(x));
    return y;
}

// ---------------------------------------------------------------------------
__global__ void zero_int(int* __restrict__ p, int n) {
    int i = blockIdx.x * blockDim.x + threadIdx.x;
    if (i < n) p[i] = 0;
}

// ---------------------------------------------------------------------------
// e0h = fp16(l2norm(ent)); egh = fp16(l2norm(ent)*g0).  Warp per row.
// ---------------------------------------------------------------------------
__global__ void normalize_split(const float* __restrict__ in, const float* __restrict__ g0,
                                __half* __restrict__ e0h, __half* __restrict__ egh,
                                int M, int D) {
    int warp = (blockIdx.x * blockDim.x + threadIdx.x) >> 5;
    int lane = threadIdx.x & 31;
    if (warp >= M) return;
    const float4* ip = (const float4*)(in + (size_t)warp * D);
    const float4* gp = (const float4*)g0;
    int nv = D >> 2;
    float s = 0.f;
    for (int i = lane; i < nv; i += 32) {
        float4 v = ip[i];
        s += v.x * v.x + v.y * v.y + v.z * v.z + v.w * v.w;
    }
    #pragma unroll
    for (int o = 16; o; o >>= 1) s += __shfl_xor_sync(0xFFFFFFFFu, s, o);
    float inv = 1.f / fmaxf(sqrtf(s), 1e-12f);
    size_t rbase = (size_t)warp * D;
    for (int i = lane; i < nv; i += 32) {
        float4 v = ip[i];
        float4 n = make_float4(v.x * inv, v.y * inv, v.z * inv, v.w * inv);
        *(uint2*)(e0h + rbase + i * 4) = h4(n);
        float4 g = gp[i];
        *(uint2*)(egh + rbase + i * 4) =
            h4(make_float4(n.x * g.x, n.y * g.y, n.z * g.z, n.w * g.w));
    }
}

// ---------------------------------------------------------------------------
// Edge operand (all fp16): A[e,:] = e0h[dst[e],:] * relh[edge[e],:].
// ---------------------------------------------------------------------------
__global__ void split_edge(const __half* __restrict__ e0h, const __half* __restrict__ relh,
                           const int* __restrict__ dsts, const int* __restrict__ edges,
                           __half* __restrict__ eh, int E, int D) {
    int warp = (blockIdx.x * blockDim.x + threadIdx.x) >> 5;
    int lane = threadIdx.x & 31;
    if (warp >= E) return;
    int dst = dsts[warp];
    int rl = edges[warp];
    const uint2* ap = (const uint2*)(e0h + (size_t)dst * D);
    const uint2* gp = (const uint2*)(relh + (size_t)rl * D);
    uint2* op = (uint2*)(eh + (size_t)warp * D);
    int nv = D >> 2;
    for (int i = lane; i < nv; i += 32) {
        uint2 a = ap[i], g = gp[i];
        __half2* ah = (__half2*)&a;
        __half2* gh = (__half2*)&g;
        uint2 r;
        __half2* rh = (__half2*)&r;
        rh[0] = __hmul2(ah[0], gh[0]);
        rh[1] = __hmul2(ah[1], gh[1]);
        op[i] = r;
    }
}

// ---------------------------------------------------------------------------
// Weight + relation fp16 conversion: W1 as-is ([N,K]); WE transposed; rel.
// ---------------------------------------------------------------------------
__global__ void split_weights(const float* __restrict__ W1, const float* __restrict__ WE,
                              const float* __restrict__ rel,
                              __half* __restrict__ w1h, __half* __restrict__ weth,
                              __half* __restrict__ relh, int D, int RD) {
    int i = blockIdx.x * blockDim.x + threadIdx.x;
    int tot = D * D;
    if (i < tot) {
        w1h[i] = __float2half_rn(W1[i]);
        int k = i / D, j = i % D;
        weth[(size_t)j * D + k] = __float2half_rn(WE[i]);
    }
    if (i < RD) relh[i] = __float2half_rn(rel[i]);
}

// ---------------------------------------------------------------------------
// CSR build
// ---------------------------------------------------------------------------
__global__ void count_deg(const int* __restrict__ srcs, int* __restrict__ cnt, int E) {
    int e = blockIdx.x * blockDim.x + threadIdx.x;
    if (e < E) atomicAdd(&cnt[srcs[e]], 1);
}
__global__ void scan1(const int* __restrict__ cnt, int* __restrict__ off,
                      int* __restrict__ bsum, int N) {
    __shared__ int sm[1024];
    int tid = threadIdx.x;
    int i = blockIdx.x * 1024 + tid;
    int v = (i < N) ? cnt[i] : 0;
    sm[tid] = v;
    __syncthreads();
    #pragma unroll
    for (int d = 1; d < 1024; d <<= 1) {
        int t = (tid >= d) ? sm[tid - d] : 0;
        __syncthreads();
        sm[tid] += t;
        __syncthreads();
    }
    if (i < N) off[i] = sm[tid] - v;
    if (tid == 1023) bsum[blockIdx.x] = sm[1023];
}
__global__ void scan2(int* __restrict__ bsum, int nb) {
    __shared__ int sm[1024];
    int tid = threadIdx.x;
    int v = (tid < nb) ? bsum[tid] : 0;
    sm[tid] = v;
    __syncthreads();
    #pragma unroll
    for (int d = 1; d < 1024; d <<= 1) {
        int t = (tid >= d) ? sm[tid - d] : 0;
        __syncthreads();
        sm[tid] += t;
        __syncthreads();
    }
    if (tid < nb) bsum[tid] = sm[tid] - v;
}
__global__ void scan3(int* __restrict__ off, int* __restrict__ cur,
                      const int* __restrict__ bsum, int N, int E) {
    int i = blockIdx.x * blockDim.x + threadIdx.x;
    if (i < N) {
        int o = off[i] + bsum[i >> 10];
        off[i] = o;
        cur[i] = o;
    }
    if (i == 0) off[N] = E;
}
__global__ void fill_eidx(const int* __restrict__ srcs, int* __restrict__ cur,
                          int* __restrict__ eidx, int E) {
    int e = blockIdx.x * blockDim.x + threadIdx.x;
    if (e < E) {
        int pos = atomicAdd(&cur[srcs[e]], 1);
        eidx[pos] = e;
    }
}

// ---------------------------------------------------------------------------
// Fused node aggregation (warp per node).  Cb/Ce read as fp16.
// ---------------------------------------------------------------------------
__global__ void node_aggregate(const __half* __restrict__ e0h, const __half* __restrict__ Cbh,
                               const __half* __restrict__ Ceh, const float* __restrict__ Epre,
                               const float* __restrict__ Wa,
                               const int* __restrict__ off, const int* __restrict__ eidx,
                               float* __restrict__ entnew, int N, int D) {
    __shared__ float waS[512];
    for (int i = threadIdx.x; i < D; i += blockDim.x) waS[i] = Wa[i];
    __syncthreads();

    int warp = (blockIdx.x * blockDim.x + threadIdx.x) >> 5;
    int lane = threadIdx.x & 31;
    if (warp >= N) return;
    int o0 = off[warp], o1 = off[warp + 1];
    int deg = o1 - o0;

    const uint2* ep = (const uint2*)(e0h + (size_t)warp * D);
    const uint2* cbp = (const uint2*)(Cbh + (size_t)warp * D);
    const float4* wp = (const float4*)waS;

    float4 ew[4], acc[4];
    float sb = 0.f;
    #pragma unroll
    for (int i = 0; i < 4; i++) {
        int ii = lane + i * 32;
        float4 e = f4ofh(ep[ii]);
        float4 w = wp[ii];
        ew[i] = make_float4(e.x * w.x, e.y * w.y, e.z * w.z, e.w * w.w);
        float4 c = f4ofh(cbp[ii]);
        acc[i] = c;
        sb += ew[i].x * tanha(c.x) + ew[i].y * tanha(c.y) +
              ew[i].z * tanha(c.z) + ew[i].w * tanha(c.w);
    }
    #pragma unroll
    for (int o = 16; o; o >>= 1) sb += __shfl_xor_sync(0xFFFFFFFFu, sb, o);
    float lb = sb > 0.f ? sb : 0.2f * sb;
    float ab = expf(-lb);
    float coef = (deg > 0) ? ab : 0.f;
    float den = coef;
    #pragma unroll
    for (int i = 0; i < 4; i++) {
        acc[i].x *= coef; acc[i].y *= coef; acc[i].z *= coef; acc[i].w *= coef;
    }

    for (int j = o0; j < o1; j++) {
        int e = eidx[j];
        const uint2* cp = (const uint2*)(Ceh + (size_t)e * D);
        float4 cv[4];
        float s = 0.f;
        #pragma unroll
        for (int i = 0; i < 4; i++) {
            int ii = lane + i * 32;
            float4 c = f4ofh(cp[ii]);
            cv[i] = c;
            s += ew[i].x * tanha(c.x) + ew[i].y * tanha(c.y) +
                 ew[i].z * tanha(c.z) + ew[i].w * tanha(c.w);
        }
        #pragma unroll
        for (int o = 16; o; o >>= 1) s += __shfl_xor_sync(0xFFFFFFFFu, s, o);
        float l = s > 0.f ? s : 0.2f * s;
        float aexp = expf(-l);
        den += aexp;
        #pragma unroll
        for (int i = 0; i < 4; i++) {
            acc[i].x = fmaf(aexp, cv[i].x, acc[i].x);
            acc[i].y = fmaf(aexp, cv[i].y, acc[i].y);
            acc[i].z = fmaf(aexp, cv[i].z, acc[i].z);
            acc[i].w = fmaf(aexp, cv[i].w, acc[i].w);
        }
    }

    if (den == 0.f) den = 1e-12f;
    float invden = 1.f / den;
    const float4* epp = (const float4*)(Epre + (size_t)warp * D);
    float4* op = (float4*)(entnew + (size_t)warp * D);
    float nrm = 0.f;
    float4 tv[4];
    #pragma unroll
    for (int i = 0; i < 4; i++) {
        int ii = lane + i * 32;
        float4 ep4 = epp[ii];
        float4 t;
        float x = acc[i].x * invden; t.x = ep4.x + (x > 0.f ? x : expm1f(x));
        x = acc[i].y * invden;       t.y = ep4.y + (x > 0.f ? x : expm1f(x));
        x = acc[i].z * invden;       t.z = ep4.z + (x > 0.f ? x : expm1f(x));
        x = acc[i].w * invden;       t.w = ep4.w + (x > 0.f ? x : expm1f(x));
        tv[i] = t;
        nrm += t.x * t.x + t.y * t.y + t.z * t.z + t.w * t.w;
    }
    #pragma unroll
    for (int o = 16; o; o >>= 1) nrm += __shfl_xor_sync(0xFFFFFFFFu, nrm, o);
    float inv = 1.f / fmaxf(sqrtf(nrm), 1e-12f);
    #pragma unroll
    for (int i = 0; i < 4; i++) {
        int ii = lane + i * 32;
        float4 t = tv[i];
        op[ii] = make_float4(t.x * inv, t.y * inv, t.z * inv, t.w * inv);
    }
}

// ---------------------------------------------------------------------------
// mma.sync fp16 GEMM (single pass): C[M,D] = A @ W^T,  W stored [N,K].
// HOUT: write fp16 C (Cbase/Cedge) vs fp32 (Epre).
// ---------------------------------------------------------------------------
#define MM_BM 128
#define MM_BN 256
#define MM_BK 32
#define MM_LD 40
#define MM_STAGES 4
static constexpr int MM_AH = 0;
static constexpr int MM_BH = 128 * MM_LD;
static constexpr int MM_STAGE_H = 15360;
static constexpr int MM_STAGE_BYTES = MM_STAGE_H * 2;
static constexpr int MM_SMEM_BYTES = MM_STAGES * MM_STAGE_BYTES;

template<bool HOUT>
__global__ void __launch_bounds__(512, 1)
gemm_mma_kernel(const __half* __restrict__ A, const __half* __restrict__ Bh,
                void* __restrict__ Cv, int M, int D) {
    extern __shared__ __half sh[];
    uint32_t sbase = smem_to_u32(sh);
    int tid = threadIdx.x;
    int lane = tid & 31;
    int warp = tid >> 5;
    int mb = blockIdx.x * MM_BM;
    int nb = blockIdx.y * MM_BN;
    int wm = (warp >> 2) * 32;
    int wn = (warp & 3) * 64;
    const int nch = D / MM_BK;

    float acc[2][8][4];
    #pragma unroll
    for (int i = 0; i < 2; i++)
        #pragma unroll
        for (int j = 0; j < 8; j++)
            #pragma unroll
            for (int q = 0; q < 4; q++) acc[i][j][q] = 0.f;

    int arow = tid >> 2;
    int achk = (tid & 3) * 8;
    int gma = mb + arow;
    bool apred = gma < M;
    size_t abase = (size_t)(apred ? gma : 0) * D + achk;

    auto stage_load = [&](int ch) {
        if (ch < nch) {
            int kb = ch * MM_BK;
            uint32_t st = sbase + (ch % MM_STAGES) * MM_STAGE_BYTES;
            cp16(st + (MM_AH + arow * MM_LD + achk) * 2, A + abase + kb, apred);
            #pragma unroll
            for (int i = 0; i < 2; i++) {
                int idx = tid + i * 512;
                int row = idx >> 2;
                int chk = (idx & 3) * 8;
                size_t go = (size_t)(nb + row) * D + kb + chk;
                cp16(st + (MM_BH + row * MM_LD + chk) * 2, Bh + go, true);
            }
        }
        asm volatile("cp.async.commit_group;" ::: "memory");
    };

    stage_load(0);
    stage_load(1);
    stage_load(2);

    int a_r = (lane & 15);
    int a_c = (lane >> 4) << 3;
    int b_r = (lane & 7) + ((lane & 16) >> 1);
    int b_c = (lane & 8);

    for (int ch = 0; ch < nch; ch++) {
        asm volatile("cp.async.wait_group 2;" ::: "memory");
        __syncthreads();
        stage_load(ch + 3);

        uint32_t stb = sbase + (ch % MM_STAGES) * MM_STAGE_BYTES;
        #pragma unroll
        for (int s16 = 0; s16 < 2; s16++) {
            int k0 = s16 * 16;
            uint32_t ah[2][4], bh[8][2];
            #pragma unroll
            for (int mi = 0; mi < 2; mi++) {
                uint32_t addr = stb + (MM_AH + (wm + mi * 16 + a_r) * MM_LD + k0 + a_c) * 2;
                ldsm4(addr, ah[mi][0], ah[mi][1], ah[mi][2], ah[mi][3]);
            }
            #pragma unroll
            for (int nj = 0; nj < 4; nj++) {
                uint32_t addr = stb + (MM_BH + (wn + nj * 16 + b_r) * MM_LD + k0 + b_c) * 2;
                ldsm4(addr, bh[2 * nj][0], bh[2 * nj][1], bh[2 * nj + 1][0], bh[2 * nj + 1][1]);
            }
            #pragma unroll
            for (int mi = 0; mi < 2; mi++)
                #pragma unroll
                for (int nj = 0; nj < 8; nj++) mma_fp16(acc[mi][nj], ah[mi], bh[nj]);
        }
        __syncthreads();
    }

    #pragma unroll
    for (int mi = 0; mi < 2; mi++) {
        int gm0 = mb + wm + mi * 16 + (lane >> 2);
        int gm1 = gm0 + 8;
        #pragma unroll
        for (int nj = 0; nj < 8; nj++) {
            int gn = nb + wn + nj * 8 + (lane & 3) * 2;
            if (HOUT) {
                __half* C = (__half*)Cv;
                if (gm0 < M)
                    *(uint32_t*)(C + (size_t)gm0 * D + gn) =
                        pkh(__float2half_rn(acc[mi][nj][0]), __float2half_rn(acc[mi][nj][1]));
                if (gm1 < M)
                    *(uint32_t*)(C + (size_t)gm1 * D + gn) =
                        pkh(__float2half_rn(acc[mi][nj][2]), __float2half_rn(acc[mi][nj][3]));
            } else {
                float* C = (float*)Cv;
                if (gm0 < M)
                    *(float2*)(C + (size_t)gm0 * D + gn) = make_float2(acc[mi][nj][0], acc[mi][nj][1]);
                if (gm1 < M)
                    *(float2*)(C + (size_t)gm1 * D + gn) = make_float2(acc[mi][nj][2], acc[mi][nj][3]);
            }
        }
    }
}

// ---------------------------------------------------------------------------
// fp32 tiled SGEMM (tiny rel_new GEMM, R=500)
// ---------------------------------------------------------------------------
__global__ void gemm128_plain(const float* __restrict__ A0, const float* __restrict__ W,
                              float* __restrict__ C, int M, int D) {
    constexpr int BM = 128, BN = 128, BK = 16;
    __shared__ float As[BK][BM];
    __shared__ float Bs[BK][BN];
    int tid = threadIdx.x;
    int mb = blockIdx.x * BM;
    int nb = blockIdx.y * BN;
    int tx = tid & 15, ty = tid >> 4;
    float acc[8][8];
    #pragma unroll
    for (int i = 0; i < 8; i++)
        #pragma unroll
        for (int j = 0; j < 8; j++) acc[i][j] = 0.f;
    for (int kb = 0; kb < D; kb += BK) {
        #pragma unroll
        for (int i = 0; i < 2; i++) {
            int q = tid + i * 256;
            int row = q >> 2;
            int kc = (q & 3) << 2;
            int gr = mb + row;
            float4 v = make_float4(0.f, 0.f, 0.f, 0.f);
            if (gr < M) v = *(const float4*)(A0 + (size_t)gr * D + kb + kc);
            As[kc + 0][row] = v.x; As[kc + 1][row] = v.y;
            As[kc + 2][row] = v.z; As[kc + 3][row] = v.w;
        }
        #pragma unroll
        for (int i = 0; i < 2; i++) {
            int q = tid + i * 256;
            int kr = q >> 5;
            int jc = (q & 31) << 2;
            *(float4*)&Bs[kr][jc] = *(const float4*)(W + (size_t)(kb + kr) * D + nb + jc);
        }
        __syncthreads();
        #pragma unroll
        for (int k = 0; k < BK; k++) {
            float a[8], b[8];
            *(float4*)&a[0] = *(const float4*)&As[k][ty * 8];
            *(float4*)&a[4] = *(const float4*)&As[k][ty * 8 + 4];
            *(float4*)&b[0] = *(const float4*)&Bs[k][tx * 8];
            *(float4*)&b[4] = *(const float4*)&Bs[k][tx * 8 + 4];
            #pragma unroll
            for (int i = 0; i < 8; i++)
                #pragma unroll
                for (int j = 0; j < 8; j++)
                    acc[i][j] = fmaf(a[i], b[j], acc[i][j]);
        }
        __syncthreads();
    }
    #pragma unroll
    for (int i = 0; i < 8; i++) {
        int gr = mb + ty * 8 + i;
        if (gr < M) {
            float* cp = C + (size_t)gr * D + nb + tx * 8;
            *(float4*)(cp + 0) = make_float4(acc[i][0], acc[i][1], acc[i][2], acc[i][3]);
            *(float4*)(cp + 4) = make_float4(acc[i][4], acc[i][5], acc[i][6], acc[i][7]);
        }
    }
}

// ---------------------------------------------------------------------------
// Final gather
// ---------------------------------------------------------------------------
__global__ void gather_out(const int* __restrict__ triples, const float* __restrict__ entn,
                           const float* __restrict__ reln, float4* __restrict__ out,
                           int B, int D) {
    int nv = D >> 2;
    int total = B * 3 * nv;
    int i = blockIdx.x * blockDim.x + threadIdx.x;
    int stride = gridDim.x * blockDim.x;
    for (; i < total; i += stride) {
        int d4 = i % nv;
        int bt = i / nv;
        int t = bt % 3;
        int b = bt / 3;
        int idx = triples[b * 3 + t];
        const float4* srcp = (t == 1) ? (const float4*)(reln + (size_t)idx * D)
                                      : (const float4*)(entn + (size_t)idx * D);
        out[i] = srcp[d4];
    }
}

// ---------------------------------------------------------------------------
// Launch
// ---------------------------------------------------------------------------
extern "C" void kernel_launch(void* const* d_in, const int* in_sizes, int n_in,
                              void* d_out, int out_size) {
    const int*   triples  = (const int*)d_in[0];
    const int*   nodelist = (const int*)d_in[1];
    const int*   edgelist = (const int*)d_in[2];
    const float* ent      = (const float*)d_in[3];
    const float* rel      = (const float*)d_in[4];
    const float* W1       = (const float*)d_in[5];
    const float* Wa       = (const float*)d_in[6];
    const float* g0       = (const float*)d_in[7];
    const float* WE       = (const float*)d_in[8];
    const float* WR       = (const float*)d_in[9];

    int B = in_sizes[0] / 3;
    int E = in_sizes[2];
    int D = in_sizes[6];
    int N = in_sizes[3] / D;
    int R = in_sizes[4] / D;

    float *entn, *Epre, *reln;
    int *cnt, *off, *cur, *eidx, *bsum;
    __half *Cbaseh, *Cedgeh, *e0h, *egh, *edh, *relh, *w1h, *weth;
    cudaGetSymbolAddress((void**)&entn,   g_entn);
    cudaGetSymbolAddress((void**)&Epre,   g_Epre);
    cudaGetSymbolAddress((void**)&reln,   g_reln);
    cudaGetSymbolAddress((void**)&Cbaseh, g_Cbaseh);
    cudaGetSymbolAddress((void**)&Cedgeh, g_Cedgeh);
    cudaGetSymbolAddress((void**)&cnt,    g_cnt);
    cudaGetSymbolAddress((void**)&off,    g_off);
    cudaGetSymbolAddress((void**)&cur,    g_cur);
    cudaGetSymbolAddress((void**)&eidx,   g_eidx);
    cudaGetSymbolAddress((void**)&bsum,   g_bsum);
    cudaGetSymbolAddress((void**)&e0h,    g_e0h);
    cudaGetSymbolAddress((void**)&egh,    g_egh);
    cudaGetSymbolAddress((void**)&edh,    g_edh);
    cudaGetSymbolAddress((void**)&relh,   g_relh);
    cudaGetSymbolAddress((void**)&w1h,    g_w1h);
    cudaGetSymbolAddress((void**)&weth,   g_weth);

    cudaFuncSetAttribute(gemm_mma_kernel<true>,
                         cudaFuncAttributeMaxDynamicSharedMemorySize, MM_SMEM_BYTES);
    cudaFuncSetAttribute(gemm_mma_kernel<false>,
                         cudaFuncAttributeMaxDynamicSharedMemorySize, MM_SMEM_BYTES);

    // ---- CSR build (src = node_list[0,:])
    zero_int<<<(N + 255) / 256, 256>>>(cnt, N);
    count_deg<<<(E + 255) / 256, 256>>>(nodelist, cnt, E);
    int nblk = (N + 1023) / 1024;
    scan1<<<nblk, 1024>>>(cnt, off, bsum, N);
    scan2<<<1, 1024>>>(bsum, nblk);
    scan3<<<(N + 255) / 256, 256>>>(off, cur, bsum, N, E);
    fill_eidx<<<(E + 255) / 256, 256>>>(nodelist, cur, eidx, E);

    // ---- operand prep
    normalize_split<<<(N + 7) / 8, 256>>>(ent, g0, e0h, egh, N, D);
    split_weights<<<(D * D + 255) / 256, 256>>>(W1, WE, rel, w1h, weth, relh, D, R * D);
    split_edge<<<(E + 7) / 8, 256>>>(e0h, relh, nodelist + E, edgelist, edh, E, D);

    // ---- GEMMs (single-pass fp16; Cbase/Cedge out fp16, Epre out fp32)
    dim3 gN((N + MM_BM - 1) / MM_BM, D / MM_BN);
    dim3 gE2((E + MM_BM - 1) / MM_BM, D / MM_BN);
    gemm_mma_kernel<true><<<gN, 512, MM_SMEM_BYTES>>>(egh, w1h, Cbaseh, N, D);
    gemm_mma_kernel<true><<<gE2, 512, MM_SMEM_BYTES>>>(edh, w1h, Cedgeh, E, D);
    gemm_mma_kernel<false><<<gN, 512, MM_SMEM_BYTES>>>(e0h, weth, Epre, N, D);

    // ---- fused aggregation + epilogue
    node_aggregate<<<(N + 7) / 8, 256>>>(e0h, Cbaseh, Cedgeh, Epre, Wa, off, eidx, entn, N, D);

    // ---- rel_new + output gather
    dim3 gR((R + 127) / 128, D / 128);
    gemm128_plain<<<gR, 256>>>(rel, WR, reln, R, D);
    int total4 = B * 3 * (D >> 2);
    gather_out<<<(total4 + 255) / 256, 256>>>(triples, entn, reln, (float4*)d_out, B, D);
}

// round 10
// speedup vs baseline: 4.7189x; 1.0117x over previous
#include <cuda_runtime.h>
#include <cuda_fp16.h>
#include <math.h>
#include <stdint.h>

// ---------------------------------------------------------------------------
// UPGAT layer.  N=100000, R=500, D=512, E=150000, B=4096.
// GEMMs: fp16 single-pass mma.sync (fp32 acc); Cbase/Cedge stored fp16.
// Cedge is materialized in CSR order -> node_aggregate streams it sequentially.
// ---------------------------------------------------------------------------

#define MAX_N 100000
#define MAX_E 150000
#define MAX_R 500
#define MAX_D 512

__device__ float g_entn [(size_t)MAX_N * MAX_D];   // ent_new output
__device__ float g_Epre [(size_t)MAX_N * MAX_D];
__device__ float g_reln [(size_t)MAX_R * MAX_D];

// fp16 message matrices
__device__ __half g_Cbaseh[(size_t)MAX_N * MAX_D];
__device__ __half g_Cedgeh[(size_t)MAX_E * MAX_D];   // CSR-ordered rows

// CSR scratch
__device__ int g_cnt [MAX_N];
__device__ int g_off [MAX_N + 1];
__device__ int g_cur [MAX_N];
__device__ int g_eidx[MAX_E];
__device__ int g_bsum[128];

// fp16 operands
__device__ __half g_e0h[(size_t)MAX_N * MAX_D];
__device__ __half g_egh[(size_t)MAX_N * MAX_D];
__device__ __half g_edh[(size_t)MAX_E * MAX_D];     // CSR-ordered rows
__device__ __half g_relh[(size_t)MAX_R * MAX_D];
__device__ __half g_w1h[MAX_D * MAX_D];
__device__ __half g_weth[MAX_D * MAX_D];

// ---------------------------------------------------------------------------
// helpers
// ---------------------------------------------------------------------------
__device__ __forceinline__ uint32_t smem_to_u32(const void* smem_ptr) {
    uint32_t addr;
    asm("{ .reg .u64 tmp; cvta.to.shared.u64 tmp, %1; cvt.u32.u64 %0, tmp; }"
        : "=r"(addr) : "l"(smem_ptr));
    return addr;
}
__device__ __forceinline__ void ldsm4(uint32_t addr, uint32_t& r0, uint32_t& r1,
                                      uint32_t& r2, uint32_t& r3) {
    asm volatile("ldmatrix.sync.aligned.m8n8.x4.shared.b16 {%0,%1,%2,%3}, [%4];"
                 : "=r"(r0), "=r"(r1), "=r"(r2), "=r"(r3) : "r"(addr));
}
__device__ __forceinline__ void mma_fp16(float* d, const uint32_t* a, const uint32_t* b) {
    asm volatile(
        "mma.sync.aligned.m16n8k16.row.col.f32.f16.f16.f32 "
        "{%0,%1,%2,%3}, {%4,%5,%6,%7}, {%8,%9}, {%0,%1,%2,%3};"
        : "+f"(d[0]), "+f"(d[1]), "+f"(d[2]), "+f"(d[3])
        : "r"(a[0]), "r"(a[1]), "r"(a[2]), "r"(a[3]), "r"(b[0]), "r"(b[1]));
}
__device__ __forceinline__ void cp16(uint32_t dst, const void* src, bool pred) {
    int sz = pred ? 16 : 0;
    asm volatile("cp.async.cg.shared.global [%0], [%1], 16, %2;"
                 :: "r"(dst), "l"(src), "r"(sz) : "memory");
}
__device__ __forceinline__ uint32_t pkh(__half a, __half b) {
    __half2 t = __halves2half2(a, b);
    return *reinterpret_cast<uint32_t*>(&t);
}
__device__ __forceinline__ uint2 h4(float4 v) {
    return make_uint2(pkh(__float2half_rn(v.x), __float2half_rn(v.y)),
                      pkh(__float2half_rn(v.z), __float2half_rn(v.w)));
}
__device__ __forceinline__ float4 f4ofh(uint2 u) {
    __half2* h2 = (__half2*)&u;
    float2 a = __half22float2(h2[0]);
    float2 b = __half22float2(h2[1]);
    return make_float4(a.x, a.y, b.x, b.y);
}
__device__ __forceinline__ float tanha(float x) {
    float y;
    asm("tanh.approx.f32 %0, %1;" : "=f"(y) : "f"(x));
    return y;
}

// ---------------------------------------------------------------------------
__global__ void zero_int(int* __restrict__ p, int n) {
    int i = blockIdx.x * blockDim.x + threadIdx.x;
    if (i < n) p[i] = 0;
}

// ---------------------------------------------------------------------------
// e0h = fp16(l2norm(ent)); egh = fp16(l2norm(ent)*g0).  Warp per row.
// ---------------------------------------------------------------------------
__global__ void normalize_split(const float* __restrict__ in, const float* __restrict__ g0,
                                __half* __restrict__ e0h, __half* __restrict__ egh,
                                int M, int D) {
    int warp = (blockIdx.x * blockDim.x + threadIdx.x) >> 5;
    int lane = threadIdx.x & 31;
    if (warp >= M) return;
    const float4* ip = (const float4*)(in + (size_t)warp * D);
    const float4* gp = (const float4*)g0;
    int nv = D >> 2;
    float s = 0.f;
    for (int i = lane; i < nv; i += 32) {
        float4 v = ip[i];
        s += v.x * v.x + v.y * v.y + v.z * v.z + v.w * v.w;
    }
    #pragma unroll
    for (int o = 16; o; o >>= 1) s += __shfl_xor_sync(0xFFFFFFFFu, s, o);
    float inv = 1.f / fmaxf(sqrtf(s), 1e-12f);
    size_t rbase = (size_t)warp * D;
    for (int i = lane; i < nv; i += 32) {
        float4 v = ip[i];
        float4 n = make_float4(v.x * inv, v.y * inv, v.z * inv, v.w * inv);
        *(uint2*)(e0h + rbase + i * 4) = h4(n);
        float4 g = gp[i];
        *(uint2*)(egh + rbase + i * 4) =
            h4(make_float4(n.x * g.x, n.y * g.y, n.z * g.z, n.w * g.w));
    }
}

// ---------------------------------------------------------------------------
// Edge operand in CSR order: row j = e0h[dst[eidx[j]]] * relh[edge[eidx[j]]].
// ---------------------------------------------------------------------------
__global__ void split_edge(const __half* __restrict__ e0h, const __half* __restrict__ relh,
                           const int* __restrict__ dsts, const int* __restrict__ edges,
                           const int* __restrict__ eidx,
                           __half* __restrict__ eh, int E, int D) {
    int warp = (blockIdx.x * blockDim.x + threadIdx.x) >> 5;
    int lane = threadIdx.x & 31;
    if (warp >= E) return;
    int e = eidx[warp];
    int dst = dsts[e];
    int rl = edges[e];
    const uint2* ap = (const uint2*)(e0h + (size_t)dst * D);
    const uint2* gp = (const uint2*)(relh + (size_t)rl * D);
    uint2* op = (uint2*)(eh + (size_t)warp * D);
    int nv = D >> 2;
    for (int i = lane; i < nv; i += 32) {
        uint2 a = ap[i], g = gp[i];
        __half2* ah = (__half2*)&a;
        __half2* gh = (__half2*)&g;
        uint2 r;
        __half2* rh = (__half2*)&r;
        rh[0] = __hmul2(ah[0], gh[0]);
        rh[1] = __hmul2(ah[1], gh[1]);
        op[i] = r;
    }
}

// ---------------------------------------------------------------------------
// Weight + relation fp16 conversion: W1 as-is ([N,K]); WE transposed; rel.
// ---------------------------------------------------------------------------
__global__ void split_weights(const float* __restrict__ W1, const float* __restrict__ WE,
                              const float* __restrict__ rel,
                              __half* __restrict__ w1h, __half* __restrict__ weth,
                              __half* __restrict__ relh, int D, int RD) {
    int i = blockIdx.x * blockDim.x + threadIdx.x;
    int tot = D * D;
    if (i < tot) {
        w1h[i] = __float2half_rn(W1[i]);
        int k = i / D, j = i % D;
        weth[(size_t)j * D + k] = __float2half_rn(WE[i]);
    }
    if (i < RD) relh[i] = __float2half_rn(rel[i]);
}

// ---------------------------------------------------------------------------
// CSR build
// ---------------------------------------------------------------------------
__global__ void count_deg(const int* __restrict__ srcs, int* __restrict__ cnt, int E) {
    int e = blockIdx.x * blockDim.x + threadIdx.x;
    if (e < E) atomicAdd(&cnt[srcs[e]], 1);
}
__global__ void scan1(const int* __restrict__ cnt, int* __restrict__ off,
                      int* __restrict__ bsum, int N) {
    __shared__ int sm[1024];
    int tid = threadIdx.x;
    int i = blockIdx.x * 1024 + tid;
    int v = (i < N) ? cnt[i] : 0;
    sm[tid] = v;
    __syncthreads();
    #pragma unroll
    for (int d = 1; d < 1024; d <<= 1) {
        int t = (tid >= d) ? sm[tid - d] : 0;
        __syncthreads();
        sm[tid] += t;
        __syncthreads();
    }
    if (i < N) off[i] = sm[tid] - v;
    if (tid == 1023) bsum[blockIdx.x] = sm[1023];
}
// merged scan of block sums + offset fixup + cur init (replaces scan2+scan3)
__global__ void scan3b(int* __restrict__ off, int* __restrict__ cur,
                       const int* __restrict__ bsum, int nblk, int N, int E) {
    __shared__ int sb[128];
    int tid = threadIdx.x;
    if (tid < 128) sb[tid] = (tid < nblk) ? bsum[tid] : 0;
    __syncthreads();
    #pragma unroll
    for (int d = 1; d < 128; d <<= 1) {
        int t = (tid < 128 && tid >= d) ? sb[tid - d] : 0;
        __syncthreads();
        if (tid < 128) sb[tid] += t;
        __syncthreads();
    }
    int i = blockIdx.x * blockDim.x + tid;
    if (i < N) {
        int bi = i >> 10;
        int pre = (bi == 0) ? 0 : sb[bi - 1];
        int o = off[i] + pre;
        off[i] = o;
        cur[i] = o;
    }
    if (i == 0) off[N] = E;
}
__global__ void fill_eidx(const int* __restrict__ srcs, int* __restrict__ cur,
                          int* __restrict__ eidx, int E) {
    int e = blockIdx.x * blockDim.x + threadIdx.x;
    if (e < E) {
        int pos = atomicAdd(&cur[srcs[e]], 1);
        eidx[pos] = e;
    }
}

// ---------------------------------------------------------------------------
// Fused node aggregation (warp per node).  Ce rows are CSR-contiguous;
// edge loop software-pipelined (prefetch row j+1 during row j's reduce).
// ---------------------------------------------------------------------------
__global__ void node_aggregate(const __half* __restrict__ e0h, const __half* __restrict__ Cbh,
                               const __half* __restrict__ Ceh, const float* __restrict__ Epre,
                               const float* __restrict__ Wa,
                               const int* __restrict__ off,
                               float* __restrict__ entnew, int N, int D) {
    __shared__ float waS[512];
    for (int i = threadIdx.x; i < D; i += blockDim.x) waS[i] = Wa[i];
    __syncthreads();

    int warp = (blockIdx.x * blockDim.x + threadIdx.x) >> 5;
    int lane = threadIdx.x & 31;
    if (warp >= N) return;
    int o0 = off[warp], o1 = off[warp + 1];
    int deg = o1 - o0;

    const uint2* ep = (const uint2*)(e0h + (size_t)warp * D);
    const uint2* cbp = (const uint2*)(Cbh + (size_t)warp * D);
    const float4* wp = (const float4*)waS;

    float4 ew[4], acc[4];
    float sb = 0.f;
    #pragma unroll
    for (int i = 0; i < 4; i++) {
        int ii = lane + i * 32;
        float4 e = f4ofh(ep[ii]);
        float4 w = wp[ii];
        ew[i] = make_float4(e.x * w.x, e.y * w.y, e.z * w.z, e.w * w.w);
        float4 c = f4ofh(cbp[ii]);
        acc[i] = c;
        sb += ew[i].x * tanha(c.x) + ew[i].y * tanha(c.y) +
              ew[i].z * tanha(c.z) + ew[i].w * tanha(c.w);
    }
    #pragma unroll
    for (int o = 16; o; o >>= 1) sb += __shfl_xor_sync(0xFFFFFFFFu, sb, o);
    float lb = sb > 0.f ? sb : 0.2f * sb;
    float ab = expf(-lb);
    float coef = (deg > 0) ? ab : 0.f;
    float den = coef;
    #pragma unroll
    for (int i = 0; i < 4; i++) {
        acc[i].x *= coef; acc[i].y *= coef; acc[i].z *= coef; acc[i].w *= coef;
    }

    // pipelined edge loop over contiguous rows [o0, o1)
    uint2 nxt[4];
    if (deg > 0) {
        const uint2* cp = (const uint2*)(Ceh + (size_t)o0 * D);
        #pragma unroll
        for (int i = 0; i < 4; i++) nxt[i] = cp[lane + i * 32];
    }
    for (int j = o0; j < o1; j++) {
        uint2 cur4[4];
        #pragma unroll
        for (int i = 0; i < 4; i++) cur4[i] = nxt[i];
        if (j + 1 < o1) {
            const uint2* cp = (const uint2*)(Ceh + (size_t)(j + 1) * D);
            #pragma unroll
            for (int i = 0; i < 4; i++) nxt[i] = cp[lane + i * 32];
        }
        float4 cv[4];
        float s = 0.f;
        #pragma unroll
        for (int i = 0; i < 4; i++) {
            float4 c = f4ofh(cur4[i]);
            cv[i] = c;
            s += ew[i].x * tanha(c.x) + ew[i].y * tanha(c.y) +
                 ew[i].z * tanha(c.z) + ew[i].w * tanha(c.w);
        }
        #pragma unroll
        for (int o = 16; o; o >>= 1) s += __shfl_xor_sync(0xFFFFFFFFu, s, o);
        float l = s > 0.f ? s : 0.2f * s;
        float aexp = expf(-l);
        den += aexp;
        #pragma unroll
        for (int i = 0; i < 4; i++) {
            acc[i].x = fmaf(aexp, cv[i].x, acc[i].x);
            acc[i].y = fmaf(aexp, cv[i].y, acc[i].y);
            acc[i].z = fmaf(aexp, cv[i].z, acc[i].z);
            acc[i].w = fmaf(aexp, cv[i].w, acc[i].w);
        }
    }

    if (den == 0.f) den = 1e-12f;
    float invden = 1.f / den;
    const float4* epp = (const float4*)(Epre + (size_t)warp * D);
    float4* op = (float4*)(entnew + (size_t)warp * D);
    float nrm = 0.f;
    float4 tv[4];
    #pragma unroll
    for (int i = 0; i < 4; i++) {
        int ii = lane + i * 32;
        float4 ep4 = epp[ii];
        float4 t;
        float x = acc[i].x * invden; t.x = ep4.x + (x > 0.f ? x : expm1f(x));
        x = acc[i].y * invden;       t.y = ep4.y + (x > 0.f ? x : expm1f(x));
        x = acc[i].z * invden;       t.z = ep4.z + (x > 0.f ? x : expm1f(x));
        x = acc[i].w * invden;       t.w = ep4.w + (x > 0.f ? x : expm1f(x));
        tv[i] = t;
        nrm += t.x * t.x + t.y * t.y + t.z * t.z + t.w * t.w;
    }
    #pragma unroll
    for (int o = 16; o; o >>= 1) nrm += __shfl_xor_sync(0xFFFFFFFFu, nrm, o);
    float inv = 1.f / fmaxf(sqrtf(nrm), 1e-12f);
    #pragma unroll
    for (int i = 0; i < 4; i++) {
        int ii = lane + i * 32;
        float4 t = tv[i];
        op[ii] = make_float4(t.x * inv, t.y * inv, t.z * inv, t.w * inv);
    }
}

// ---------------------------------------------------------------------------
// mma.sync fp16 GEMM (single pass): C[M,D] = A @ W^T,  W stored [N,K].
// HOUT: write fp16 C (Cbase/Cedge) vs fp32 (Epre).
// ---------------------------------------------------------------------------
#define MM_BM 128
#define MM_BN 256
#define MM_BK 32
#define MM_LD 40
#define MM_STAGES 4
static constexpr int MM_AH = 0;
static constexpr int MM_BH = 128 * MM_LD;
static constexpr int MM_STAGE_H = 15360;
static constexpr int MM_STAGE_BYTES = MM_STAGE_H * 2;
static constexpr int MM_SMEM_BYTES = MM_STAGES * MM_STAGE_BYTES;

template<bool HOUT>
__global__ void __launch_bounds__(512, 1)
gemm_mma_kernel(const __half* __restrict__ A, const __half* __restrict__ Bh,
                void* __restrict__ Cv, int M, int D) {
    extern __shared__ __half sh[];
    uint32_t sbase = smem_to_u32(sh);
    int tid = threadIdx.x;
    int lane = tid & 31;
    int warp = tid >> 5;
    int mb = blockIdx.x * MM_BM;
    int nb = blockIdx.y * MM_BN;
    int wm = (warp >> 2) * 32;
    int wn = (warp & 3) * 64;
    const int nch = D / MM_BK;

    float acc[2][8][4];
    #pragma unroll
    for (int i = 0; i < 2; i++)
        #pragma unroll
        for (int j = 0; j < 8; j++)
            #pragma unroll
            for (int q = 0; q < 4; q++) acc[i][j][q] = 0.f;

    int arow = tid >> 2;
    int achk = (tid & 3) * 8;
    int gma = mb + arow;
    bool apred = gma < M;
    size_t abase = (size_t)(apred ? gma : 0) * D + achk;

    auto stage_load = [&](int ch) {
        if (ch < nch) {
            int kb = ch * MM_BK;
            uint32_t st = sbase + (ch % MM_STAGES) * MM_STAGE_BYTES;
            cp16(st + (MM_AH + arow * MM_LD + achk) * 2, A + abase + kb, apred);
            #pragma unroll
            for (int i = 0; i < 2; i++) {
                int idx = tid + i * 512;
                int row = idx >> 2;
                int chk = (idx & 3) * 8;
                size_t go = (size_t)(nb + row) * D + kb + chk;
                cp16(st + (MM_BH + row * MM_LD + chk) * 2, Bh + go, true);
            }
        }
        asm volatile("cp.async.commit_group;" ::: "memory");
    };

    stage_load(0);
    stage_load(1);
    stage_load(2);

    int a_r = (lane & 15);
    int a_c = (lane >> 4) << 3;
    int b_r = (lane & 7) + ((lane & 16) >> 1);
    int b_c = (lane & 8);

    for (int ch = 0; ch < nch; ch++) {
        asm volatile("cp.async.wait_group 2;" ::: "memory");
        __syncthreads();
        stage_load(ch + 3);

        uint32_t stb = sbase + (ch % MM_STAGES) * MM_STAGE_BYTES;
        #pragma unroll
        for (int s16 = 0; s16 < 2; s16++) {
            int k0 = s16 * 16;
            uint32_t ah[2][4], bh[8][2];
            #pragma unroll
            for (int mi = 0; mi < 2; mi++) {
                uint32_t addr = stb + (MM_AH + (wm + mi * 16 + a_r) * MM_LD + k0 + a_c) * 2;
                ldsm4(addr, ah[mi][0], ah[mi][1], ah[mi][2], ah[mi][3]);
            }
            #pragma unroll
            for (int nj = 0; nj < 4; nj++) {
                uint32_t addr = stb + (MM_BH + (wn + nj * 16 + b_r) * MM_LD + k0 + b_c) * 2;
                ldsm4(addr, bh[2 * nj][0], bh[2 * nj][1], bh[2 * nj + 1][0], bh[2 * nj + 1][1]);
            }
            #pragma unroll
            for (int mi = 0; mi < 2; mi++)
                #pragma unroll
                for (int nj = 0; nj < 8; nj++) mma_fp16(acc[mi][nj], ah[mi], bh[nj]);
        }
        __syncthreads();
    }

    #pragma unroll
    for (int mi = 0; mi < 2; mi++) {
        int gm0 = mb + wm + mi * 16 + (lane >> 2);
        int gm1 = gm0 + 8;
        #pragma unroll
        for (int nj = 0; nj < 8; nj++) {
            int gn = nb + wn + nj * 8 + (lane & 3) * 2;
            if (HOUT) {
                __half* C = (__half*)Cv;
                if (gm0 < M)
                    *(uint32_t*)(C + (size_t)gm0 * D + gn) =
                        pkh(__float2half_rn(acc[mi][nj][0]), __float2half_rn(acc[mi][nj][1]));
                if (gm1 < M)
                    *(uint32_t*)(C + (size_t)gm1 * D + gn) =
                        pkh(__float2half_rn(acc[mi][nj][2]), __float2half_rn(acc[mi][nj][3]));
            } else {
                float* C = (float*)Cv;
                if (gm0 < M)
                    *(float2*)(C + (size_t)gm0 * D + gn) = make_float2(acc[mi][nj][0], acc[mi][nj][1]);
                if (gm1 < M)
                    *(float2*)(C + (size_t)gm1 * D + gn) = make_float2(acc[mi][nj][2], acc[mi][nj][3]);
            }
        }
    }
}

// ---------------------------------------------------------------------------
// fp32 tiled SGEMM (tiny rel_new GEMM, R=500)
// ---------------------------------------------------------------------------
__global__ void gemm128_plain(const float* __restrict__ A0, const float* __restrict__ W,
                              float* __restrict__ C, int M, int D) {
    constexpr int BM = 128, BN = 128, BK = 16;
    __shared__ float As[BK][BM];
    __shared__ float Bs[BK][BN];
    int tid = threadIdx.x;
    int mb = blockIdx.x * BM;
    int nb = blockIdx.y * BN;
    int tx = tid & 15, ty = tid >> 4;
    float acc[8][8];
    #pragma unroll
    for (int i = 0; i < 8; i++)
        #pragma unroll
        for (int j = 0; j < 8; j++) acc[i][j] = 0.f;
    for (int kb = 0; kb < D; kb += BK) {
        #pragma unroll
        for (int i = 0; i < 2; i++) {
            int q = tid + i * 256;
            int row = q >> 2;
            int kc = (q & 3) << 2;
            int gr = mb + row;
            float4 v = make_float4(0.f, 0.f, 0.f, 0.f);
            if (gr < M) v = *(const float4*)(A0 + (size_t)gr * D + kb + kc);
            As[kc + 0][row] = v.x; As[kc + 1][row] = v.y;
            As[kc + 2][row] = v.z; As[kc + 3][row] = v.w;
        }
        #pragma unroll
        for (int i = 0; i < 2; i++) {
            int q = tid + i * 256;
            int kr = q >> 5;
            int jc = (q & 31) << 2;
            *(float4*)&Bs[kr][jc] = *(const float4*)(W + (size_t)(kb + kr) * D + nb + jc);
        }
        __syncthreads();
        #pragma unroll
        for (int k = 0; k < BK; k++) {
            float a[8], b[8];
            *(float4*)&a[0] = *(const float4*)&As[k][ty * 8];
            *(float4*)&a[4] = *(const float4*)&As[k][ty * 8 + 4];
            *(float4*)&b[0] = *(const float4*)&Bs[k][tx * 8];
            *(float4*)&b[4] = *(const float4*)&Bs[k][tx * 8 + 4];
            #pragma unroll
            for (int i = 0; i < 8; i++)
                #pragma unroll
                for (int j = 0; j < 8; j++)
                    acc[i][j] = fmaf(a[i], b[j], acc[i][j]);
        }
        __syncthreads();
    }
    #pragma unroll
    for (int i = 0; i < 8; i++) {
        int gr = mb + ty * 8 + i;
        if (gr < M) {
            float* cp = C + (size_t)gr * D + nb + tx * 8;
            *(float4*)(cp + 0) = make_float4(acc[i][0], acc[i][1], acc[i][2], acc[i][3]);
            *(float4*)(cp + 4) = make_float4(acc[i][4], acc[i][5], acc[i][6], acc[i][7]);
        }
    }
}

// ---------------------------------------------------------------------------
// Final gather
// ---------------------------------------------------------------------------
__global__ void gather_out(const int* __restrict__ triples, const float* __restrict__ entn,
                           const float* __restrict__ reln, float4* __restrict__ out,
                           int B, int D) {
    int nv = D >> 2;
    int total = B * 3 * nv;
    int i = blockIdx.x * blockDim.x + threadIdx.x;
    int stride = gridDim.x * blockDim.x;
    for (; i < total; i += stride) {
        int d4 = i % nv;
        int bt = i / nv;
        int t = bt % 3;
        int b = bt / 3;
        int idx = triples[b * 3 + t];
        const float4* srcp = (t == 1) ? (const float4*)(reln + (size_t)idx * D)
                                      : (const float4*)(entn + (size_t)idx * D);
        out[i] = srcp[d4];
    }
}

// ---------------------------------------------------------------------------
// Launch
// ---------------------------------------------------------------------------
extern "C" void kernel_launch(void* const* d_in, const int* in_sizes, int n_in,
                              void* d_out, int out_size) {
    const int*   triples  = (const int*)d_in[0];
    const int*   nodelist = (const int*)d_in[1];
    const int*   edgelist = (const int*)d_in[2];
    const float* ent      = (const float*)d_in[3];
    const float* rel      = (const float*)d_in[4];
    const float* W1       = (const float*)d_in[5];
    const float* Wa       = (const float*)d_in[6];
    const float* g0       = (const float*)d_in[7];
    const float* WE       = (const float*)d_in[8];
    const float* WR       = (const float*)d_in[9];

    int B = in_sizes[0] / 3;
    int E = in_sizes[2];
    int D = in_sizes[6];
    int N = in_sizes[3] / D;
    int R = in_sizes[4] / D;

    float *entn, *Epre, *reln;
    int *cnt, *off, *cur, *eidx, *bsum;
    __half *Cbaseh, *Cedgeh, *e0h, *egh, *edh, *relh, *w1h, *weth;
    cudaGetSymbolAddress((void**)&entn,   g_entn);
    cudaGetSymbolAddress((void**)&Epre,   g_Epre);
    cudaGetSymbolAddress((void**)&reln,   g_reln);
    cudaGetSymbolAddress((void**)&Cbaseh, g_Cbaseh);
    cudaGetSymbolAddress((void**)&Cedgeh, g_Cedgeh);
    cudaGetSymbolAddress((void**)&cnt,    g_cnt);
    cudaGetSymbolAddress((void**)&off,    g_off);
    cudaGetSymbolAddress((void**)&cur,    g_cur);
    cudaGetSymbolAddress((void**)&eidx,   g_eidx);
    cudaGetSymbolAddress((void**)&bsum,   g_bsum);
    cudaGetSymbolAddress((void**)&e0h,    g_e0h);
    cudaGetSymbolAddress((void**)&egh,    g_egh);
    cudaGetSymbolAddress((void**)&edh,    g_edh);
    cudaGetSymbolAddress((void**)&relh,   g_relh);
    cudaGetSymbolAddress((void**)&w1h,    g_w1h);
    cudaGetSymbolAddress((void**)&weth,   g_weth);

    cudaFuncSetAttribute(gemm_mma_kernel<true>,
                         cudaFuncAttributeMaxDynamicSharedMemorySize, MM_SMEM_BYTES);
    cudaFuncSetAttribute(gemm_mma_kernel<false>,
                         cudaFuncAttributeMaxDynamicSharedMemorySize, MM_SMEM_BYTES);

    int nblk = (N + 1023) / 1024;
    dim3 gN((N + MM_BM - 1) / MM_BM, D / MM_BN);
    dim3 gE2((E + MM_BM - 1) / MM_BM, D / MM_BN);

    // launch order arranged so the 6th launch is a big GEMM (ncu -s 5 -c 1)
    normalize_split<<<(N + 7) / 8, 256>>>(ent, g0, e0h, egh, N, D);          // 1
    split_weights<<<(D * D + 255) / 256, 256>>>(W1, WE, rel, w1h, weth, relh, D, R * D); // 2
    zero_int<<<(N + 255) / 256, 256>>>(cnt, N);                              // 3
    count_deg<<<(E + 255) / 256, 256>>>(nodelist, cnt, E);                   // 4
    scan1<<<nblk, 1024>>>(cnt, off, bsum, N);                                // 5
    gemm_mma_kernel<true><<<gN, 512, MM_SMEM_BYTES>>>(egh, w1h, Cbaseh, N, D); // 6 <- profiled
    scan3b<<<(N + 255) / 256, 256>>>(off, cur, bsum, nblk, N, E);            // 7
    fill_eidx<<<(E + 255) / 256, 256>>>(nodelist, cur, eidx, E);             // 8
    split_edge<<<(E + 7) / 8, 256>>>(e0h, relh, nodelist + E, edgelist, eidx, edh, E, D); // 9
    gemm_mma_kernel<true><<<gE2, 512, MM_SMEM_BYTES>>>(edh, w1h, Cedgeh, E, D); // 10
    gemm_mma_kernel<false><<<gN, 512, MM_SMEM_BYTES>>>(e0h, weth, Epre, N, D);  // 11
    node_aggregate<<<(N + 7) / 8, 256>>>(e0h, Cbaseh, Cedgeh, Epre, Wa, off, entn, N, D); // 12
    dim3 gR((R + 127) / 128, D / 128);
    gemm128_plain<<<gR, 256>>>(rel, WR, reln, R, D);                         // 13
    int total4 = B * 3 * (D >> 2);
    gather_out<<<(total4 + 255) / 256, 256>>>(triples, entn, reln, (float4*)d_out, B, D); // 14
}

// round 11
// speedup vs baseline: 5.1205x; 1.0851x over previous
#include <cuda_runtime.h>
#include <cuda_fp16.h>
#include <math.h>
#include <stdint.h>

// ---------------------------------------------------------------------------
// UPGAT layer.  N=100000, R=500, D=512, E=150000, B=4096.
// GEMMs: fp16 single-pass mma.sync (fp32 acc); Cbase/Cedge stored fp16.
// Cedge materialized in CSR order.  2-stream fork-join overlap (capture-safe).
// ---------------------------------------------------------------------------

#define MAX_N 100000
#define MAX_E 150000
#define MAX_R 500
#define MAX_D 512

__device__ float g_entn [(size_t)MAX_N * MAX_D];
__device__ float g_Epre [(size_t)MAX_N * MAX_D];
__device__ float g_reln [(size_t)MAX_R * MAX_D];

__device__ __half g_Cbaseh[(size_t)MAX_N * MAX_D];
__device__ __half g_Cedgeh[(size_t)MAX_E * MAX_D];

__device__ int g_cnt [MAX_N];
__device__ int g_off [MAX_N + 1];
__device__ int g_cur [MAX_N];
__device__ int g_eidx[MAX_E];
__device__ int g_bsum[128];

__device__ __half g_e0h[(size_t)MAX_N * MAX_D];
__device__ __half g_egh[(size_t)MAX_N * MAX_D];
__device__ __half g_edh[(size_t)MAX_E * MAX_D];
__device__ __half g_relh[(size_t)MAX_R * MAX_D];
__device__ __half g_w1h[MAX_D * MAX_D];
__device__ __half g_weth[MAX_D * MAX_D];

// ---------------------------------------------------------------------------
// helpers
// ---------------------------------------------------------------------------
__device__ __forceinline__ uint32_t smem_to_u32(const void* smem_ptr) {
    uint32_t addr;
    asm("{ .reg .u64 tmp; cvta.to.shared.u64 tmp, %1; cvt.u32.u64 %0, tmp; }"
        : "=r"(addr) : "l"(smem_ptr));
    return addr;
}
__device__ __forceinline__ void ldsm4(uint32_t addr, uint32_t& r0, uint32_t& r1,
                                      uint32_t& r2, uint32_t& r3) {
    asm volatile("ldmatrix.sync.aligned.m8n8.x4.shared.b16 {%0,%1,%2,%3}, [%4];"
                 : "=r"(r0), "=r"(r1), "=r"(r2), "=r"(r3) : "r"(addr));
}
__device__ __forceinline__ void mma_fp16(float* d, const uint32_t* a, const uint32_t* b) {
    asm volatile(
        "mma.sync.aligned.m16n8k16.row.col.f32.f16.f16.f32 "
        "{%0,%1,%2,%3}, {%4,%5,%6,%7}, {%8,%9}, {%0,%1,%2,%3};"
        : "+f"(d[0]), "+f"(d[1]), "+f"(d[2]), "+f"(d[3])
        : "r"(a[0]), "r"(a[1]), "r"(a[2]), "r"(a[3]), "r"(b[0]), "r"(b[1]));
}
__device__ __forceinline__ void cp16(uint32_t dst, const void* src, bool pred) {
    int sz = pred ? 16 : 0;
    asm volatile("cp.async.cg.shared.global [%0], [%1], 16, %2;"
                 :: "r"(dst), "l"(src), "r"(sz) : "memory");
}
__device__ __forceinline__ uint32_t pkh(__half a, __half b) {
    __half2 t = __halves2half2(a, b);
    return *reinterpret_cast<uint32_t*>(&t);
}
__device__ __forceinline__ uint2 h4(float4 v) {
    return make_uint2(pkh(__float2half_rn(v.x), __float2half_rn(v.y)),
                      pkh(__float2half_rn(v.z), __float2half_rn(v.w)));
}
__device__ __forceinline__ float4 f4ofh(uint2 u) {
    __half2* h2 = (__half2*)&u;
    float2 a = __half22float2(h2[0]);
    float2 b = __half22float2(h2[1]);
    return make_float4(a.x, a.y, b.x, b.y);
}
__device__ __forceinline__ float tanha(float x) {
    float y;
    asm("tanh.approx.f32 %0, %1;" : "=f"(y) : "f"(x));
    return y;
}

// ---------------------------------------------------------------------------
__global__ void zero_int(int* __restrict__ p, int n) {
    int i = blockIdx.x * blockDim.x + threadIdx.x;
    if (i < n) p[i] = 0;
}

__global__ void normalize_split(const float* __restrict__ in, const float* __restrict__ g0,
                                __half* __restrict__ e0h, __half* __restrict__ egh,
                                int M, int D) {
    int warp = (blockIdx.x * blockDim.x + threadIdx.x) >> 5;
    int lane = threadIdx.x & 31;
    if (warp >= M) return;
    const float4* ip = (const float4*)(in + (size_t)warp * D);
    const float4* gp = (const float4*)g0;
    int nv = D >> 2;
    float s = 0.f;
    for (int i = lane; i < nv; i += 32) {
        float4 v = ip[i];
        s += v.x * v.x + v.y * v.y + v.z * v.z + v.w * v.w;
    }
    #pragma unroll
    for (int o = 16; o; o >>= 1) s += __shfl_xor_sync(0xFFFFFFFFu, s, o);
    float inv = 1.f / fmaxf(sqrtf(s), 1e-12f);
    size_t rbase = (size_t)warp * D;
    for (int i = lane; i < nv; i += 32) {
        float4 v = ip[i];
        float4 n = make_float4(v.x * inv, v.y * inv, v.z * inv, v.w * inv);
        *(uint2*)(e0h + rbase + i * 4) = h4(n);
        float4 g = gp[i];
        *(uint2*)(egh + rbase + i * 4) =
            h4(make_float4(n.x * g.x, n.y * g.y, n.z * g.z, n.w * g.w));
    }
}

__global__ void split_edge(const __half* __restrict__ e0h, const __half* __restrict__ relh,
                           const int* __restrict__ dsts, const int* __restrict__ edges,
                           const int* __restrict__ eidx,
                           __half* __restrict__ eh, int E, int D) {
    int warp = (blockIdx.x * blockDim.x + threadIdx.x) >> 5;
    int lane = threadIdx.x & 31;
    if (warp >= E) return;
    int e = eidx[warp];
    int dst = dsts[e];
    int rl = edges[e];
    const uint2* ap = (const uint2*)(e0h + (size_t)dst * D);
    const uint2* gp = (const uint2*)(relh + (size_t)rl * D);
    uint2* op = (uint2*)(eh + (size_t)warp * D);
    int nv = D >> 2;
    for (int i = lane; i < nv; i += 32) {
        uint2 a = ap[i], g = gp[i];
        __half2* ah = (__half2*)&a;
        __half2* gh = (__half2*)&g;
        uint2 r;
        __half2* rh = (__half2*)&r;
        rh[0] = __hmul2(ah[0], gh[0]);
        rh[1] = __hmul2(ah[1], gh[1]);
        op[i] = r;
    }
}

__global__ void split_weights(const float* __restrict__ W1, const float* __restrict__ WE,
                              const float* __restrict__ rel,
                              __half* __restrict__ w1h, __half* __restrict__ weth,
                              __half* __restrict__ relh, int D, int RD) {
    int i = blockIdx.x * blockDim.x + threadIdx.x;
    int tot = D * D;
    if (i < tot) {
        w1h[i] = __float2half_rn(W1[i]);
        int k = i / D, j = i % D;
        weth[(size_t)j * D + k] = __float2half_rn(WE[i]);
    }
    if (i < RD) relh[i] = __float2half_rn(rel[i]);
}

__global__ void count_deg(const int* __restrict__ srcs, int* __restrict__ cnt, int E) {
    int e = blockIdx.x * blockDim.x + threadIdx.x;
    if (e < E) atomicAdd(&cnt[srcs[e]], 1);
}
__global__ void scan1(const int* __restrict__ cnt, int* __restrict__ off,
                      int* __restrict__ bsum, int N) {
    __shared__ int sm[1024];
    int tid = threadIdx.x;
    int i = blockIdx.x * 1024 + tid;
    int v = (i < N) ? cnt[i] : 0;
    sm[tid] = v;
    __syncthreads();
    #pragma unroll
    for (int d = 1; d < 1024; d <<= 1) {
        int t = (tid >= d) ? sm[tid - d] : 0;
        __syncthreads();
        sm[tid] += t;
        __syncthreads();
    }
    if (i < N) off[i] = sm[tid] - v;
    if (tid == 1023) bsum[blockIdx.x] = sm[1023];
}
__global__ void scan3b(int* __restrict__ off, int* __restrict__ cur,
                       const int* __restrict__ bsum, int nblk, int N, int E) {
    __shared__ int sb[128];
    int tid = threadIdx.x;
    if (tid < 128) sb[tid] = (tid < nblk) ? bsum[tid] : 0;
    __syncthreads();
    #pragma unroll
    for (int d = 1; d < 128; d <<= 1) {
        int t = (tid < 128 && tid >= d) ? sb[tid - d] : 0;
        __syncthreads();
        if (tid < 128) sb[tid] += t;
        __syncthreads();
    }
    int i = blockIdx.x * blockDim.x + tid;
    if (i < N) {
        int bi = i >> 10;
        int pre = (bi == 0) ? 0 : sb[bi - 1];
        int o = off[i] + pre;
        off[i] = o;
        cur[i] = o;
    }
    if (i == 0) off[N] = E;
}
__global__ void fill_eidx(const int* __restrict__ srcs, int* __restrict__ cur,
                          int* __restrict__ eidx, int E) {
    int e = blockIdx.x * blockDim.x + threadIdx.x;
    if (e < E) {
        int pos = atomicAdd(&cur[srcs[e]], 1);
        eidx[pos] = e;
    }
}

__global__ void node_aggregate(const __half* __restrict__ e0h, const __half* __restrict__ Cbh,
                               const __half* __restrict__ Ceh, const float* __restrict__ Epre,
                               const float* __restrict__ Wa,
                               const int* __restrict__ off,
                               float* __restrict__ entnew, int N, int D) {
    __shared__ float waS[512];
    for (int i = threadIdx.x; i < D; i += blockDim.x) waS[i] = Wa[i];
    __syncthreads();

    int warp = (blockIdx.x * blockDim.x + threadIdx.x) >> 5;
    int lane = threadIdx.x & 31;
    if (warp >= N) return;
    int o0 = off[warp], o1 = off[warp + 1];
    int deg = o1 - o0;

    const uint2* ep = (const uint2*)(e0h + (size_t)warp * D);
    const uint2* cbp = (const uint2*)(Cbh + (size_t)warp * D);
    const float4* wp = (const float4*)waS;

    float4 ew[4], acc[4];
    float sb = 0.f;
    #pragma unroll
    for (int i = 0; i < 4; i++) {
        int ii = lane + i * 32;
        float4 e = f4ofh(ep[ii]);
        float4 w = wp[ii];
        ew[i] = make_float4(e.x * w.x, e.y * w.y, e.z * w.z, e.w * w.w);
        float4 c = f4ofh(cbp[ii]);
        acc[i] = c;
        sb += ew[i].x * tanha(c.x) + ew[i].y * tanha(c.y) +
              ew[i].z * tanha(c.z) + ew[i].w * tanha(c.w);
    }
    #pragma unroll
    for (int o = 16; o; o >>= 1) sb += __shfl_xor_sync(0xFFFFFFFFu, sb, o);
    float lb = sb > 0.f ? sb : 0.2f * sb;
    float ab = expf(-lb);
    float coef = (deg > 0) ? ab : 0.f;
    float den = coef;
    #pragma unroll
    for (int i = 0; i < 4; i++) {
        acc[i].x *= coef; acc[i].y *= coef; acc[i].z *= coef; acc[i].w *= coef;
    }

    uint2 nxt[4];
    if (deg > 0) {
        const uint2* cp = (const uint2*)(Ceh + (size_t)o0 * D);
        #pragma unroll
        for (int i = 0; i < 4; i++) nxt[i] = cp[lane + i * 32];
    }
    for (int j = o0; j < o1; j++) {
        uint2 cur4[4];
        #pragma unroll
        for (int i = 0; i < 4; i++) cur4[i] = nxt[i];
        if (j + 1 < o1) {
            const uint2* cp = (const uint2*)(Ceh + (size_t)(j + 1) * D);
            #pragma unroll
            for (int i = 0; i < 4; i++) nxt[i] = cp[lane + i * 32];
        }
        float4 cv[4];
        float s = 0.f;
        #pragma unroll
        for (int i = 0; i < 4; i++) {
            float4 c = f4ofh(cur4[i]);
            cv[i] = c;
            s += ew[i].x * tanha(c.x) + ew[i].y * tanha(c.y) +
                 ew[i].z * tanha(c.z) + ew[i].w * tanha(c.w);
        }
        #pragma unroll
        for (int o = 16; o; o >>= 1) s += __shfl_xor_sync(0xFFFFFFFFu, s, o);
        float l = s > 0.f ? s : 0.2f * s;
        float aexp = expf(-l);
        den += aexp;
        #pragma unroll
        for (int i = 0; i < 4; i++) {
            acc[i].x = fmaf(aexp, cv[i].x, acc[i].x);
            acc[i].y = fmaf(aexp, cv[i].y, acc[i].y);
            acc[i].z = fmaf(aexp, cv[i].z, acc[i].z);
            acc[i].w = fmaf(aexp, cv[i].w, acc[i].w);
        }
    }

    if (den == 0.f) den = 1e-12f;
    float invden = 1.f / den;
    const float4* epp = (const float4*)(Epre + (size_t)warp * D);
    float4* op = (float4*)(entnew + (size_t)warp * D);
    float nrm = 0.f;
    float4 tv[4];
    #pragma unroll
    for (int i = 0; i < 4; i++) {
        int ii = lane + i * 32;
        float4 ep4 = epp[ii];
        float4 t;
        float x = acc[i].x * invden; t.x = ep4.x + (x > 0.f ? x : expm1f(x));
        x = acc[i].y * invden;       t.y = ep4.y + (x > 0.f ? x : expm1f(x));
        x = acc[i].z * invden;       t.z = ep4.z + (x > 0.f ? x : expm1f(x));
        x = acc[i].w * invden;       t.w = ep4.w + (x > 0.f ? x : expm1f(x));
        tv[i] = t;
        nrm += t.x * t.x + t.y * t.y + t.z * t.z + t.w * t.w;
    }
    #pragma unroll
    for (int o = 16; o; o >>= 1) nrm += __shfl_xor_sync(0xFFFFFFFFu, nrm, o);
    float inv = 1.f / fmaxf(sqrtf(nrm), 1e-12f);
    #pragma unroll
    for (int i = 0; i < 4; i++) {
        int ii = lane + i * 32;
        float4 t = tv[i];
        op[ii] = make_float4(t.x * inv, t.y * inv, t.z * inv, t.w * inv);
    }
}

// ---------------------------------------------------------------------------
// mma.sync fp16 GEMM (single pass)
// ---------------------------------------------------------------------------
#define MM_BM 128
#define MM_BN 256
#define MM_BK 32
#define MM_LD 40
#define MM_STAGES 4
static constexpr int MM_AH = 0;
static constexpr int MM_BH = 128 * MM_LD;
static constexpr int MM_STAGE_H = 15360;
static constexpr int MM_STAGE_BYTES = MM_STAGE_H * 2;
static constexpr int MM_SMEM_BYTES = MM_STAGES * MM_STAGE_BYTES;

template<bool HOUT>
__global__ void __launch_bounds__(512, 1)
gemm_mma_kernel(const __half* __restrict__ A, const __half* __restrict__ Bh,
                void* __restrict__ Cv, int M, int D) {
    extern __shared__ __half sh[];
    uint32_t sbase = smem_to_u32(sh);
    int tid = threadIdx.x;
    int lane = tid & 31;
    int warp = tid >> 5;
    int mb = blockIdx.x * MM_BM;
    int nb = blockIdx.y * MM_BN;
    int wm = (warp >> 2) * 32;
    int wn = (warp & 3) * 64;
    const int nch = D / MM_BK;

    float acc[2][8][4];
    #pragma unroll
    for (int i = 0; i < 2; i++)
        #pragma unroll
        for (int j = 0; j < 8; j++)
            #pragma unroll
            for (int q = 0; q < 4; q++) acc[i][j][q] = 0.f;

    int arow = tid >> 2;
    int achk = (tid & 3) * 8;
    int gma = mb + arow;
    bool apred = gma < M;
    size_t abase = (size_t)(apred ? gma : 0) * D + achk;

    auto stage_load = [&](int ch) {
        if (ch < nch) {
            int kb = ch * MM_BK;
            uint32_t st = sbase + (ch % MM_STAGES) * MM_STAGE_BYTES;
            cp16(st + (MM_AH + arow * MM_LD + achk) * 2, A + abase + kb, apred);
            #pragma unroll
            for (int i = 0; i < 2; i++) {
                int idx = tid + i * 512;
                int row = idx >> 2;
                int chk = (idx & 3) * 8;
                size_t go = (size_t)(nb + row) * D + kb + chk;
                cp16(st + (MM_BH + row * MM_LD + chk) * 2, Bh + go, true);
            }
        }
        asm volatile("cp.async.commit_group;" ::: "memory");
    };

    stage_load(0);
    stage_load(1);
    stage_load(2);

    int a_r = (lane & 15);
    int a_c = (lane >> 4) << 3;
    int b_r = (lane & 7) + ((lane & 16) >> 1);
    int b_c = (lane & 8);

    for (int ch = 0; ch < nch; ch++) {
        asm volatile("cp.async.wait_group 2;" ::: "memory");
        __syncthreads();
        stage_load(ch + 3);

        uint32_t stb = sbase + (ch % MM_STAGES) * MM_STAGE_BYTES;
        #pragma unroll
        for (int s16 = 0; s16 < 2; s16++) {
            int k0 = s16 * 16;
            uint32_t ah[2][4], bh[8][2];
            #pragma unroll
            for (int mi = 0; mi < 2; mi++) {
                uint32_t addr = stb + (MM_AH + (wm + mi * 16 + a_r) * MM_LD + k0 + a_c) * 2;
                ldsm4(addr, ah[mi][0], ah[mi][1], ah[mi][2], ah[mi][3]);
            }
            #pragma unroll
            for (int nj = 0; nj < 4; nj++) {
                uint32_t addr = stb + (MM_BH + (wn + nj * 16 + b_r) * MM_LD + k0 + b_c) * 2;
                ldsm4(addr, bh[2 * nj][0], bh[2 * nj][1], bh[2 * nj + 1][0], bh[2 * nj + 1][1]);
            }
            #pragma unroll
            for (int mi = 0; mi < 2; mi++)
                #pragma unroll
                for (int nj = 0; nj < 8; nj++) mma_fp16(acc[mi][nj], ah[mi], bh[nj]);
        }
        __syncthreads();
    }

    #pragma unroll
    for (int mi = 0; mi < 2; mi++) {
        int gm0 = mb + wm + mi * 16 + (lane >> 2);
        int gm1 = gm0 + 8;
        #pragma unroll
        for (int nj = 0; nj < 8; nj++) {
            int gn = nb + wn + nj * 8 + (lane & 3) * 2;
            if (HOUT) {
                __half* C = (__half*)Cv;
                if (gm0 < M)
                    *(uint32_t*)(C + (size_t)gm0 * D + gn) =
                        pkh(__float2half_rn(acc[mi][nj][0]), __float2half_rn(acc[mi][nj][1]));
                if (gm1 < M)
                    *(uint32_t*)(C + (size_t)gm1 * D + gn) =
                        pkh(__float2half_rn(acc[mi][nj][2]), __float2half_rn(acc[mi][nj][3]));
            } else {
                float* C = (float*)Cv;
                if (gm0 < M)
                    *(float2*)(C + (size_t)gm0 * D + gn) = make_float2(acc[mi][nj][0], acc[mi][nj][1]);
                if (gm1 < M)
                    *(float2*)(C + (size_t)gm1 * D + gn) = make_float2(acc[mi][nj][2], acc[mi][nj][3]);
            }
        }
    }
}

// ---------------------------------------------------------------------------
// fp32 tiled SGEMM (tiny rel_new GEMM, R=500)
// ---------------------------------------------------------------------------
__global__ void gemm128_plain(const float* __restrict__ A0, const float* __restrict__ W,
                              float* __restrict__ C, int M, int D) {
    constexpr int BM = 128, BN = 128, BK = 16;
    __shared__ float As[BK][BM];
    __shared__ float Bs[BK][BN];
    int tid = threadIdx.x;
    int mb = blockIdx.x * BM;
    int nb = blockIdx.y * BN;
    int tx = tid & 15, ty = tid >> 4;
    float acc[8][8];
    #pragma unroll
    for (int i = 0; i < 8; i++)
        #pragma unroll
        for (int j = 0; j < 8; j++) acc[i][j] = 0.f;
    for (int kb = 0; kb < D; kb += BK) {
        #pragma unroll
        for (int i = 0; i < 2; i++) {
            int q = tid + i * 256;
            int row = q >> 2;
            int kc = (q & 3) << 2;
            int gr = mb + row;
            float4 v = make_float4(0.f, 0.f, 0.f, 0.f);
            if (gr < M) v = *(const float4*)(A0 + (size_t)gr * D + kb + kc);
            As[kc + 0][row] = v.x; As[kc + 1][row] = v.y;
            As[kc + 2][row] = v.z; As[kc + 3][row] = v.w;
        }
        #pragma unroll
        for (int i = 0; i < 2; i++) {
            int q = tid + i * 256;
            int kr = q >> 5;
            int jc = (q & 31) << 2;
            *(float4*)&Bs[kr][jc] = *(const float4*)(W + (size_t)(kb + kr) * D + nb + jc);
        }
        __syncthreads();
        #pragma unroll
        for (int k = 0; k < BK; k++) {
            float a[8], b[8];
            *(float4*)&a[0] = *(const float4*)&As[k][ty * 8];
            *(float4*)&a[4] = *(const float4*)&As[k][ty * 8 + 4];
            *(float4*)&b[0] = *(const float4*)&Bs[k][tx * 8];
            *(float4*)&b[4] = *(const float4*)&Bs[k][tx * 8 + 4];
            #pragma unroll
            for (int i = 0; i < 8; i++)
                #pragma unroll
                for (int j = 0; j < 8; j++)
                    acc[i][j] = fmaf(a[i], b[j], acc[i][j]);
        }
        __syncthreads();
    }
    #pragma unroll
    for (int i = 0; i < 8; i++) {
        int gr = mb + ty * 8 + i;
        if (gr < M) {
            float* cp = C + (size_t)gr * D + nb + tx * 8;
            *(float4*)(cp + 0) = make_float4(acc[i][0], acc[i][1], acc[i][2], acc[i][3]);
            *(float4*)(cp + 4) = make_float4(acc[i][4], acc[i][5], acc[i][6], acc[i][7]);
        }
    }
}

// ---------------------------------------------------------------------------
// Final gather
// ---------------------------------------------------------------------------
__global__ void gather_out(const int* __restrict__ triples, const float* __restrict__ entn,
                           const float* __restrict__ reln, float4* __restrict__ out,
                           int B, int D) {
    int nv = D >> 2;
    int total = B * 3 * nv;
    int i = blockIdx.x * blockDim.x + threadIdx.x;
    int stride = gridDim.x * blockDim.x;
    for (; i < total; i += stride) {
        int d4 = i % nv;
        int bt = i / nv;
        int t = bt % 3;
        int b = bt / 3;
        int idx = triples[b * 3 + t];
        const float4* srcp = (t == 1) ? (const float4*)(reln + (size_t)idx * D)
                                      : (const float4*)(entn + (size_t)idx * D);
        out[i] = srcp[d4];
    }
}

// ---------------------------------------------------------------------------
// Launch: 2-stream fork-join DAG (capture-safe event pattern)
// ---------------------------------------------------------------------------
extern "C" void kernel_launch(void* const* d_in, const int* in_sizes, int n_in,
                              void* d_out, int out_size) {
    const int*   triples  = (const int*)d_in[0];
    const int*   nodelist = (const int*)d_in[1];
    const int*   edgelist = (const int*)d_in[2];
    const float* ent      = (const float*)d_in[3];
    const float* rel      = (const float*)d_in[4];
    const float* W1       = (const float*)d_in[5];
    const float* Wa       = (const float*)d_in[6];
    const float* g0       = (const float*)d_in[7];
    const float* WE       = (const float*)d_in[8];
    const float* WR       = (const float*)d_in[9];

    int B = in_sizes[0] / 3;
    int E = in_sizes[2];
    int D = in_sizes[6];
    int N = in_sizes[3] / D;
    int R = in_sizes[4] / D;

    float *entn, *Epre, *reln;
    int *cnt, *off, *cur, *eidx, *bsum;
    __half *Cbaseh, *Cedgeh, *e0h, *egh, *edh, *relh, *w1h, *weth;
    cudaGetSymbolAddress((void**)&entn,   g_entn);
    cudaGetSymbolAddress((void**)&Epre,   g_Epre);
    cudaGetSymbolAddress((void**)&reln,   g_reln);
    cudaGetSymbolAddress((void**)&Cbaseh, g_Cbaseh);
    cudaGetSymbolAddress((void**)&Cedgeh, g_Cedgeh);
    cudaGetSymbolAddress((void**)&cnt,    g_cnt);
    cudaGetSymbolAddress((void**)&off,    g_off);
    cudaGetSymbolAddress((void**)&cur,    g_cur);
    cudaGetSymbolAddress((void**)&eidx,   g_eidx);
    cudaGetSymbolAddress((void**)&bsum,   g_bsum);
    cudaGetSymbolAddress((void**)&e0h,    g_e0h);
    cudaGetSymbolAddress((void**)&egh,    g_egh);
    cudaGetSymbolAddress((void**)&edh,    g_edh);
    cudaGetSymbolAddress((void**)&relh,   g_relh);
    cudaGetSymbolAddress((void**)&w1h,    g_w1h);
    cudaGetSymbolAddress((void**)&weth,   g_weth);

    cudaFuncSetAttribute(gemm_mma_kernel<true>,
                         cudaFuncAttributeMaxDynamicSharedMemorySize, MM_SMEM_BYTES);
    cudaFuncSetAttribute(gemm_mma_kernel<false>,
                         cudaFuncAttributeMaxDynamicSharedMemorySize, MM_SMEM_BYTES);

    int nblk = (N + 1023) / 1024;
    dim3 gN((N + MM_BM - 1) / MM_BM, D / MM_BN);
    dim3 gE2((E + MM_BM - 1) / MM_BM, D / MM_BN);
    dim3 gR((R + 127) / 128, D / 128);
    int total4 = B * 3 * (D >> 2);

    // fork-join resources (created each call; never destroyed — only the
    // correctness run and the capture call execute this path)
    cudaStream_t s1;
    cudaStreamCreateWithFlags(&s1, cudaStreamNonBlocking);
    cudaEvent_t evFork, evNorm, evJoin;
    cudaEventCreateWithFlags(&evFork, cudaEventDisableTiming);
    cudaEventCreateWithFlags(&evNorm, cudaEventDisableTiming);
    cudaEventCreateWithFlags(&evJoin, cudaEventDisableTiming);

    // ---- fork
    cudaEventRecord(evFork, 0);
    cudaStreamWaitEvent(s1, evFork, 0);

    // ---- s0: normalize + weight conversion, then big N-side GEMMs
    normalize_split<<<(N + 7) / 8, 256>>>(ent, g0, e0h, egh, N, D);
    split_weights<<<(D * D + 255) / 256, 256>>>(W1, WE, rel, w1h, weth, relh, D, R * D);
    cudaEventRecord(evNorm, 0);
    gemm_mma_kernel<true><<<gN, 512, MM_SMEM_BYTES>>>(egh, w1h, Cbaseh, N, D);
    gemm_mma_kernel<false><<<gN, 512, MM_SMEM_BYTES>>>(e0h, weth, Epre, N, D);

    // ---- s1: CSR build + rel GEMM (independent), then edge ops after evNorm
    zero_int<<<(N + 255) / 256, 256, 0, s1>>>(cnt, N);
    count_deg<<<(E + 255) / 256, 256, 0, s1>>>(nodelist, cnt, E);
    scan1<<<nblk, 1024, 0, s1>>>(cnt, off, bsum, N);
    scan3b<<<(N + 255) / 256, 256, 0, s1>>>(off, cur, bsum, nblk, N, E);
    fill_eidx<<<(E + 255) / 256, 256, 0, s1>>>(nodelist, cur, eidx, E);
    gemm128_plain<<<gR, 256, 0, s1>>>(rel, WR, reln, R, D);
    cudaStreamWaitEvent(s1, evNorm, 0);   // need e0h/relh/w1h
    split_edge<<<(E + 7) / 8, 256, 0, s1>>>(e0h, relh, nodelist + E, edgelist, eidx, edh, E, D);
    gemm_mma_kernel<true><<<gE2, 512, MM_SMEM_BYTES, s1>>>(edh, w1h, Cedgeh, E, D);
    cudaEventRecord(evJoin, s1);

    // ---- join on s0: aggregation + output
    cudaStreamWaitEvent(0, evJoin, 0);
    node_aggregate<<<(N + 7) / 8, 256>>>(e0h, Cbaseh, Cedgeh, Epre, Wa, off, entn, N, D);
    gather_out<<<(total4 + 255) / 256, 256>>>(triples, entn, reln, (float4*)d_out, B, D);
}

// round 12
// speedup vs baseline: 6.1307x; 1.1973x over previous
#include <cuda_runtime.h>
#include <cuda_fp16.h>
#include <math.h>
#include <stdint.h>

// ---------------------------------------------------------------------------
// UPGAT layer.  N=100000, R=500, D=512, E=150000, B=4096.
// GEMMs: fp16 single-pass mma.sync, 128x128 CTA tile, 2 CTAs/SM, BK=64.
// Cedge materialized in CSR order.  2-stream fork-join overlap.
// ---------------------------------------------------------------------------

#define MAX_N 100000
#define MAX_E 150000
#define MAX_R 500
#define MAX_D 512

__device__ float g_entn [(size_t)MAX_N * MAX_D];
__device__ float g_Epre [(size_t)MAX_N * MAX_D];
__device__ float g_reln [(size_t)MAX_R * MAX_D];

__device__ __half g_Cbaseh[(size_t)MAX_N * MAX_D];
__device__ __half g_Cedgeh[(size_t)MAX_E * MAX_D];

__device__ int g_cnt [MAX_N];
__device__ int g_off [MAX_N + 1];
__device__ int g_cur [MAX_N];
__device__ int g_eidx[MAX_E];
__device__ int g_bsum[128];

__device__ __half g_e0h[(size_t)MAX_N * MAX_D];
__device__ __half g_egh[(size_t)MAX_N * MAX_D];
__device__ __half g_edh[(size_t)MAX_E * MAX_D];
__device__ __half g_relh[(size_t)MAX_R * MAX_D];
__device__ __half g_w1h[MAX_D * MAX_D];
__device__ __half g_weth[MAX_D * MAX_D];

// ---------------------------------------------------------------------------
// helpers
// ---------------------------------------------------------------------------
__device__ __forceinline__ uint32_t smem_to_u32(const void* smem_ptr) {
    uint32_t addr;
    asm("{ .reg .u64 tmp; cvta.to.shared.u64 tmp, %1; cvt.u32.u64 %0, tmp; }"
        : "=r"(addr) : "l"(smem_ptr));
    return addr;
}
__device__ __forceinline__ void ldsm4(uint32_t addr, uint32_t& r0, uint32_t& r1,
                                      uint32_t& r2, uint32_t& r3) {
    asm volatile("ldmatrix.sync.aligned.m8n8.x4.shared.b16 {%0,%1,%2,%3}, [%4];"
                 : "=r"(r0), "=r"(r1), "=r"(r2), "=r"(r3) : "r"(addr));
}
__device__ __forceinline__ void mma_fp16(float* d, const uint32_t* a, const uint32_t* b) {
    asm volatile(
        "mma.sync.aligned.m16n8k16.row.col.f32.f16.f16.f32 "
        "{%0,%1,%2,%3}, {%4,%5,%6,%7}, {%8,%9}, {%0,%1,%2,%3};"
        : "+f"(d[0]), "+f"(d[1]), "+f"(d[2]), "+f"(d[3])
        : "r"(a[0]), "r"(a[1]), "r"(a[2]), "r"(a[3]), "r"(b[0]), "r"(b[1]));
}
__device__ __forceinline__ void cp16(uint32_t dst, const void* src, bool pred) {
    int sz = pred ? 16 : 0;
    asm volatile("cp.async.cg.shared.global [%0], [%1], 16, %2;"
                 :: "r"(dst), "l"(src), "r"(sz) : "memory");
}
__device__ __forceinline__ uint32_t pkh(__half a, __half b) {
    __half2 t = __halves2half2(a, b);
    return *reinterpret_cast<uint32_t*>(&t);
}
__device__ __forceinline__ uint2 h4(float4 v) {
    return make_uint2(pkh(__float2half_rn(v.x), __float2half_rn(v.y)),
                      pkh(__float2half_rn(v.z), __float2half_rn(v.w)));
}
__device__ __forceinline__ float4 f4ofh(uint2 u) {
    __half2* h2 = (__half2*)&u;
    float2 a = __half22float2(h2[0]);
    float2 b = __half22float2(h2[1]);
    return make_float4(a.x, a.y, b.x, b.y);
}
__device__ __forceinline__ float tanha(float x) {
    float y;
    asm("tanh.approx.f32 %0, %1;" : "=f"(y) : "f"(x));
    return y;
}

// ---------------------------------------------------------------------------
__global__ void zero_int(int* __restrict__ p, int n) {
    int i = blockIdx.x * blockDim.x + threadIdx.x;
    if (i < n) p[i] = 0;
}

__global__ void normalize_split(const float* __restrict__ in, const float* __restrict__ g0,
                                __half* __restrict__ e0h, __half* __restrict__ egh,
                                int M, int D) {
    int warp = (blockIdx.x * blockDim.x + threadIdx.x) >> 5;
    int lane = threadIdx.x & 31;
    if (warp >= M) return;
    const float4* ip = (const float4*)(in + (size_t)warp * D);
    const float4* gp = (const float4*)g0;
    int nv = D >> 2;
    float s = 0.f;
    for (int i = lane; i < nv; i += 32) {
        float4 v = ip[i];
        s += v.x * v.x + v.y * v.y + v.z * v.z + v.w * v.w;
    }
    #pragma unroll
    for (int o = 16; o; o >>= 1) s += __shfl_xor_sync(0xFFFFFFFFu, s, o);
    float inv = 1.f / fmaxf(sqrtf(s), 1e-12f);
    size_t rbase = (size_t)warp * D;
    for (int i = lane; i < nv; i += 32) {
        float4 v = ip[i];
        float4 n = make_float4(v.x * inv, v.y * inv, v.z * inv, v.w * inv);
        *(uint2*)(e0h + rbase + i * 4) = h4(n);
        float4 g = gp[i];
        *(uint2*)(egh + rbase + i * 4) =
            h4(make_float4(n.x * g.x, n.y * g.y, n.z * g.z, n.w * g.w));
    }
}

__global__ void split_edge(const __half* __restrict__ e0h, const __half* __restrict__ relh,
                           const int* __restrict__ dsts, const int* __restrict__ edges,
                           const int* __restrict__ eidx,
                           __half* __restrict__ eh, int E, int D) {
    int warp = (blockIdx.x * blockDim.x + threadIdx.x) >> 5;
    int lane = threadIdx.x & 31;
    if (warp >= E) return;
    int e = eidx[warp];
    int dst = dsts[e];
    int rl = edges[e];
    const uint2* ap = (const uint2*)(e0h + (size_t)dst * D);
    const uint2* gp = (const uint2*)(relh + (size_t)rl * D);
    uint2* op = (uint2*)(eh + (size_t)warp * D);
    int nv = D >> 2;
    for (int i = lane; i < nv; i += 32) {
        uint2 a = ap[i], g = gp[i];
        __half2* ah = (__half2*)&a;
        __half2* gh = (__half2*)&g;
        uint2 r;
        __half2* rh = (__half2*)&r;
        rh[0] = __hmul2(ah[0], gh[0]);
        rh[1] = __hmul2(ah[1], gh[1]);
        op[i] = r;
    }
}

__global__ void split_weights(const float* __restrict__ W1, const float* __restrict__ WE,
                              const float* __restrict__ rel,
                              __half* __restrict__ w1h, __half* __restrict__ weth,
                              __half* __restrict__ relh, int D, int RD) {
    int i = blockIdx.x * blockDim.x + threadIdx.x;
    int tot = D * D;
    if (i < tot) {
        w1h[i] = __float2half_rn(W1[i]);
        int k = i / D, j = i % D;
        weth[(size_t)j * D + k] = __float2half_rn(WE[i]);
    }
    if (i < RD) relh[i] = __float2half_rn(rel[i]);
}

__global__ void count_deg(const int* __restrict__ srcs, int* __restrict__ cnt, int E) {
    int e = blockIdx.x * blockDim.x + threadIdx.x;
    if (e < E) atomicAdd(&cnt[srcs[e]], 1);
}
__global__ void scan1(const int* __restrict__ cnt, int* __restrict__ off,
                      int* __restrict__ bsum, int N) {
    __shared__ int sm[1024];
    int tid = threadIdx.x;
    int i = blockIdx.x * 1024 + tid;
    int v = (i < N) ? cnt[i] : 0;
    sm[tid] = v;
    __syncthreads();
    #pragma unroll
    for (int d = 1; d < 1024; d <<= 1) {
        int t = (tid >= d) ? sm[tid - d] : 0;
        __syncthreads();
        sm[tid] += t;
        __syncthreads();
    }
    if (i < N) off[i] = sm[tid] - v;
    if (tid == 1023) bsum[blockIdx.x] = sm[1023];
}
__global__ void scan3b(int* __restrict__ off, int* __restrict__ cur,
                       const int* __restrict__ bsum, int nblk, int N, int E) {
    __shared__ int sb[128];
    int tid = threadIdx.x;
    if (tid < 128) sb[tid] = (tid < nblk) ? bsum[tid] : 0;
    __syncthreads();
    #pragma unroll
    for (int d = 1; d < 128; d <<= 1) {
        int t = (tid < 128 && tid >= d) ? sb[tid - d] : 0;
        __syncthreads();
        if (tid < 128) sb[tid] += t;
        __syncthreads();
    }
    int i = blockIdx.x * blockDim.x + tid;
    if (i < N) {
        int bi = i >> 10;
        int pre = (bi == 0) ? 0 : sb[bi - 1];
        int o = off[i] + pre;
        off[i] = o;
        cur[i] = o;
    }
    if (i == 0) off[N] = E;
}
__global__ void fill_eidx(const int* __restrict__ srcs, int* __restrict__ cur,
                          int* __restrict__ eidx, int E) {
    int e = blockIdx.x * blockDim.x + threadIdx.x;
    if (e < E) {
        int pos = atomicAdd(&cur[srcs[e]], 1);
        eidx[pos] = e;
    }
}

__global__ void node_aggregate(const __half* __restrict__ e0h, const __half* __restrict__ Cbh,
                               const __half* __restrict__ Ceh, const float* __restrict__ Epre,
                               const float* __restrict__ Wa,
                               const int* __restrict__ off,
                               float* __restrict__ entnew, int N, int D) {
    __shared__ float waS[512];
    for (int i = threadIdx.x; i < D; i += blockDim.x) waS[i] = Wa[i];
    __syncthreads();

    int warp = (blockIdx.x * blockDim.x + threadIdx.x) >> 5;
    int lane = threadIdx.x & 31;
    if (warp >= N) return;
    int o0 = off[warp], o1 = off[warp + 1];
    int deg = o1 - o0;

    const uint2* ep = (const uint2*)(e0h + (size_t)warp * D);
    const uint2* cbp = (const uint2*)(Cbh + (size_t)warp * D);
    const float4* wp = (const float4*)waS;

    float4 ew[4], acc[4];
    float sb = 0.f;
    #pragma unroll
    for (int i = 0; i < 4; i++) {
        int ii = lane + i * 32;
        float4 e = f4ofh(ep[ii]);
        float4 w = wp[ii];
        ew[i] = make_float4(e.x * w.x, e.y * w.y, e.z * w.z, e.w * w.w);
        float4 c = f4ofh(cbp[ii]);
        acc[i] = c;
        sb += ew[i].x * tanha(c.x) + ew[i].y * tanha(c.y) +
              ew[i].z * tanha(c.z) + ew[i].w * tanha(c.w);
    }
    #pragma unroll
    for (int o = 16; o; o >>= 1) sb += __shfl_xor_sync(0xFFFFFFFFu, sb, o);
    float lb = sb > 0.f ? sb : 0.2f * sb;
    float ab = expf(-lb);
    float coef = (deg > 0) ? ab : 0.f;
    float den = coef;
    #pragma unroll
    for (int i = 0; i < 4; i++) {
        acc[i].x *= coef; acc[i].y *= coef; acc[i].z *= coef; acc[i].w *= coef;
    }

    uint2 nxt[4];
    if (deg > 0) {
        const uint2* cp = (const uint2*)(Ceh + (size_t)o0 * D);
        #pragma unroll
        for (int i = 0; i < 4; i++) nxt[i] = cp[lane + i * 32];
    }
    for (int j = o0; j < o1; j++) {
        uint2 cur4[4];
        #pragma unroll
        for (int i = 0; i < 4; i++) cur4[i] = nxt[i];
        if (j + 1 < o1) {
            const uint2* cp = (const uint2*)(Ceh + (size_t)(j + 1) * D);
            #pragma unroll
            for (int i = 0; i < 4; i++) nxt[i] = cp[lane + i * 32];
        }
        float4 cv[4];
        float s = 0.f;
        #pragma unroll
        for (int i = 0; i < 4; i++) {
            float4 c = f4ofh(cur4[i]);
            cv[i] = c;
            s += ew[i].x * tanha(c.x) + ew[i].y * tanha(c.y) +
                 ew[i].z * tanha(c.z) + ew[i].w * tanha(c.w);
        }
        #pragma unroll
        for (int o = 16; o; o >>= 1) s += __shfl_xor_sync(0xFFFFFFFFu, s, o);
        float l = s > 0.f ? s : 0.2f * s;
        float aexp = expf(-l);
        den += aexp;
        #pragma unroll
        for (int i = 0; i < 4; i++) {
            acc[i].x = fmaf(aexp, cv[i].x, acc[i].x);
            acc[i].y = fmaf(aexp, cv[i].y, acc[i].y);
            acc[i].z = fmaf(aexp, cv[i].z, acc[i].z);
            acc[i].w = fmaf(aexp, cv[i].w, acc[i].w);
        }
    }

    if (den == 0.f) den = 1e-12f;
    float invden = 1.f / den;
    const float4* epp = (const float4*)(Epre + (size_t)warp * D);
    float4* op = (float4*)(entnew + (size_t)warp * D);
    float nrm = 0.f;
    float4 tv[4];
    #pragma unroll
    for (int i = 0; i < 4; i++) {
        int ii = lane + i * 32;
        float4 ep4 = epp[ii];
        float4 t;
        float x = acc[i].x * invden; t.x = ep4.x + (x > 0.f ? x : expm1f(x));
        x = acc[i].y * invden;       t.y = ep4.y + (x > 0.f ? x : expm1f(x));
        x = acc[i].z * invden;       t.z = ep4.z + (x > 0.f ? x : expm1f(x));
        x = acc[i].w * invden;       t.w = ep4.w + (x > 0.f ? x : expm1f(x));
        tv[i] = t;
        nrm += t.x * t.x + t.y * t.y + t.z * t.z + t.w * t.w;
    }
    #pragma unroll
    for (int o = 16; o; o >>= 1) nrm += __shfl_xor_sync(0xFFFFFFFFu, nrm, o);
    float inv = 1.f / fmaxf(sqrtf(nrm), 1e-12f);
    #pragma unroll
    for (int i = 0; i < 4; i++) {
        int ii = lane + i * 32;
        float4 t = tv[i];
        op[ii] = make_float4(t.x * inv, t.y * inv, t.z * inv, t.w * inv);
    }
}

// ---------------------------------------------------------------------------
// mma.sync fp16 GEMM: CTA 128x128, 256 threads (8 warps: 4M x 2N, warp 32x64),
// BK=64, 3-stage cp.async, 2 CTAs/SM.
// ---------------------------------------------------------------------------
#define MM_BM 128
#define MM_BN 128
#define MM_BK 64
#define MM_LD 72
#define MM_STAGES 3
static constexpr int MM_AH = 0;
static constexpr int MM_BH = 128 * MM_LD;                 // 9216 halves
static constexpr int MM_STAGE_H = 2 * 128 * MM_LD;        // 18432 halves
static constexpr int MM_STAGE_BYTES = MM_STAGE_H * 2;     // 36864
static constexpr int MM_SMEM_BYTES = MM_STAGES * MM_STAGE_BYTES; // 110592

template<bool HOUT>
__global__ void __launch_bounds__(256, 2)
gemm_mma_kernel(const __half* __restrict__ A, const __half* __restrict__ Bh,
                void* __restrict__ Cv, int M, int D) {
    extern __shared__ __half sh[];
    uint32_t sbase = smem_to_u32(sh);
    int tid = threadIdx.x;
    int lane = tid & 31;
    int warp = tid >> 5;
    int mb = blockIdx.x * MM_BM;
    int nb = blockIdx.y * MM_BN;
    int wm = (warp >> 1) * 32;      // 4 M groups
    int wn = (warp & 1) * 64;       // 2 N groups
    const int nch = D / MM_BK;      // 8

    float acc[2][8][4];
    #pragma unroll
    for (int i = 0; i < 2; i++)
        #pragma unroll
        for (int j = 0; j < 8; j++)
            #pragma unroll
            for (int q = 0; q < 4; q++) acc[i][j][q] = 0.f;

    // staging: 64-half rows, 8 chunks of 8 halves; idx = tid + i*256
    int arow = tid >> 3;            // 0..31 base; +i*32
    int achk = (tid & 7) * 8;
    bool apred[4];
    size_t abase[4];
    #pragma unroll
    for (int i = 0; i < 4; i++) {
        int gm = mb + arow + i * 32;
        apred[i] = gm < M;
        abase[i] = (size_t)(apred[i] ? gm : 0) * D + achk;
    }

    auto stage_load = [&](int ch) {
        if (ch < nch) {
            int kb = ch * MM_BK;
            uint32_t st = sbase + (ch % MM_STAGES) * MM_STAGE_BYTES;
            #pragma unroll
            for (int i = 0; i < 4; i++) {
                int row = arow + i * 32;
                cp16(st + (MM_AH + row * MM_LD + achk) * 2, A + abase[i] + kb, apred[i]);
                size_t go = (size_t)(nb + row) * D + kb + achk;
                cp16(st + (MM_BH + row * MM_LD + achk) * 2, Bh + go, true);
            }
        }
        asm volatile("cp.async.commit_group;" ::: "memory");
    };

    stage_load(0);
    stage_load(1);

    int a_r = (lane & 15);
    int a_c = (lane >> 4) << 3;
    int b_r = (lane & 7) + ((lane & 16) >> 1);
    int b_c = (lane & 8);

    for (int ch = 0; ch < nch; ch++) {
        asm volatile("cp.async.wait_group 1;" ::: "memory");
        __syncthreads();
        stage_load(ch + 2);

        uint32_t stb = sbase + (ch % MM_STAGES) * MM_STAGE_BYTES;
        #pragma unroll
        for (int s16 = 0; s16 < 4; s16++) {
            int k0 = s16 * 16;
            uint32_t ah[2][4], bh[8][2];
            #pragma unroll
            for (int mi = 0; mi < 2; mi++) {
                uint32_t addr = stb + (MM_AH + (wm + mi * 16 + a_r) * MM_LD + k0 + a_c) * 2;
                ldsm4(addr, ah[mi][0], ah[mi][1], ah[mi][2], ah[mi][3]);
            }
            #pragma unroll
            for (int nj = 0; nj < 4; nj++) {
                uint32_t addr = stb + (MM_BH + (wn + nj * 16 + b_r) * MM_LD + k0 + b_c) * 2;
                ldsm4(addr, bh[2 * nj][0], bh[2 * nj][1], bh[2 * nj + 1][0], bh[2 * nj + 1][1]);
            }
            #pragma unroll
            for (int mi = 0; mi < 2; mi++)
                #pragma unroll
                for (int nj = 0; nj < 8; nj++) mma_fp16(acc[mi][nj], ah[mi], bh[nj]);
        }
        __syncthreads();
    }

    #pragma unroll
    for (int mi = 0; mi < 2; mi++) {
        int gm0 = mb + wm + mi * 16 + (lane >> 2);
        int gm1 = gm0 + 8;
        #pragma unroll
        for (int nj = 0; nj < 8; nj++) {
            int gn = nb + wn + nj * 8 + (lane & 3) * 2;
            if (HOUT) {
                __half* C = (__half*)Cv;
                if (gm0 < M)
                    *(uint32_t*)(C + (size_t)gm0 * D + gn) =
                        pkh(__float2half_rn(acc[mi][nj][0]), __float2half_rn(acc[mi][nj][1]));
                if (gm1 < M)
                    *(uint32_t*)(C + (size_t)gm1 * D + gn) =
                        pkh(__float2half_rn(acc[mi][nj][2]), __float2half_rn(acc[mi][nj][3]));
            } else {
                float* C = (float*)Cv;
                if (gm0 < M)
                    *(float2*)(C + (size_t)gm0 * D + gn) = make_float2(acc[mi][nj][0], acc[mi][nj][1]);
                if (gm1 < M)
                    *(float2*)(C + (size_t)gm1 * D + gn) = make_float2(acc[mi][nj][2], acc[mi][nj][3]);
            }
        }
    }
}

// ---------------------------------------------------------------------------
// fp32 tiled SGEMM (tiny rel_new GEMM, R=500)
// ---------------------------------------------------------------------------
__global__ void gemm128_plain(const float* __restrict__ A0, const float* __restrict__ W,
                              float* __restrict__ C, int M, int D) {
    constexpr int BM = 128, BN = 128, BK = 16;
    __shared__ float As[BK][BM];
    __shared__ float Bs[BK][BN];
    int tid = threadIdx.x;
    int mb = blockIdx.x * BM;
    int nb = blockIdx.y * BN;
    int tx = tid & 15, ty = tid >> 4;
    float acc[8][8];
    #pragma unroll
    for (int i = 0; i < 8; i++)
        #pragma unroll
        for (int j = 0; j < 8; j++) acc[i][j] = 0.f;
    for (int kb = 0; kb < D; kb += BK) {
        #pragma unroll
        for (int i = 0; i < 2; i++) {
            int q = tid + i * 256;
            int row = q >> 2;
            int kc = (q & 3) << 2;
            int gr = mb + row;
            float4 v = make_float4(0.f, 0.f, 0.f, 0.f);
            if (gr < M) v = *(const float4*)(A0 + (size_t)gr * D + kb + kc);
            As[kc + 0][row] = v.x; As[kc + 1][row] = v.y;
            As[kc + 2][row] = v.z; As[kc + 3][row] = v.w;
        }
        #pragma unroll
        for (int i = 0; i < 2; i++) {
            int q = tid + i * 256;
            int kr = q >> 5;
            int jc = (q & 31) << 2;
            *(float4*)&Bs[kr][jc] = *(const float4*)(W + (size_t)(kb + kr) * D + nb + jc);
        }
        __syncthreads();
        #pragma unroll
        for (int k = 0; k < BK; k++) {
            float a[8], b[8];
            *(float4*)&a[0] = *(const float4*)&As[k][ty * 8];
            *(float4*)&a[4] = *(const float4*)&As[k][ty * 8 + 4];
            *(float4*)&b[0] = *(const float4*)&Bs[k][tx * 8];
            *(float4*)&b[4] = *(const float4*)&Bs[k][tx * 8 + 4];
            #pragma unroll
            for (int i = 0; i < 8; i++)
                #pragma unroll
                for (int j = 0; j < 8; j++)
                    acc[i][j] = fmaf(a[i], b[j], acc[i][j]);
        }
        __syncthreads();
    }
    #pragma unroll
    for (int i = 0; i < 8; i++) {
        int gr = mb + ty * 8 + i;
        if (gr < M) {
            float* cp = C + (size_t)gr * D + nb + tx * 8;
            *(float4*)(cp + 0) = make_float4(acc[i][0], acc[i][1], acc[i][2], acc[i][3]);
            *(float4*)(cp + 4) = make_float4(acc[i][4], acc[i][5], acc[i][6], acc[i][7]);
        }
    }
}

// ---------------------------------------------------------------------------
// Final gather
// ---------------------------------------------------------------------------
__global__ void gather_out(const int* __restrict__ triples, const float* __restrict__ entn,
                           const float* __restrict__ reln, float4* __restrict__ out,
                           int B, int D) {
    int nv = D >> 2;
    int total = B * 3 * nv;
    int i = blockIdx.x * blockDim.x + threadIdx.x;
    int stride = gridDim.x * blockDim.x;
    for (; i < total; i += stride) {
        int d4 = i % nv;
        int bt = i / nv;
        int t = bt % 3;
        int b = bt / 3;
        int idx = triples[b * 3 + t];
        const float4* srcp = (t == 1) ? (const float4*)(reln + (size_t)idx * D)
                                      : (const float4*)(entn + (size_t)idx * D);
        out[i] = srcp[d4];
    }
}

// ---------------------------------------------------------------------------
// Launch: 2-stream fork-join DAG
// ---------------------------------------------------------------------------
extern "C" void kernel_launch(void* const* d_in, const int* in_sizes, int n_in,
                              void* d_out, int out_size) {
    const int*   triples  = (const int*)d_in[0];
    const int*   nodelist = (const int*)d_in[1];
    const int*   edgelist = (const int*)d_in[2];
    const float* ent      = (const float*)d_in[3];
    const float* rel      = (const float*)d_in[4];
    const float* W1       = (const float*)d_in[5];
    const float* Wa       = (const float*)d_in[6];
    const float* g0       = (const float*)d_in[7];
    const float* WE       = (const float*)d_in[8];
    const float* WR       = (const float*)d_in[9];

    int B = in_sizes[0] / 3;
    int E = in_sizes[2];
    int D = in_sizes[6];
    int N = in_sizes[3] / D;
    int R = in_sizes[4] / D;

    float *entn, *Epre, *reln;
    int *cnt, *off, *cur, *eidx, *bsum;
    __half *Cbaseh, *Cedgeh, *e0h, *egh, *edh, *relh, *w1h, *weth;
    cudaGetSymbolAddress((void**)&entn,   g_entn);
    cudaGetSymbolAddress((void**)&Epre,   g_Epre);
    cudaGetSymbolAddress((void**)&reln,   g_reln);
    cudaGetSymbolAddress((void**)&Cbaseh, g_Cbaseh);
    cudaGetSymbolAddress((void**)&Cedgeh, g_Cedgeh);
    cudaGetSymbolAddress((void**)&cnt,    g_cnt);
    cudaGetSymbolAddress((void**)&off,    g_off);
    cudaGetSymbolAddress((void**)&cur,    g_cur);
    cudaGetSymbolAddress((void**)&eidx,   g_eidx);
    cudaGetSymbolAddress((void**)&bsum,   g_bsum);
    cudaGetSymbolAddress((void**)&e0h,    g_e0h);
    cudaGetSymbolAddress((void**)&egh,    g_egh);
    cudaGetSymbolAddress((void**)&edh,    g_edh);
    cudaGetSymbolAddress((void**)&relh,   g_relh);
    cudaGetSymbolAddress((void**)&w1h,    g_w1h);
    cudaGetSymbolAddress((void**)&weth,   g_weth);

    cudaFuncSetAttribute(gemm_mma_kernel<true>,
                         cudaFuncAttributeMaxDynamicSharedMemorySize, MM_SMEM_BYTES);
    cudaFuncSetAttribute(gemm_mma_kernel<false>,
                         cudaFuncAttributeMaxDynamicSharedMemorySize, MM_SMEM_BYTES);

    int nblk = (N + 1023) / 1024;
    dim3 gN((N + MM_BM - 1) / MM_BM, D / MM_BN);
    dim3 gE2((E + MM_BM - 1) / MM_BM, D / MM_BN);
    dim3 gR((R + 127) / 128, D / 128);
    int total4 = B * 3 * (D >> 2);

    cudaStream_t s1;
    cudaStreamCreateWithFlags(&s1, cudaStreamNonBlocking);
    cudaEvent_t evFork, evNorm, evJoin;
    cudaEventCreateWithFlags(&evFork, cudaEventDisableTiming);
    cudaEventCreateWithFlags(&evNorm, cudaEventDisableTiming);
    cudaEventCreateWithFlags(&evJoin, cudaEventDisableTiming);

    cudaEventRecord(evFork, 0);
    cudaStreamWaitEvent(s1, evFork, 0);

    // s0: normalize + weights, then N-side GEMMs
    normalize_split<<<(N + 7) / 8, 256>>>(ent, g0, e0h, egh, N, D);
    split_weights<<<(D * D + 255) / 256, 256>>>(W1, WE, rel, w1h, weth, relh, D, R * D);
    cudaEventRecord(evNorm, 0);
    gemm_mma_kernel<true><<<gN, 256, MM_SMEM_BYTES>>>(egh, w1h, Cbaseh, N, D);
    gemm_mma_kernel<false><<<gN, 256, MM_SMEM_BYTES>>>(e0h, weth, Epre, N, D);

    // s1: CSR + rel GEMM, then edge ops after evNorm
    zero_int<<<(N + 255) / 256, 256, 0, s1>>>(cnt, N);
    count_deg<<<(E + 255) / 256, 256, 0, s1>>>(nodelist, cnt, E);
    scan1<<<nblk, 1024, 0, s1>>>(cnt, off, bsum, N);
    scan3b<<<(N + 255) / 256, 256, 0, s1>>>(off, cur, bsum, nblk, N, E);
    fill_eidx<<<(E + 255) / 256, 256, 0, s1>>>(nodelist, cur, eidx, E);
    gemm128_plain<<<gR, 256, 0, s1>>>(rel, WR, reln, R, D);
    cudaStreamWaitEvent(s1, evNorm, 0);
    split_edge<<<(E + 7) / 8, 256, 0, s1>>>(e0h, relh, nodelist + E, edgelist, eidx, edh, E, D);
    gemm_mma_kernel<true><<<gE2, 256, MM_SMEM_BYTES, s1>>>(edh, w1h, Cedgeh, E, D);
    cudaEventRecord(evJoin, s1);

    // join: aggregation + output
    cudaStreamWaitEvent(0, evJoin, 0);
    node_aggregate<<<(N + 7) / 8, 256>>>(e0h, Cbaseh, Cedgeh, Epre, Wa, off, entn, N, D);
    gather_out<<<(total4 + 255) / 256, 256>>>(triples, entn, reln, (float4*)d_out, B, D);
}